// round 3
// baseline (speedup 1.0000x reference)
#include <cuda_runtime.h>
#include <math.h>

// Problem constants
#define BB   8
#define NT   1024
#define C1d  256
#define C2d  512
#define C3d  1024
#define KVd  1792
#define NHd  4
#define C2E  2048

// ---------------- scratch (device statics; no allocation in kernel_launch) ----
__device__ float g_Y  [BB*NT*KVd];       // LN(concat)                 58.7 MB
__device__ float g_X  [BB*NT*C2d];       // LN(emb2)                   16.8 MB
__device__ float g_G  [BB*C2d*KVd];      // X^T Y                      29.4 MB
__device__ float g_T1 [BB*NHd*C2d*KVd];  // Wq^T G                    117.4 MB
__device__ float g_S  [BB*NHd*C2d*KVd];  // scores -> probs           117.4 MB
__device__ float g_sc [BB*NHd];          // per-map softmax scale
__device__ float g_M  [BB*KVd*C2d];      // sum_h Wv_h probs_h^T / H   29.4 MB
__device__ float g_ctx[BB*NT*C2d];       //                            16.8 MB
__device__ float g_cx2[BB*NT*C2d];       // residual                   16.8 MB
__device__ float g_Z  [BB*NT*C2d];       // LN(cx2)                    16.8 MB
__device__ float g_F  [BB*NT*C2E];       // gelu(fc1)                  67.1 MB

// ---------------- generic batched SGEMM: C = op(A)*op(B) (+epilogue) ---------
// EPI: 0 none, 1 +add, 2 +bias then gelu, 3 +bias +add
#define BM 128
#define BN 128
#define BK 16

__device__ __forceinline__ int selidx(int mode, int z) {
    return mode == 0 ? z : (mode == 1 ? (z & 3) : (z >> 2));   // H = 4
}

template<bool TA, bool TB, int EPI>
__global__ __launch_bounds__(256, 2)
void gemm_k(const float* __restrict__ A, const float* __restrict__ B,
            float* __restrict__ C, const float* __restrict__ bias,
            const float* __restrict__ addp,
            int M, int Nn, int K,
            long sA, long sB, long sC,
            int selA, int selB, int nH, long hA, long hB, float outScale)
{
    __shared__ float As[BK][BM + 4];
    __shared__ float Bs[BK][BN + 4];

    const int z = blockIdx.z;
    const float* Ab = A + (long)selidx(selA, z) * sA;
    const float* Bb = B + (long)selidx(selB, z) * sB;
    float*       Cb = C + (long)z * sC;

    const int m0 = blockIdx.y * BM;
    const int n0 = blockIdx.x * BN;
    const int tid = threadIdx.x;
    const int cx = tid & 15;       // 0..15
    const int cy = tid >> 4;       // 0..15

    float acc[8][8];
#pragma unroll
    for (int i = 0; i < 8; i++)
#pragma unroll
        for (int j = 0; j < 8; j++) acc[i][j] = 0.f;

    for (int h = 0; h < nH; ++h) {
        const float* Ah = Ab + (long)h * hA;
        const float* Bh = Bb + (long)h * hB;
        for (int k0 = 0; k0 < K; k0 += BK) {
            // ---- load A tile into As[k][m]
            if (TA) {
                // A is [K, M] row-major (lda = M), tile 16 x 128, contiguous in m
#pragma unroll
                for (int r = 0; r < 2; ++r) {
                    int f  = tid + r * 256;        // 0..511 float4s
                    int kk = f >> 5;               // /32
                    int mq = f & 31;
                    float4 v = *(const float4*)(Ah + (long)(k0 + kk) * M + m0 + mq * 4);
                    *(float4*)&As[kk][mq * 4] = v;
                }
            } else {
                // A is [M, K] row-major (lda = K)
#pragma unroll
                for (int r = 0; r < 2; ++r) {
                    int f  = tid + r * 256;
                    int mm = f >> 2;               // /4 -> 0..127
                    int kq = f & 3;
                    float4 v = *(const float4*)(Ah + (long)(m0 + mm) * K + k0 + kq * 4);
                    As[kq * 4 + 0][mm] = v.x;
                    As[kq * 4 + 1][mm] = v.y;
                    As[kq * 4 + 2][mm] = v.z;
                    As[kq * 4 + 3][mm] = v.w;
                }
            }
            // ---- load B tile into Bs[k][n]
            if (!TB) {
                // B is [K, N] row-major (ldb = Nn)
#pragma unroll
                for (int r = 0; r < 2; ++r) {
                    int f  = tid + r * 256;
                    int kk = f >> 5;
                    int nq = f & 31;
                    float4 v = *(const float4*)(Bh + (long)(k0 + kk) * Nn + n0 + nq * 4);
                    *(float4*)&Bs[kk][nq * 4] = v;
                }
            } else {
                // B is [N, K] row-major (ldb = K)
#pragma unroll
                for (int r = 0; r < 2; ++r) {
                    int f  = tid + r * 256;
                    int nn = f >> 2;
                    int kq = f & 3;
                    float4 v = *(const float4*)(Bh + (long)(n0 + nn) * K + k0 + kq * 4);
                    Bs[kq * 4 + 0][nn] = v.x;
                    Bs[kq * 4 + 1][nn] = v.y;
                    Bs[kq * 4 + 2][nn] = v.z;
                    Bs[kq * 4 + 3][nn] = v.w;
                }
            }
            __syncthreads();

#pragma unroll
            for (int kk = 0; kk < BK; ++kk) {
                float a[8], b[8];
                *(float4*)&a[0] = *(const float4*)&As[kk][cy * 4];
                *(float4*)&a[4] = *(const float4*)&As[kk][64 + cy * 4];
                *(float4*)&b[0] = *(const float4*)&Bs[kk][cx * 4];
                *(float4*)&b[4] = *(const float4*)&Bs[kk][64 + cx * 4];
#pragma unroll
                for (int i = 0; i < 8; i++)
#pragma unroll
                    for (int j = 0; j < 8; j++) acc[i][j] += a[i] * b[j];
            }
            __syncthreads();
        }
    }

    // ---- epilogue
#pragma unroll
    for (int ri = 0; ri < 2; ++ri) {
#pragma unroll
        for (int i2 = 0; i2 < 4; ++i2) {
            const int  i = ri * 4 + i2;
            const long m = m0 + (ri ? 64 : 0) + cy * 4 + i2;
#pragma unroll
            for (int cj = 0; cj < 2; ++cj) {
                const int  jb  = cj * 4;
                const long col = n0 + (cj ? 64 : 0) + cx * 4;
                float vv[4];
#pragma unroll
                for (int j2 = 0; j2 < 4; ++j2) {
                    float v = acc[i][jb + j2] * outScale;
                    if (EPI == 1) v += addp[m * Nn + col + j2];
                    if (EPI == 2) {
                        v += bias[col + j2];
                        v = 0.5f * v * (1.f + erff(v * 0.70710678118654752f));
                    }
                    if (EPI == 3) v += bias[col + j2] + addp[m * Nn + col + j2];
                    vv[j2] = v;
                }
                *(float4*)&Cb[m * Nn + col] = make_float4(vv[0], vv[1], vv[2], vv[3]);
            }
        }
    }
}

// ---------------- fused input LayerNorms: Y = LN(concat), X = LN(emb2) -------
__global__ void ln_in_kernel(const float* __restrict__ e1, const float* __restrict__ e2,
                             const float* __restrict__ e3,
                             const float* __restrict__ ag, const float* __restrict__ ab,
                             const float* __restrict__ g1, const float* __restrict__ b1,
                             float* __restrict__ Y, float* __restrict__ X)
{
    const long row = blockIdx.x;                 // b*N + n
    const int  tid = threadIdx.x;
    const float* p1 = e1 + row * C1d;
    const float* p2 = e2 + row * C2d;
    const float* p3 = e3 + row * C3d;
    __shared__ float sh[256];

    float v[7];
    float s = 0.f, q = 0.f;
#pragma unroll
    for (int j = 0; j < 7; ++j) {
        int i = tid + j * 256;
        float x;
        if (j == 0)            x = p1[i];
        else if (j <= 2)       x = p2[i - C1d];
        else                   x = p3[i - (C1d + C2d)];
        v[j] = x; s += x; q += x * x;
    }
    sh[tid] = s; __syncthreads();
    for (int o = 128; o; o >>= 1) { if (tid < o) sh[tid] += sh[tid + o]; __syncthreads(); }
    float tot = sh[0]; __syncthreads();
    sh[tid] = q; __syncthreads();
    for (int o = 128; o; o >>= 1) { if (tid < o) sh[tid] += sh[tid + o]; __syncthreads(); }
    float totq = sh[0]; __syncthreads();

    float mean = tot * (1.f / KVd);
    float inv  = rsqrtf(totq * (1.f / KVd) - mean * mean + 1e-6f);
#pragma unroll
    for (int j = 0; j < 7; ++j) {
        int i = tid + j * 256;
        Y[row * KVd + i] = (v[j] - mean) * inv * ag[i] + ab[i];
    }

    // X = LN(emb2) with ln1
    float u0 = p2[tid], u1 = p2[tid + 256];
    s = u0 + u1; q = u0 * u0 + u1 * u1;
    sh[tid] = s; __syncthreads();
    for (int o = 128; o; o >>= 1) { if (tid < o) sh[tid] += sh[tid + o]; __syncthreads(); }
    tot = sh[0]; __syncthreads();
    sh[tid] = q; __syncthreads();
    for (int o = 128; o; o >>= 1) { if (tid < o) sh[tid] += sh[tid + o]; __syncthreads(); }
    totq = sh[0]; __syncthreads();
    mean = tot * (1.f / C2d);
    inv  = rsqrtf(totq * (1.f / C2d) - mean * mean + 1e-6f);
    X[row * C2d + tid]       = (u0 - mean) * inv * g1[tid]       + b1[tid];
    X[row * C2d + tid + 256] = (u1 - mean) * inv * g1[tid + 256] + b1[tid + 256];
}

// ---------------- LN over cx2 -> Z -------------------------------------------
__global__ void ln2_kernel(const float* __restrict__ in,
                           const float* __restrict__ g, const float* __restrict__ b,
                           float* __restrict__ out)
{
    const long row = blockIdx.x;
    const int  tid = threadIdx.x;
    const float* p = in + row * C2d;
    __shared__ float sh[256];
    float u0 = p[tid], u1 = p[tid + 256];
    float s = u0 + u1, q = u0 * u0 + u1 * u1;
    sh[tid] = s; __syncthreads();
    for (int o = 128; o; o >>= 1) { if (tid < o) sh[tid] += sh[tid + o]; __syncthreads(); }
    float tot = sh[0]; __syncthreads();
    sh[tid] = q; __syncthreads();
    for (int o = 128; o; o >>= 1) { if (tid < o) sh[tid] += sh[tid + o]; __syncthreads(); }
    float totq = sh[0]; __syncthreads();
    float mean = tot * (1.f / C2d);
    float inv  = rsqrtf(totq * (1.f / C2d) - mean * mean + 1e-6f);
    out[row * C2d + tid]       = (u0 - mean) * inv * g[tid]       + b[tid];
    out[row * C2d + tid + 256] = (u1 - mean) * inv * g[tid + 256] + b[tid + 256];
}

// ---------------- per-(b,h) map variance -> softmax scale --------------------
// probs = softmax_k(S * scale), scale = a * rsqrt(a^2*var(S) + 1e-5), a=1/sqrt(KV)
// (instance-norm mean is a per-map scalar -> cancels inside each row softmax)
__global__ void stats_kernel(const float* __restrict__ S, float* __restrict__ scale)
{
    const int z   = blockIdx.x;
    const int tid = threadIdx.x;
    const float4* p = (const float4*)(S + (long)z * C2d * KVd);
    const int n4 = C2d * KVd / 4;
    float s = 0.f, q = 0.f;
    for (int i = tid; i < n4; i += 1024) {
        float4 v = p[i];
        s += v.x + v.y + v.z + v.w;
        q += v.x * v.x + v.y * v.y + v.z * v.z + v.w * v.w;
    }
    __shared__ float sh[1024];
    sh[tid] = s; __syncthreads();
    for (int o = 512; o; o >>= 1) { if (tid < o) sh[tid] += sh[tid + o]; __syncthreads(); }
    float tot = sh[0]; __syncthreads();
    sh[tid] = q; __syncthreads();
    for (int o = 512; o; o >>= 1) { if (tid < o) sh[tid] += sh[tid + o]; __syncthreads(); }
    float totq = sh[0];
    if (tid == 0) {
        const float cnt  = (float)(C2d * KVd);
        float mean = tot / cnt;
        float var  = totq / cnt - mean * mean;
        float a    = rsqrtf((float)KVd);
        scale[z]   = a * rsqrtf(a * a * var + 1e-5f);
    }
}

// ---------------- row softmax over k (in place) -------------------------------
__global__ void softmax_kernel(float* __restrict__ S, const float* __restrict__ scale)
{
    const long row = blockIdx.x;                 // z*C2 + c
    const int  tid = threadIdx.x;
    float* p = S + row * KVd;
    const float sc = scale[blockIdx.x >> 9];     // /512
    __shared__ float sh[256];

    float v[7];
    float mx = -1e30f;
#pragma unroll
    for (int j = 0; j < 7; ++j) { v[j] = p[tid + j * 256]; mx = fmaxf(mx, v[j]); }
    sh[tid] = mx; __syncthreads();
    for (int o = 128; o; o >>= 1) { if (tid < o) sh[tid] = fmaxf(sh[tid], sh[tid + o]); __syncthreads(); }
    mx = sh[0]; __syncthreads();

    float s = 0.f;
#pragma unroll
    for (int j = 0; j < 7; ++j) { v[j] = __expf((v[j] - mx) * sc); s += v[j]; }
    sh[tid] = s; __syncthreads();
    for (int o = 128; o; o >>= 1) { if (tid < o) sh[tid] += sh[tid + o]; __syncthreads(); }
    const float inv = 1.f / sh[0];
#pragma unroll
    for (int j = 0; j < 7; ++j) p[tid + j * 256] = v[j] * inv;
}

// ---------------- launcher ----------------------------------------------------
extern "C" void kernel_launch(void* const* d_in, const int* in_sizes, int n_in,
                              void* d_out, int out_size)
{
    const float* emb1   = (const float*)d_in[0];
    const float* emb2   = (const float*)d_in[1];
    const float* emb3   = (const float*)d_in[2];
    const float* Wq     = (const float*)d_in[3];
    const float* Wk     = (const float*)d_in[4];
    const float* Wv     = (const float*)d_in[5];
    const float* Wout   = (const float*)d_in[6];
    const float* ln1_g  = (const float*)d_in[7];
    const float* ln1_b  = (const float*)d_in[8];
    const float* lnall_g= (const float*)d_in[9];
    const float* lnall_b= (const float*)d_in[10];
    const float* lnffn_g= (const float*)d_in[11];
    const float* lnffn_b= (const float*)d_in[12];
    const float* fc1_w  = (const float*)d_in[13];
    const float* fc1_b  = (const float*)d_in[14];
    const float* fc2_w  = (const float*)d_in[15];
    const float* fc2_b  = (const float*)d_in[16];
    float* out = (float*)d_out;

    void *pY, *pX, *pG, *pT1, *pS, *psc, *pM, *pctx, *pcx2, *pZ, *pF;
    cudaGetSymbolAddress(&pY,  g_Y);   cudaGetSymbolAddress(&pX,  g_X);
    cudaGetSymbolAddress(&pG,  g_G);   cudaGetSymbolAddress(&pT1, g_T1);
    cudaGetSymbolAddress(&pS,  g_S);   cudaGetSymbolAddress(&psc, g_sc);
    cudaGetSymbolAddress(&pM,  g_M);   cudaGetSymbolAddress(&pctx, g_ctx);
    cudaGetSymbolAddress(&pcx2, g_cx2); cudaGetSymbolAddress(&pZ, g_Z);
    cudaGetSymbolAddress(&pF,  g_F);
    float *Y=(float*)pY, *X=(float*)pX, *G=(float*)pG, *T1=(float*)pT1, *S=(float*)pS;
    float *scl=(float*)psc, *Mm=(float*)pM, *ctx=(float*)pctx, *cx2=(float*)pcx2;
    float *Z=(float*)pZ, *F=(float*)pF;

    // 1. input LayerNorms
    ln_in_kernel<<<BB * NT, 256>>>(emb1, emb2, emb3, lnall_g, lnall_b, ln1_g, ln1_b, Y, X);

    // 2. G_b = X_b^T Y_b                       [512,1792] per batch
    gemm_k<true, false, 0><<<dim3(KVd / BN, C2d / BM, BB), 256>>>(
        X, Y, G, nullptr, nullptr, C2d, KVd, NT,
        (long)NT * C2d, (long)NT * KVd, (long)C2d * KVd, 0, 0, 1, 0, 0, 1.f);

    // 3. T1[b,h] = Wq_h^T G_b                  [512,1792] per (b,h)
    gemm_k<true, false, 0><<<dim3(KVd / BN, C2d / BM, BB * NHd), 256>>>(
        Wq, G, T1, nullptr, nullptr, C2d, KVd, C2d,
        (long)C2d * C2d, (long)C2d * KVd, (long)C2d * KVd, 1, 2, 1, 0, 0, 1.f);

    // 4. S[b,h] = T1[b,h] Wk_h                 [512,1792] per (b,h)
    gemm_k<false, false, 0><<<dim3(KVd / BN, C2d / BM, BB * NHd), 256>>>(
        T1, Wk, S, nullptr, nullptr, C2d, KVd, KVd,
        (long)C2d * KVd, (long)KVd * KVd, (long)C2d * KVd, 0, 1, 1, 0, 0, 1.f);

    // 5. per-map variance -> softmax scale; 6. row softmax in place
    stats_kernel<<<BB * NHd, 1024>>>(S, scl);
    softmax_kernel<<<BB * NHd * C2d, 256>>>(S, scl);

    // 7. M_b = (1/H) sum_h Wv_h probs[b,h]^T   [1792,512] per batch (h folded into K loop)
    gemm_k<false, true, 0><<<dim3(C2d / BN, KVd / BM, BB), 256>>>(
        Wv, S, Mm, nullptr, nullptr, KVd, C2d, KVd,
        0, (long)NHd * C2d * KVd, (long)KVd * C2d, 0, 0,
        NHd, (long)KVd * KVd, (long)C2d * KVd, 1.f / NHd);

    // 8. ctx_b = Y_b M_b                       [1024,512] per batch
    gemm_k<false, false, 0><<<dim3(C2d / BN, NT / BM, BB), 256>>>(
        Y, Mm, ctx, nullptr, nullptr, NT, C2d, KVd,
        (long)NT * KVd, (long)KVd * C2d, (long)NT * C2d, 0, 0, 1, 0, 0, 1.f);

    // 9. cx2 = ctx @ Wout + emb2               [8192,512]
    gemm_k<false, false, 1><<<dim3(C2d / BN, BB * NT / BM, 1), 256>>>(
        ctx, Wout, cx2, nullptr, emb2, BB * NT, C2d, C2d,
        0, 0, 0, 0, 0, 1, 0, 0, 1.f);

    // 10. Z = LN(cx2)
    ln2_kernel<<<BB * NT, 256>>>(cx2, lnffn_g, lnffn_b, Z);

    // 11. F = gelu(Z @ fc1_w + fc1_b)          [8192,2048]
    gemm_k<false, false, 2><<<dim3(C2E / BN, BB * NT / BM, 1), 256>>>(
        Z, fc1_w, F, fc1_b, nullptr, BB * NT, C2E, C2d,
        0, 0, 0, 0, 0, 1, 0, 0, 1.f);

    // 12. out = F @ fc2_w + fc2_b + cx2        [8192,512]
    gemm_k<false, false, 3><<<dim3(C2d / BN, BB * NT / BM, 1), 256>>>(
        F, fc2_w, out, fc2_b, cx2, BB * NT, C2d, C2E,
        0, 0, 0, 0, 0, 1, 0, 0, 1.f);
}

// round 7
// speedup vs baseline: 1.8564x; 1.8564x over previous
#include <cuda_runtime.h>
#include <cuda_bf16.h>
#include <math.h>
#include <stdint.h>

// Problem constants
#define BB   8
#define NT   1024
#define C1d  256
#define C2d  512
#define C3d  1024
#define KVd  1792
#define NHd  4
#define C2E  2048

// ===================== scratch (device statics) ==============================
__device__ __nv_bfloat16 g_Yh [BB*NT*KVd], g_Yl [BB*NT*KVd];     // LN(concat), [b][n][kv]
__device__ __nv_bfloat16 g_Yth[BB*NT*KVd], g_Ytl[BB*NT*KVd];     // transposed  [b][kv][n]
__device__ __nv_bfloat16 g_Xh [BB*NT*C2d], g_Xl [BB*NT*C2d];     // LN(emb2)    [b][n][c]
__device__ __nv_bfloat16 g_Xth[BB*NT*C2d], g_Xtl[BB*NT*C2d];     // transposed  [b][c][n]
__device__ __nv_bfloat16 g_Gth[BB*KVd*C2d], g_Gtl[BB*KVd*C2d];   // Gt = Yt Xt^T [b][kv][c]
__device__ __nv_bfloat16 g_T1h[BB*NHd*C2d*KVd], g_T1l[BB*NHd*C2d*KVd];
__device__ float         g_S  [BB*NHd*C2d*KVd];                  // scores fp32
__device__ __nv_bfloat16 g_Ph [BB*NHd*C2d*KVd], g_Pl [BB*NHd*C2d*KVd]; // probs
__device__ __nv_bfloat16 g_Mth[BB*C2d*KVd], g_Mtl[BB*C2d*KVd];   // Mmt [b][c][e]
__device__ __nv_bfloat16 g_Ch [BB*NT*C2d], g_Cl [BB*NT*C2d];     // ctx
__device__ float         g_cx2[BB*NT*C2d];                       // residual fp32
__device__ __nv_bfloat16 g_Zh [BB*NT*C2d], g_Zl [BB*NT*C2d];     // LN(cx2)
__device__ __nv_bfloat16 g_Fh [BB*NT*C2E], g_Fl [BB*NT*C2E];     // gelu(fc1)
// weights (pre-transposed + split)
__device__ __nv_bfloat16 g_WqTh[NHd*C2d*C2d], g_WqTl[NHd*C2d*C2d];
__device__ __nv_bfloat16 g_WkTh[NHd*KVd*KVd], g_WkTl[NHd*KVd*KVd];
__device__ __nv_bfloat16 g_Wvh [NHd*KVd*KVd], g_Wvl [NHd*KVd*KVd];
__device__ __nv_bfloat16 g_WoTh[C2d*C2d],     g_WoTl[C2d*C2d];
__device__ __nv_bfloat16 g_f1Th[C2E*C2d],     g_f1Tl[C2E*C2d];
__device__ __nv_bfloat16 g_f2Th[C2d*C2E],     g_f2Tl[C2d*C2E];
__device__ float g_sc[BB*NHd];

// ===================== PTX helpers (baseline sm_80+ only) ====================
__device__ __forceinline__ uint32_t smem_u32(const void* p) {
    uint32_t a;
    asm("{ .reg .u64 t; cvta.to.shared.u64 t, %1; cvt.u32.u64 %0, t; }" : "=r"(a) : "l"(p));
    return a;
}
#define CPA16(d, s)   asm volatile("cp.async.cg.shared.global [%0], [%1], 16;" :: "r"(d), "l"(s))
#define CPA_COMMIT()  asm volatile("cp.async.commit_group;" ::: "memory")
#define CPA_WAIT1()   asm volatile("cp.async.wait_group 1;" ::: "memory")
#define CPA_WAIT0()   asm volatile("cp.async.wait_group 0;" ::: "memory")

#define LDSM4(r, a) \
    asm volatile("ldmatrix.sync.aligned.m8n8.x4.shared.b16 {%0,%1,%2,%3}, [%4];" \
        : "=r"((r)[0]), "=r"((r)[1]), "=r"((r)[2]), "=r"((r)[3]) : "r"(a))

#define MMA16816(C, A, B0, B1) \
    asm volatile("mma.sync.aligned.m16n8k16.row.col.f32.bf16.bf16.f32 " \
        "{%0,%1,%2,%3}, {%4,%5,%6,%7}, {%8,%9}, {%0,%1,%2,%3};" \
        : "+f"((C)[0]), "+f"((C)[1]), "+f"((C)[2]), "+f"((C)[3]) \
        : "r"((A)[0]), "r"((A)[1]), "r"((A)[2]), "r"((A)[3]), "r"(B0), "r"(B1))

__device__ __forceinline__ void splt(float v, __nv_bfloat16& h, __nv_bfloat16& l) {
    h = __float2bfloat16(v);
    l = __float2bfloat16(v - __bfloat162float(h));
}
__device__ __forceinline__ int selidx(int mode, int z) {
    return mode == 0 ? z : (mode == 1 ? (z & 3) : (z >> 2));
}

// ===================== mma.sync split-bf16 GEMM ==============================
// C[M,Nn] = outScale * sum_h A_h[M,K] * B_h[N,K]^T  (+ epilogue)
// EPI: 0 none, 1 +add, 2 +bias,gelu, 3 +bias+add.  OUT: 0 fp32, 1 bf16 hi/lo
#define BKC    32                   // k per chunk (bf16 elems)
#define PADE   40                   // smem row stride in elems (80 B)
#define TILEB  (128 * PADE * 2)     // 10240 B per tile
#define STAGEB (4 * TILEB)          // 40960 B per stage (Ah,Al,Bh,Bl)
#define SMEMSZ (2 * STAGEB)         // 81920 B

template<int EPI, int OUT>
__global__ __launch_bounds__(256)
void mma_gemm(const __nv_bfloat16* __restrict__ Ahi, const __nv_bfloat16* __restrict__ Alo,
              const __nv_bfloat16* __restrict__ Bhi, const __nv_bfloat16* __restrict__ Blo,
              float* __restrict__ C, __nv_bfloat16* __restrict__ Chi, __nv_bfloat16* __restrict__ Clo,
              const float* __restrict__ bias, const float* __restrict__ addp,
              int M, int Nn, int K, int lda, int ldb,
              long sA, long sB, long sC, int selA, int selB,
              int nH, long hA, long hB, float outScale)
{
    extern __shared__ char smem[];
    const uint32_t sb = smem_u32(smem);
    const int tid = threadIdx.x, wid = tid >> 5, lane = tid & 31;
    const int z = blockIdx.z;
    const int m0 = blockIdx.y * 128, n0 = blockIdx.x * 128;
    const int warpM = (wid & 3) * 32, warpN = (wid >> 2) * 64;

    const __nv_bfloat16* A0h = Ahi + (long)selidx(selA, z) * sA;
    const __nv_bfloat16* A0l = Alo + (long)selidx(selA, z) * sA;
    const __nv_bfloat16* B0h = Bhi + (long)selidx(selB, z) * sB;
    const __nv_bfloat16* B0l = Blo + (long)selidx(selB, z) * sB;

    const int nchK = K >> 5;        // chunks of 32
    const int nch  = nH * nchK;

    // stage a chunk of all four operand tiles via cp.async (one commit group)
    auto issue = [&](int ch) {
        const uint32_t so = sb + (uint32_t)(ch & 1) * STAGEB;
        const int h  = ch / nchK;
        const int k0 = (ch - h * nchK) << 5;
        const __nv_bfloat16* srcs[4] = { A0h + (long)h * hA, A0l + (long)h * hA,
                                         B0h + (long)h * hB, B0l + (long)h * hB };
#pragma unroll
        for (int t4 = 0; t4 < 4; ++t4) {
            const int ld = (t4 < 2) ? lda : ldb;
            const int rb = (t4 < 2) ? m0  : n0;
            const uint32_t to = so + t4 * TILEB;
#pragma unroll
            for (int it = 0; it < 2; ++it) {
                const int idx = tid + it * 256;       // 0..511
                const int row = idx >> 2, seg = idx & 3;
                const __nv_bfloat16* g = srcs[t4] + (long)(rb + row) * ld + k0 + seg * 8;
                CPA16(to + row * 80 + seg * 16, g);
            }
        }
        CPA_COMMIT();
    };

    float acc[2][8][4];
#pragma unroll
    for (int i = 0; i < 2; ++i)
#pragma unroll
        for (int j = 0; j < 8; ++j)
#pragma unroll
            for (int k = 0; k < 4; ++k) acc[i][j][k] = 0.f;

    issue(0);
    issue(1);

    // ldmatrix lane address components
    const uint32_t aRow = (uint32_t)(warpM + (lane & 15)) * 80 + ((lane >> 4) << 4);
    const uint32_t bRow = (uint32_t)(warpN + (((lane >> 3) >> 1) << 3) + (lane & 7)) * 80
                        + (((lane >> 3) & 1) << 4);

    for (int ch = 0; ch < nch; ++ch) {
        if (ch < nch - 1) { CPA_WAIT1(); } else { CPA_WAIT0(); }
        __syncthreads();
        const uint32_t so = sb + (uint32_t)(ch & 1) * STAGEB;
#pragma unroll
        for (int ks = 0; ks < 2; ++ks) {
            const uint32_t kb = ks * 32;
            uint32_t ah[2][4], al[2][4], bb[4][4];
#pragma unroll
            for (int mf = 0; mf < 2; ++mf) {
                const uint32_t ad = so + aRow + (uint32_t)(mf * 16 * 80) + kb;
                LDSM4(ah[mf], ad);
                LDSM4(al[mf], ad + TILEB);
            }
#pragma unroll
            for (int q = 0; q < 4; ++q)
                LDSM4(bb[q], so + 2 * TILEB + bRow + (uint32_t)(q * 16 * 80) + kb);
            // pass 1: Ah*Bh, pass 2: Al*Bh
#pragma unroll
            for (int mf = 0; mf < 2; ++mf)
#pragma unroll
                for (int nf = 0; nf < 8; ++nf) {
                    const uint32_t b0 = bb[nf >> 1][(nf & 1) * 2];
                    const uint32_t b1 = bb[nf >> 1][(nf & 1) * 2 + 1];
                    MMA16816(acc[mf][nf], ah[mf], b0, b1);
                    MMA16816(acc[mf][nf], al[mf], b0, b1);
                }
            // reload Bl over bb; pass 3: Ah*Bl
#pragma unroll
            for (int q = 0; q < 4; ++q)
                LDSM4(bb[q], so + 3 * TILEB + bRow + (uint32_t)(q * 16 * 80) + kb);
#pragma unroll
            for (int mf = 0; mf < 2; ++mf)
#pragma unroll
                for (int nf = 0; nf < 8; ++nf)
                    MMA16816(acc[mf][nf], ah[mf],
                             bb[nf >> 1][(nf & 1) * 2], bb[nf >> 1][(nf & 1) * 2 + 1]);
        }
        __syncthreads();
        if (ch + 2 < nch) issue(ch + 2);
    }

    // ---- epilogue (register accumulators -> gmem)
    const int rbase = m0 + warpM + (lane >> 2);
    const int cbase = n0 + warpN + (lane & 3) * 2;
#pragma unroll
    for (int mf = 0; mf < 2; ++mf) {
#pragma unroll
        for (int h2 = 0; h2 < 2; ++h2) {
            const long m = rbase + mf * 16 + h2 * 8;
#pragma unroll
            for (int nf = 0; nf < 8; ++nf) {
                const long col = cbase + nf * 8;
                float v0 = acc[mf][nf][h2 * 2]     * outScale;
                float v1 = acc[mf][nf][h2 * 2 + 1] * outScale;
                if (EPI == 1) {
                    const float2 ad = *(const float2*)(addp + m * Nn + col);
                    v0 += ad.x; v1 += ad.y;
                }
                if (EPI == 2) {
                    v0 += bias[col]; v1 += bias[col + 1];
                    v0 = 0.5f * v0 * (1.f + erff(v0 * 0.70710678118654752f));
                    v1 = 0.5f * v1 * (1.f + erff(v1 * 0.70710678118654752f));
                }
                if (EPI == 3) {
                    const float2 ad = *(const float2*)(addp + m * Nn + col);
                    v0 += bias[col]     + ad.x;
                    v1 += bias[col + 1] + ad.y;
                }
                const long idx = (long)z * sC + m * Nn + col;
                if (OUT == 0) {
                    *(float2*)(C + idx) = make_float2(v0, v1);
                } else {
                    __nv_bfloat16 h0, l0, h1, l1;
                    splt(v0, h0, l0); splt(v1, h1, l1);
                    __nv_bfloat162 hv; hv.x = h0; hv.y = h1;
                    __nv_bfloat162 lv; lv.x = l0; lv.y = l1;
                    *(__nv_bfloat162*)(Chi + idx) = hv;
                    *(__nv_bfloat162*)(Clo + idx) = lv;
                }
            }
        }
    }
}

// ===================== prep kernels =========================================
// fp32 [Z][R][C] -> hi/lo bf16 [Z][C][R]
__global__ void tsplit_k(const float* __restrict__ in, __nv_bfloat16* __restrict__ oh,
                         __nv_bfloat16* __restrict__ ol, int R, int Cc)
{
    __shared__ float t[32][33];
    const long zo = (long)blockIdx.z * R * Cc;
    const int c0 = blockIdx.x * 32, r0 = blockIdx.y * 32;
    const int x = threadIdx.x, y = threadIdx.y;
#pragma unroll
    for (int j = 0; j < 32; j += 8) t[y + j][x] = in[zo + (long)(r0 + y + j) * Cc + c0 + x];
    __syncthreads();
#pragma unroll
    for (int j = 0; j < 32; j += 8) {
        float v = t[x][y + j];
        __nv_bfloat16 h, l; splt(v, h, l);
        const long o = zo + (long)(c0 + y + j) * R + r0 + x;
        oh[o] = h; ol[o] = l;
    }
}

// fp32 -> hi/lo bf16 (same layout)
__global__ void psplit_k(const float* __restrict__ in, __nv_bfloat16* __restrict__ oh,
                         __nv_bfloat16* __restrict__ ol, long n4)
{
    for (long i = blockIdx.x * blockDim.x + threadIdx.x; i < n4; i += (long)gridDim.x * blockDim.x) {
        float4 v = ((const float4*)in)[i];
        __nv_bfloat16 hh[4], ll[4];
        splt(v.x, hh[0], ll[0]); splt(v.y, hh[1], ll[1]);
        splt(v.z, hh[2], ll[2]); splt(v.w, hh[3], ll[3]);
        ((uint2*)oh)[i] = *(uint2*)hh;
        ((uint2*)ol)[i] = *(uint2*)ll;
    }
}

// bf16 [Z][R][C] -> [Z][C][R]
__global__ void tb16_k(const __nv_bfloat16* __restrict__ in, __nv_bfloat16* __restrict__ out,
                       int R, int Cc)
{
    __shared__ __nv_bfloat16 t[32][33];
    const long zo = (long)blockIdx.z * R * Cc;
    const int c0 = blockIdx.x * 32, r0 = blockIdx.y * 32;
    const int x = threadIdx.x, y = threadIdx.y;
#pragma unroll
    for (int j = 0; j < 32; j += 8) t[y + j][x] = in[zo + (long)(r0 + y + j) * Cc + c0 + x];
    __syncthreads();
#pragma unroll
    for (int j = 0; j < 32; j += 8) out[zo + (long)(c0 + y + j) * R + r0 + x] = t[x][y + j];
}

// input LayerNorms -> split outputs
__global__ void ln_in_kernel(const float* __restrict__ e1, const float* __restrict__ e2,
                             const float* __restrict__ e3,
                             const float* __restrict__ ag, const float* __restrict__ ab,
                             const float* __restrict__ g1, const float* __restrict__ b1,
                             __nv_bfloat16* __restrict__ Yh, __nv_bfloat16* __restrict__ Yl,
                             __nv_bfloat16* __restrict__ Xh, __nv_bfloat16* __restrict__ Xl)
{
    const long row = blockIdx.x;
    const int  tid = threadIdx.x;
    const float* p1 = e1 + row * C1d;
    const float* p2 = e2 + row * C2d;
    const float* p3 = e3 + row * C3d;
    __shared__ float sh[256];

    float v[7], s = 0.f, q = 0.f;
#pragma unroll
    for (int j = 0; j < 7; ++j) {
        int i = tid + j * 256;
        float x;
        if (j == 0)      x = p1[i];
        else if (j <= 2) x = p2[i - C1d];
        else             x = p3[i - (C1d + C2d)];
        v[j] = x; s += x; q += x * x;
    }
    sh[tid] = s; __syncthreads();
    for (int o = 128; o; o >>= 1) { if (tid < o) sh[tid] += sh[tid + o]; __syncthreads(); }
    float tot = sh[0]; __syncthreads();
    sh[tid] = q; __syncthreads();
    for (int o = 128; o; o >>= 1) { if (tid < o) sh[tid] += sh[tid + o]; __syncthreads(); }
    float totq = sh[0]; __syncthreads();
    float mean = tot * (1.f / KVd);
    float inv  = rsqrtf(totq * (1.f / KVd) - mean * mean + 1e-6f);
#pragma unroll
    for (int j = 0; j < 7; ++j) {
        int i = tid + j * 256;
        float y = (v[j] - mean) * inv * ag[i] + ab[i];
        __nv_bfloat16 h, l; splt(y, h, l);
        Yh[row * KVd + i] = h; Yl[row * KVd + i] = l;
    }
    float u0 = p2[tid], u1 = p2[tid + 256];
    s = u0 + u1; q = u0 * u0 + u1 * u1;
    sh[tid] = s; __syncthreads();
    for (int o = 128; o; o >>= 1) { if (tid < o) sh[tid] += sh[tid + o]; __syncthreads(); }
    tot = sh[0]; __syncthreads();
    sh[tid] = q; __syncthreads();
    for (int o = 128; o; o >>= 1) { if (tid < o) sh[tid] += sh[tid + o]; __syncthreads(); }
    totq = sh[0];
    mean = tot * (1.f / C2d);
    inv  = rsqrtf(totq * (1.f / C2d) - mean * mean + 1e-6f);
    {
        float y0 = (u0 - mean) * inv * g1[tid] + b1[tid];
        float y1 = (u1 - mean) * inv * g1[tid + 256] + b1[tid + 256];
        __nv_bfloat16 h, l;
        splt(y0, h, l); Xh[row * C2d + tid] = h;       Xl[row * C2d + tid] = l;
        splt(y1, h, l); Xh[row * C2d + tid + 256] = h; Xl[row * C2d + tid + 256] = l;
    }
}

__global__ void ln2_kernel(const float* __restrict__ in,
                           const float* __restrict__ g, const float* __restrict__ b,
                           __nv_bfloat16* __restrict__ Zh, __nv_bfloat16* __restrict__ Zl)
{
    const long row = blockIdx.x;
    const int  tid = threadIdx.x;
    const float* p = in + row * C2d;
    __shared__ float sh[256];
    float u0 = p[tid], u1 = p[tid + 256];
    float s = u0 + u1, q = u0 * u0 + u1 * u1;
    sh[tid] = s; __syncthreads();
    for (int o = 128; o; o >>= 1) { if (tid < o) sh[tid] += sh[tid + o]; __syncthreads(); }
    float tot = sh[0]; __syncthreads();
    sh[tid] = q; __syncthreads();
    for (int o = 128; o; o >>= 1) { if (tid < o) sh[tid] += sh[tid + o]; __syncthreads(); }
    float totq = sh[0];
    float mean = tot * (1.f / C2d);
    float inv  = rsqrtf(totq * (1.f / C2d) - mean * mean + 1e-6f);
    __nv_bfloat16 h, l;
    splt((u0 - mean) * inv * g[tid] + b[tid], h, l);
    Zh[row * C2d + tid] = h; Zl[row * C2d + tid] = l;
    splt((u1 - mean) * inv * g[tid + 256] + b[tid + 256], h, l);
    Zh[row * C2d + tid + 256] = h; Zl[row * C2d + tid + 256] = l;
}

__global__ void stats_kernel(const float* __restrict__ S, float* __restrict__ scale)
{
    const int z = blockIdx.x, tid = threadIdx.x;
    const float4* p = (const float4*)(S + (long)z * C2d * KVd);
    const int n4 = C2d * KVd / 4;
    float s = 0.f, q = 0.f;
    for (int i = tid; i < n4; i += 1024) {
        float4 v = p[i];
        s += v.x + v.y + v.z + v.w;
        q += v.x * v.x + v.y * v.y + v.z * v.z + v.w * v.w;
    }
    __shared__ float sh[1024];
    sh[tid] = s; __syncthreads();
    for (int o = 512; o; o >>= 1) { if (tid < o) sh[tid] += sh[tid + o]; __syncthreads(); }
    float tot = sh[0]; __syncthreads();
    sh[tid] = q; __syncthreads();
    for (int o = 512; o; o >>= 1) { if (tid < o) sh[tid] += sh[tid + o]; __syncthreads(); }
    float totq = sh[0];
    if (tid == 0) {
        const float cnt = (float)(C2d * KVd);
        float mean = tot / cnt;
        float var  = totq / cnt - mean * mean;
        float a    = rsqrtf((float)KVd);
        scale[z]   = a * rsqrtf(a * a * var + 1e-5f);
    }
}

__global__ void softmax_kernel(const float* __restrict__ S, const float* __restrict__ scale,
                               __nv_bfloat16* __restrict__ Ph, __nv_bfloat16* __restrict__ Pl)
{
    const long row = blockIdx.x;
    const int  tid = threadIdx.x;
    const float* p = S + row * KVd;
    const float sc = scale[blockIdx.x >> 9];
    __shared__ float sh[256];
    float v[7], mx = -1e30f;
#pragma unroll
    for (int j = 0; j < 7; ++j) { v[j] = p[tid + j * 256]; mx = fmaxf(mx, v[j]); }
    sh[tid] = mx; __syncthreads();
    for (int o = 128; o; o >>= 1) { if (tid < o) sh[tid] = fmaxf(sh[tid], sh[tid + o]); __syncthreads(); }
    mx = sh[0]; __syncthreads();
    float s = 0.f;
#pragma unroll
    for (int j = 0; j < 7; ++j) { v[j] = __expf((v[j] - mx) * sc); s += v[j]; }
    sh[tid] = s; __syncthreads();
    for (int o = 128; o; o >>= 1) { if (tid < o) sh[tid] += sh[tid + o]; __syncthreads(); }
    const float inv = 1.f / sh[0];
#pragma unroll
    for (int j = 0; j < 7; ++j) {
        __nv_bfloat16 h, l; splt(v[j] * inv, h, l);
        Ph[row * KVd + tid + j * 256] = h;
        Pl[row * KVd + tid + j * 256] = l;
    }
}

// ===================== launcher =============================================
#define SYM(v, t, s) t* v; { void* _p; cudaGetSymbolAddress(&_p, s); v = (t*)_p; }

extern "C" void kernel_launch(void* const* d_in, const int* in_sizes, int n_in,
                              void* d_out, int out_size)
{
    const float* emb1    = (const float*)d_in[0];
    const float* emb2    = (const float*)d_in[1];
    const float* emb3    = (const float*)d_in[2];
    const float* Wq      = (const float*)d_in[3];
    const float* Wk      = (const float*)d_in[4];
    const float* Wv      = (const float*)d_in[5];
    const float* Wout    = (const float*)d_in[6];
    const float* ln1_g   = (const float*)d_in[7];
    const float* ln1_b   = (const float*)d_in[8];
    const float* lnall_g = (const float*)d_in[9];
    const float* lnall_b = (const float*)d_in[10];
    const float* lnffn_g = (const float*)d_in[11];
    const float* lnffn_b = (const float*)d_in[12];
    const float* fc1_w   = (const float*)d_in[13];
    const float* fc1_b   = (const float*)d_in[14];
    const float* fc2_w   = (const float*)d_in[15];
    const float* fc2_b   = (const float*)d_in[16];
    float* out = (float*)d_out;

    SYM(Yh, __nv_bfloat16, g_Yh)   SYM(Yl, __nv_bfloat16, g_Yl)
    SYM(Yth, __nv_bfloat16, g_Yth) SYM(Ytl, __nv_bfloat16, g_Ytl)
    SYM(Xh, __nv_bfloat16, g_Xh)   SYM(Xl, __nv_bfloat16, g_Xl)
    SYM(Xth, __nv_bfloat16, g_Xth) SYM(Xtl, __nv_bfloat16, g_Xtl)
    SYM(Gth, __nv_bfloat16, g_Gth) SYM(Gtl, __nv_bfloat16, g_Gtl)
    SYM(T1h, __nv_bfloat16, g_T1h) SYM(T1l, __nv_bfloat16, g_T1l)
    SYM(S, float, g_S)
    SYM(Ph, __nv_bfloat16, g_Ph)   SYM(Pl, __nv_bfloat16, g_Pl)
    SYM(Mth, __nv_bfloat16, g_Mth) SYM(Mtl, __nv_bfloat16, g_Mtl)
    SYM(Ch, __nv_bfloat16, g_Ch)   SYM(Cl, __nv_bfloat16, g_Cl)
    SYM(cx2, float, g_cx2)
    SYM(Zh, __nv_bfloat16, g_Zh)   SYM(Zl, __nv_bfloat16, g_Zl)
    SYM(Fh, __nv_bfloat16, g_Fh)   SYM(Fl, __nv_bfloat16, g_Fl)
    SYM(WqTh, __nv_bfloat16, g_WqTh) SYM(WqTl, __nv_bfloat16, g_WqTl)
    SYM(WkTh, __nv_bfloat16, g_WkTh) SYM(WkTl, __nv_bfloat16, g_WkTl)
    SYM(Wvh, __nv_bfloat16, g_Wvh)   SYM(Wvl, __nv_bfloat16, g_Wvl)
    SYM(WoTh, __nv_bfloat16, g_WoTh) SYM(WoTl, __nv_bfloat16, g_WoTl)
    SYM(f1Th, __nv_bfloat16, g_f1Th) SYM(f1Tl, __nv_bfloat16, g_f1Tl)
    SYM(f2Th, __nv_bfloat16, g_f2Th) SYM(f2Tl, __nv_bfloat16, g_f2Tl)
    SYM(scl, float, g_sc)

    cudaFuncSetAttribute(mma_gemm<0, 0>, cudaFuncAttributeMaxDynamicSharedMemorySize, SMEMSZ);
    cudaFuncSetAttribute(mma_gemm<0, 1>, cudaFuncAttributeMaxDynamicSharedMemorySize, SMEMSZ);
    cudaFuncSetAttribute(mma_gemm<1, 0>, cudaFuncAttributeMaxDynamicSharedMemorySize, SMEMSZ);
    cudaFuncSetAttribute(mma_gemm<2, 1>, cudaFuncAttributeMaxDynamicSharedMemorySize, SMEMSZ);
    cudaFuncSetAttribute(mma_gemm<3, 0>, cudaFuncAttributeMaxDynamicSharedMemorySize, SMEMSZ);

    const dim3 t32(32, 8);
    // weight prep: transpose+split / split
    tsplit_k<<<dim3(C2d / 32, C2d / 32, NHd), t32>>>(Wq, WqTh, WqTl, C2d, C2d);
    tsplit_k<<<dim3(KVd / 32, KVd / 32, NHd), t32>>>(Wk, WkTh, WkTl, KVd, KVd);
    tsplit_k<<<dim3(C2d / 32, C2d / 32, 1), t32>>>(Wout, WoTh, WoTl, C2d, C2d);
    tsplit_k<<<dim3(C2E / 32, C2d / 32, 1), t32>>>(fc1_w, f1Th, f1Tl, C2d, C2E);
    tsplit_k<<<dim3(C2d / 32, C2E / 32, 1), t32>>>(fc2_w, f2Th, f2Tl, C2E, C2d);
    psplit_k<<<4096, 256>>>(Wv, Wvh, Wvl, (long)NHd * KVd * KVd / 4);

    // 1. input LayerNorms (split outputs)
    ln_in_kernel<<<BB * NT, 256>>>(emb1, emb2, emb3, lnall_g, lnall_b, ln1_g, ln1_b,
                                   Yh, Yl, Xh, Xl);
    // transposes for step 2
    tb16_k<<<dim3(KVd / 32, NT / 32, BB), t32>>>(Yh, Yth, NT, KVd);
    tb16_k<<<dim3(KVd / 32, NT / 32, BB), t32>>>(Yl, Ytl, NT, KVd);
    tb16_k<<<dim3(C2d / 32, NT / 32, BB), t32>>>(Xh, Xth, NT, C2d);
    tb16_k<<<dim3(C2d / 32, NT / 32, BB), t32>>>(Xl, Xtl, NT, C2d);

    // 2. Gt_b = Yt_b Xt_b^T  [1792,512], K=1024
    mma_gemm<0, 1><<<dim3(C2d / 128, KVd / 128, BB), 256, SMEMSZ>>>(
        Yth, Ytl, Xth, Xtl, nullptr, Gth, Gtl, nullptr, nullptr,
        KVd, C2d, NT, NT, NT,
        (long)KVd * NT, (long)C2d * NT, (long)KVd * C2d, 0, 0, 1, 0, 0, 1.f);

    // 3. T1[b,h] = WqT_h Gt_b^T  [512,1792], K=512
    mma_gemm<0, 1><<<dim3(KVd / 128, C2d / 128, BB * NHd), 256, SMEMSZ>>>(
        WqTh, WqTl, Gth, Gtl, nullptr, T1h, T1l, nullptr, nullptr,
        C2d, KVd, C2d, C2d, C2d,
        (long)C2d * C2d, (long)KVd * C2d, (long)C2d * KVd, 1, 2, 1, 0, 0, 1.f);

    // 4. S[b,h] = T1 WkT_h^T  [512,1792], K=1792 (fp32 out)
    mma_gemm<0, 0><<<dim3(KVd / 128, C2d / 128, BB * NHd), 256, SMEMSZ>>>(
        T1h, T1l, WkTh, WkTl, S, nullptr, nullptr, nullptr, nullptr,
        C2d, KVd, KVd, KVd, KVd,
        (long)C2d * KVd, (long)KVd * KVd, (long)C2d * KVd, 0, 1, 1, 0, 0, 1.f);

    // 5-6. instance-norm stats + row softmax (writes split probs)
    stats_kernel<<<BB * NHd, 1024>>>(S, scl);
    softmax_kernel<<<BB * NHd * C2d, 256>>>(S, scl, Ph, Pl);

    // 7. Mmt_b[c,e] = (1/H) sum_h sum_k P[b,h,c,k] Wv_h[e,k]  [512,1792]
    mma_gemm<0, 1><<<dim3(KVd / 128, C2d / 128, BB), 256, SMEMSZ>>>(
        Ph, Pl, Wvh, Wvl, nullptr, Mth, Mtl, nullptr, nullptr,
        C2d, KVd, KVd, KVd, KVd,
        (long)NHd * C2d * KVd, 0, (long)C2d * KVd, 0, 0,
        NHd, (long)C2d * KVd, (long)KVd * KVd, 1.f / NHd);

    // 8. ctx_b = Y_b Mmt_b^T  [1024,512], K=1792
    mma_gemm<0, 1><<<dim3(C2d / 128, NT / 128, BB), 256, SMEMSZ>>>(
        Yh, Yl, Mth, Mtl, nullptr, Ch, Cl, nullptr, nullptr,
        NT, C2d, KVd, KVd, KVd,
        (long)NT * KVd, (long)C2d * KVd, (long)NT * C2d, 0, 0, 1, 0, 0, 1.f);

    // 9. cx2 = ctx WoutT^T + emb2  [8192,512]
    mma_gemm<1, 0><<<dim3(C2d / 128, BB * NT / 128, 1), 256, SMEMSZ>>>(
        Ch, Cl, WoTh, WoTl, cx2, nullptr, nullptr, nullptr, emb2,
        BB * NT, C2d, C2d, C2d, C2d, 0, 0, 0, 0, 0, 1, 0, 0, 1.f);

    // 10. Z = LN(cx2) (split out)
    ln2_kernel<<<BB * NT, 256>>>(cx2, lnffn_g, lnffn_b, Zh, Zl);

    // 11. F = gelu(Z f1T^T + b1)  [8192,2048]
    mma_gemm<2, 1><<<dim3(C2E / 128, BB * NT / 128, 1), 256, SMEMSZ>>>(
        Zh, Zl, f1Th, f1Tl, nullptr, Fh, Fl, fc1_b, nullptr,
        BB * NT, C2E, C2d, C2d, C2d, 0, 0, 0, 0, 0, 1, 0, 0, 1.f);

    // 12. out = F f2T^T + b2 + cx2  [8192,512]
    mma_gemm<3, 0><<<dim3(C2d / 128, BB * NT / 128, 1), 256, SMEMSZ>>>(
        Fh, Fl, f2Th, f2Tl, out, nullptr, nullptr, fc2_b, cx2,
        BB * NT, C2d, C2E, C2E, C2E, 0, 0, 0, 0, 0, 1, 0, 0, 1.f);
}

// round 8
// speedup vs baseline: 2.2010x; 1.1856x over previous
#include <cuda_runtime.h>
#include <cuda_bf16.h>
#include <math.h>
#include <stdint.h>

// Problem constants
#define BB   8
#define NT   1024
#define C1d  256
#define C2d  512
#define C3d  1024
#define KVd  1792
#define NHd  4
#define C2E  2048

// ===================== scratch (device statics) ==============================
__device__ __nv_bfloat16 g_Yh [BB*NT*KVd], g_Yl [BB*NT*KVd];     // LN(concat), [b][n][kv]
__device__ __nv_bfloat16 g_Yth[BB*NT*KVd], g_Ytl[BB*NT*KVd];     // transposed  [b][kv][n]
__device__ __nv_bfloat16 g_Xh [BB*NT*C2d], g_Xl [BB*NT*C2d];     // LN(emb2)    [b][n][c]
__device__ __nv_bfloat16 g_Xth[BB*NT*C2d], g_Xtl[BB*NT*C2d];     // transposed  [b][c][n]
__device__ __nv_bfloat16 g_Gth[BB*KVd*C2d], g_Gtl[BB*KVd*C2d];   // Gt = Yt Xt^T [b][kv][c]
__device__ __nv_bfloat16 g_T1h[BB*NHd*C2d*KVd], g_T1l[BB*NHd*C2d*KVd];
__device__ float         g_S  [BB*NHd*C2d*KVd];                  // scores fp32
__device__ __nv_bfloat16 g_Ph [BB*NHd*C2d*KVd], g_Pl [BB*NHd*C2d*KVd]; // probs
__device__ __nv_bfloat16 g_Mth[BB*C2d*KVd], g_Mtl[BB*C2d*KVd];   // Mmt [b][c][e]
__device__ __nv_bfloat16 g_Ch [BB*NT*C2d], g_Cl [BB*NT*C2d];     // ctx
__device__ float         g_cx2[BB*NT*C2d];                       // residual fp32
__device__ __nv_bfloat16 g_Zh [BB*NT*C2d], g_Zl [BB*NT*C2d];     // LN(cx2)
__device__ __nv_bfloat16 g_Fh [BB*NT*C2E], g_Fl [BB*NT*C2E];     // gelu(fc1)
// weights (pre-transposed + split)
__device__ __nv_bfloat16 g_WqTh[NHd*C2d*C2d], g_WqTl[NHd*C2d*C2d];
__device__ __nv_bfloat16 g_WkTh[NHd*KVd*KVd], g_WkTl[NHd*KVd*KVd];
__device__ __nv_bfloat16 g_Wvh [NHd*KVd*KVd], g_Wvl [NHd*KVd*KVd];
__device__ __nv_bfloat16 g_WoTh[C2d*C2d],     g_WoTl[C2d*C2d];
__device__ __nv_bfloat16 g_f1Th[C2E*C2d],     g_f1Tl[C2E*C2d];
__device__ __nv_bfloat16 g_f2Th[C2d*C2E],     g_f2Tl[C2d*C2E];
__device__ float g_sc[BB*NHd];

// ===================== PTX helpers (baseline sm_80+ only) ====================
__device__ __forceinline__ uint32_t smem_u32(const void* p) {
    uint32_t a;
    asm("{ .reg .u64 t; cvta.to.shared.u64 t, %1; cvt.u32.u64 %0, t; }" : "=r"(a) : "l"(p));
    return a;
}
#define CPA16(d, s)   asm volatile("cp.async.cg.shared.global [%0], [%1], 16;" :: "r"(d), "l"(s))
#define CPA_COMMIT()  asm volatile("cp.async.commit_group;" ::: "memory")
#define CPA_WAIT1()   asm volatile("cp.async.wait_group 1;" ::: "memory")
#define CPA_WAIT0()   asm volatile("cp.async.wait_group 0;" ::: "memory")

#define LDSM4(r, a) \
    asm volatile("ldmatrix.sync.aligned.m8n8.x4.shared.b16 {%0,%1,%2,%3}, [%4];" \
        : "=r"((r)[0]), "=r"((r)[1]), "=r"((r)[2]), "=r"((r)[3]) : "r"(a))

#define MMA16816(C, A, B0, B1) \
    asm volatile("mma.sync.aligned.m16n8k16.row.col.f32.bf16.bf16.f32 " \
        "{%0,%1,%2,%3}, {%4,%5,%6,%7}, {%8,%9}, {%0,%1,%2,%3};" \
        : "+f"((C)[0]), "+f"((C)[1]), "+f"((C)[2]), "+f"((C)[3]) \
        : "r"((A)[0]), "r"((A)[1]), "r"((A)[2]), "r"((A)[3]), "r"(B0), "r"(B1))

__device__ __forceinline__ void splt(float v, __nv_bfloat16& h, __nv_bfloat16& l) {
    h = __float2bfloat16(v);
    l = __float2bfloat16(v - __bfloat162float(h));
}
__device__ __forceinline__ int selidx(int mode, int z) {
    return mode == 0 ? z : (mode == 1 ? (z & 3) : (z >> 2));
}

// ===================== mma.sync split-bf16 GEMM ==============================
// C[M,Nn] = outScale * sum_h A_h[M,K] * B_h[N,K]^T  (+ epilogue)
// EPI: 0 none, 1 +add, 2 +bias,gelu, 3 +bias+add.  OUT: 0 fp32, 1 bf16 hi/lo
// BK=64 elems per chunk; smem row stride 144 B (conflict-free for ldmatrix:
// 144 mod 128 = 16 cycles all eight 16B banks across an 8-row group).
#define PADB   144                  // bytes per smem row
#define TILEB  (128 * PADB)         // 18432 B per tile
#define STAGEB (4 * TILEB)          // 73728 B per stage (Ah,Al,Bh,Bl)
#define SMEMSZ (2 * STAGEB)         // 147456 B

template<int EPI, int OUT>
__global__ __launch_bounds__(256, 1)
void mma_gemm(const __nv_bfloat16* __restrict__ Ahi, const __nv_bfloat16* __restrict__ Alo,
              const __nv_bfloat16* __restrict__ Bhi, const __nv_bfloat16* __restrict__ Blo,
              float* __restrict__ C, __nv_bfloat16* __restrict__ Chi, __nv_bfloat16* __restrict__ Clo,
              const float* __restrict__ bias, const float* __restrict__ addp,
              int M, int Nn, int K, int lda, int ldb,
              long sA, long sB, long sC, int selA, int selB,
              int nH, long hA, long hB, float outScale)
{
    extern __shared__ char smem[];
    const uint32_t sb = smem_u32(smem);
    const int tid = threadIdx.x, wid = tid >> 5, lane = tid & 31;
    const int z = blockIdx.z;
    const int m0 = blockIdx.y * 128, n0 = blockIdx.x * 128;
    const int warpM = (wid & 3) * 32, warpN = (wid >> 2) * 64;

    const __nv_bfloat16* A0h = Ahi + (long)selidx(selA, z) * sA;
    const __nv_bfloat16* A0l = Alo + (long)selidx(selA, z) * sA;
    const __nv_bfloat16* B0h = Bhi + (long)selidx(selB, z) * sB;
    const __nv_bfloat16* B0l = Blo + (long)selidx(selB, z) * sB;

    const int nchK = K >> 6;        // chunks of 64
    const int nch  = nH * nchK;

    const int srow = tid >> 3;      // 0..31  (base row for staging)
    const int sseg = tid & 7;       // 16B segment

    // stage a 64-k chunk of all four operand tiles (one commit group)
    auto issue = [&](int ch) {
        const uint32_t so = sb + (uint32_t)(ch & 1) * STAGEB;
        const int h  = ch / nchK;
        const int k0 = (ch - h * nchK) << 6;
        const __nv_bfloat16* srcs[4] = { A0h + (long)h * hA, A0l + (long)h * hA,
                                         B0h + (long)h * hB, B0l + (long)h * hB };
#pragma unroll
        for (int t4 = 0; t4 < 4; ++t4) {
            const int ld = (t4 < 2) ? lda : ldb;
            const int rb = (t4 < 2) ? m0  : n0;
            const __nv_bfloat16* gb = srcs[t4] + (long)(rb + srow) * ld + k0 + sseg * 8;
            const uint32_t tb = so + t4 * TILEB + srow * PADB + sseg * 16;
#pragma unroll
            for (int j = 0; j < 4; ++j)
                CPA16(tb + j * 32 * PADB, gb + (long)(j * 32) * ld);
        }
        CPA_COMMIT();
    };

    float acc[2][8][4];
#pragma unroll
    for (int i = 0; i < 2; ++i)
#pragma unroll
        for (int j = 0; j < 8; ++j)
#pragma unroll
            for (int k = 0; k < 4; ++k) acc[i][j][k] = 0.f;

    issue(0);
    issue(1);

    // ldmatrix lane address components (byte offsets within a tile)
    const uint32_t aRow = (uint32_t)(warpM + (lane & 15)) * PADB + ((lane >> 4) << 4);
    const uint32_t bRow = (uint32_t)(warpN + ((lane >> 4) << 3) + (lane & 7)) * PADB
                        + (((lane >> 3) & 1) << 4);

    for (int ch = 0; ch < nch; ++ch) {
        if (ch < nch - 1) { CPA_WAIT1(); } else { CPA_WAIT0(); }
        __syncthreads();
        const uint32_t so = sb + (uint32_t)(ch & 1) * STAGEB;
#pragma unroll
        for (int ks = 0; ks < 4; ++ks) {
            const uint32_t kb = ks * 32;
            uint32_t ah[2][4], al[2][4], bh[4][4], bl[4][4];
#pragma unroll
            for (int mf = 0; mf < 2; ++mf) {
                const uint32_t ad = so + aRow + (uint32_t)(mf * 16 * PADB) + kb;
                LDSM4(ah[mf], ad);
                LDSM4(al[mf], ad + TILEB);
            }
#pragma unroll
            for (int q = 0; q < 4; ++q) {
                const uint32_t bd = so + 2 * TILEB + bRow + (uint32_t)(q * 16 * PADB) + kb;
                LDSM4(bh[q], bd);
                LDSM4(bl[q], bd + TILEB);
            }
            // three split passes, all fragments live -> no mid-step LDSM stall
#pragma unroll
            for (int mf = 0; mf < 2; ++mf)
#pragma unroll
                for (int nf = 0; nf < 8; ++nf) {
                    const uint32_t bh0 = bh[nf >> 1][(nf & 1) * 2];
                    const uint32_t bh1 = bh[nf >> 1][(nf & 1) * 2 + 1];
                    MMA16816(acc[mf][nf], ah[mf], bh0, bh1);
                    MMA16816(acc[mf][nf], al[mf], bh0, bh1);
                    MMA16816(acc[mf][nf], ah[mf],
                             bl[nf >> 1][(nf & 1) * 2], bl[nf >> 1][(nf & 1) * 2 + 1]);
                }
        }
        __syncthreads();
        if (ch + 2 < nch) issue(ch + 2);
    }

    // ---- epilogue (register accumulators -> gmem)
    const int rbase = m0 + warpM + (lane >> 2);
    const int cbase = n0 + warpN + (lane & 3) * 2;
#pragma unroll
    for (int mf = 0; mf < 2; ++mf) {
#pragma unroll
        for (int h2 = 0; h2 < 2; ++h2) {
            const long m = rbase + mf * 16 + h2 * 8;
#pragma unroll
            for (int nf = 0; nf < 8; ++nf) {
                const long col = cbase + nf * 8;
                float v0 = acc[mf][nf][h2 * 2]     * outScale;
                float v1 = acc[mf][nf][h2 * 2 + 1] * outScale;
                if (EPI == 1) {
                    const float2 ad = *(const float2*)(addp + m * Nn + col);
                    v0 += ad.x; v1 += ad.y;
                }
                if (EPI == 2) {
                    v0 += bias[col]; v1 += bias[col + 1];
                    v0 = 0.5f * v0 * (1.f + erff(v0 * 0.70710678118654752f));
                    v1 = 0.5f * v1 * (1.f + erff(v1 * 0.70710678118654752f));
                }
                if (EPI == 3) {
                    const float2 ad = *(const float2*)(addp + m * Nn + col);
                    v0 += bias[col]     + ad.x;
                    v1 += bias[col + 1] + ad.y;
                }
                const long idx = (long)z * sC + m * Nn + col;
                if (OUT == 0) {
                    *(float2*)(C + idx) = make_float2(v0, v1);
                } else {
                    __nv_bfloat16 h0, l0, h1, l1;
                    splt(v0, h0, l0); splt(v1, h1, l1);
                    __nv_bfloat162 hv; hv.x = h0; hv.y = h1;
                    __nv_bfloat162 lv; lv.x = l0; lv.y = l1;
                    *(__nv_bfloat162*)(Chi + idx) = hv;
                    *(__nv_bfloat162*)(Clo + idx) = lv;
                }
            }
        }
    }
}

// ===================== prep kernels =========================================
// fp32 [Z][R][C] -> hi/lo bf16 [Z][C][R]
__global__ void tsplit_k(const float* __restrict__ in, __nv_bfloat16* __restrict__ oh,
                         __nv_bfloat16* __restrict__ ol, int R, int Cc)
{
    __shared__ float t[32][33];
    const long zo = (long)blockIdx.z * R * Cc;
    const int c0 = blockIdx.x * 32, r0 = blockIdx.y * 32;
    const int x = threadIdx.x, y = threadIdx.y;
#pragma unroll
    for (int j = 0; j < 32; j += 8) t[y + j][x] = in[zo + (long)(r0 + y + j) * Cc + c0 + x];
    __syncthreads();
#pragma unroll
    for (int j = 0; j < 32; j += 8) {
        float v = t[x][y + j];
        __nv_bfloat16 h, l; splt(v, h, l);
        const long o = zo + (long)(c0 + y + j) * R + r0 + x;
        oh[o] = h; ol[o] = l;
    }
}

// fp32 -> hi/lo bf16 (same layout)
__global__ void psplit_k(const float* __restrict__ in, __nv_bfloat16* __restrict__ oh,
                         __nv_bfloat16* __restrict__ ol, long n4)
{
    for (long i = blockIdx.x * blockDim.x + threadIdx.x; i < n4; i += (long)gridDim.x * blockDim.x) {
        float4 v = ((const float4*)in)[i];
        __nv_bfloat16 hh[4], ll[4];
        splt(v.x, hh[0], ll[0]); splt(v.y, hh[1], ll[1]);
        splt(v.z, hh[2], ll[2]); splt(v.w, hh[3], ll[3]);
        ((uint2*)oh)[i] = *(uint2*)hh;
        ((uint2*)ol)[i] = *(uint2*)ll;
    }
}

// bf16 [Z][R][C] -> [Z][C][R]
__global__ void tb16_k(const __nv_bfloat16* __restrict__ in, __nv_bfloat16* __restrict__ out,
                       int R, int Cc)
{
    __shared__ __nv_bfloat16 t[32][33];
    const long zo = (long)blockIdx.z * R * Cc;
    const int c0 = blockIdx.x * 32, r0 = blockIdx.y * 32;
    const int x = threadIdx.x, y = threadIdx.y;
#pragma unroll
    for (int j = 0; j < 32; j += 8) t[y + j][x] = in[zo + (long)(r0 + y + j) * Cc + c0 + x];
    __syncthreads();
#pragma unroll
    for (int j = 0; j < 32; j += 8) out[zo + (long)(c0 + y + j) * R + r0 + x] = t[x][y + j];
}

// input LayerNorms -> split outputs
__global__ void ln_in_kernel(const float* __restrict__ e1, const float* __restrict__ e2,
                             const float* __restrict__ e3,
                             const float* __restrict__ ag, const float* __restrict__ ab,
                             const float* __restrict__ g1, const float* __restrict__ b1,
                             __nv_bfloat16* __restrict__ Yh, __nv_bfloat16* __restrict__ Yl,
                             __nv_bfloat16* __restrict__ Xh, __nv_bfloat16* __restrict__ Xl)
{
    const long row = blockIdx.x;
    const int  tid = threadIdx.x;
    const float* p1 = e1 + row * C1d;
    const float* p2 = e2 + row * C2d;
    const float* p3 = e3 + row * C3d;
    __shared__ float sh[256];

    float v[7], s = 0.f, q = 0.f;
#pragma unroll
    for (int j = 0; j < 7; ++j) {
        int i = tid + j * 256;
        float x;
        if (j == 0)      x = p1[i];
        else if (j <= 2) x = p2[i - C1d];
        else             x = p3[i - (C1d + C2d)];
        v[j] = x; s += x; q += x * x;
    }
    sh[tid] = s; __syncthreads();
    for (int o = 128; o; o >>= 1) { if (tid < o) sh[tid] += sh[tid + o]; __syncthreads(); }
    float tot = sh[0]; __syncthreads();
    sh[tid] = q; __syncthreads();
    for (int o = 128; o; o >>= 1) { if (tid < o) sh[tid] += sh[tid + o]; __syncthreads(); }
    float totq = sh[0]; __syncthreads();
    float mean = tot * (1.f / KVd);
    float inv  = rsqrtf(totq * (1.f / KVd) - mean * mean + 1e-6f);
#pragma unroll
    for (int j = 0; j < 7; ++j) {
        int i = tid + j * 256;
        float y = (v[j] - mean) * inv * ag[i] + ab[i];
        __nv_bfloat16 h, l; splt(y, h, l);
        Yh[row * KVd + i] = h; Yl[row * KVd + i] = l;
    }
    float u0 = p2[tid], u1 = p2[tid + 256];
    s = u0 + u1; q = u0 * u0 + u1 * u1;
    sh[tid] = s; __syncthreads();
    for (int o = 128; o; o >>= 1) { if (tid < o) sh[tid] += sh[tid + o]; __syncthreads(); }
    tot = sh[0]; __syncthreads();
    sh[tid] = q; __syncthreads();
    for (int o = 128; o; o >>= 1) { if (tid < o) sh[tid] += sh[tid + o]; __syncthreads(); }
    totq = sh[0];
    mean = tot * (1.f / C2d);
    inv  = rsqrtf(totq * (1.f / C2d) - mean * mean + 1e-6f);
    {
        float y0 = (u0 - mean) * inv * g1[tid] + b1[tid];
        float y1 = (u1 - mean) * inv * g1[tid + 256] + b1[tid + 256];
        __nv_bfloat16 h, l;
        splt(y0, h, l); Xh[row * C2d + tid] = h;       Xl[row * C2d + tid] = l;
        splt(y1, h, l); Xh[row * C2d + tid + 256] = h; Xl[row * C2d + tid + 256] = l;
    }
}

__global__ void ln2_kernel(const float* __restrict__ in,
                           const float* __restrict__ g, const float* __restrict__ b,
                           __nv_bfloat16* __restrict__ Zh, __nv_bfloat16* __restrict__ Zl)
{
    const long row = blockIdx.x;
    const int  tid = threadIdx.x;
    const float* p = in + row * C2d;
    __shared__ float sh[256];
    float u0 = p[tid], u1 = p[tid + 256];
    float s = u0 + u1, q = u0 * u0 + u1 * u1;
    sh[tid] = s; __syncthreads();
    for (int o = 128; o; o >>= 1) { if (tid < o) sh[tid] += sh[tid + o]; __syncthreads(); }
    float tot = sh[0]; __syncthreads();
    sh[tid] = q; __syncthreads();
    for (int o = 128; o; o >>= 1) { if (tid < o) sh[tid] += sh[tid + o]; __syncthreads(); }
    float totq = sh[0];
    float mean = tot * (1.f / C2d);
    float inv  = rsqrtf(totq * (1.f / C2d) - mean * mean + 1e-6f);
    __nv_bfloat16 h, l;
    splt((u0 - mean) * inv * g[tid] + b[tid], h, l);
    Zh[row * C2d + tid] = h; Zl[row * C2d + tid] = l;
    splt((u1 - mean) * inv * g[tid + 256] + b[tid + 256], h, l);
    Zh[row * C2d + tid + 256] = h; Zl[row * C2d + tid + 256] = l;
}

__global__ void stats_kernel(const float* __restrict__ S, float* __restrict__ scale)
{
    const int z = blockIdx.x, tid = threadIdx.x;
    const float4* p = (const float4*)(S + (long)z * C2d * KVd);
    const int n4 = C2d * KVd / 4;
    float s = 0.f, q = 0.f;
    for (int i = tid; i < n4; i += 1024) {
        float4 v = p[i];
        s += v.x + v.y + v.z + v.w;
        q += v.x * v.x + v.y * v.y + v.z * v.z + v.w * v.w;
    }
    __shared__ float sh[1024];
    sh[tid] = s; __syncthreads();
    for (int o = 512; o; o >>= 1) { if (tid < o) sh[tid] += sh[tid + o]; __syncthreads(); }
    float tot = sh[0]; __syncthreads();
    sh[tid] = q; __syncthreads();
    for (int o = 512; o; o >>= 1) { if (tid < o) sh[tid] += sh[tid + o]; __syncthreads(); }
    float totq = sh[0];
    if (tid == 0) {
        const float cnt = (float)(C2d * KVd);
        float mean = tot / cnt;
        float var  = totq / cnt - mean * mean;
        float a    = rsqrtf((float)KVd);
        scale[z]   = a * rsqrtf(a * a * var + 1e-5f);
    }
}

__global__ void softmax_kernel(const float* __restrict__ S, const float* __restrict__ scale,
                               __nv_bfloat16* __restrict__ Ph, __nv_bfloat16* __restrict__ Pl)
{
    const long row = blockIdx.x;
    const int  tid = threadIdx.x;
    const float* p = S + row * KVd;
    const float sc = scale[blockIdx.x >> 9];
    __shared__ float sh[256];
    float v[7], mx = -1e30f;
#pragma unroll
    for (int j = 0; j < 7; ++j) { v[j] = p[tid + j * 256]; mx = fmaxf(mx, v[j]); }
    sh[tid] = mx; __syncthreads();
    for (int o = 128; o; o >>= 1) { if (tid < o) sh[tid] = fmaxf(sh[tid], sh[tid + o]); __syncthreads(); }
    mx = sh[0]; __syncthreads();
    float s = 0.f;
#pragma unroll
    for (int j = 0; j < 7; ++j) { v[j] = __expf((v[j] - mx) * sc); s += v[j]; }
    sh[tid] = s; __syncthreads();
    for (int o = 128; o; o >>= 1) { if (tid < o) sh[tid] += sh[tid + o]; __syncthreads(); }
    const float inv = 1.f / sh[0];
#pragma unroll
    for (int j = 0; j < 7; ++j) {
        __nv_bfloat16 h, l; splt(v[j] * inv, h, l);
        Ph[row * KVd + tid + j * 256] = h;
        Pl[row * KVd + tid + j * 256] = l;
    }
}

// ===================== launcher =============================================
#define SYM(v, t, s) t* v; { void* _p; cudaGetSymbolAddress(&_p, s); v = (t*)_p; }

extern "C" void kernel_launch(void* const* d_in, const int* in_sizes, int n_in,
                              void* d_out, int out_size)
{
    const float* emb1    = (const float*)d_in[0];
    const float* emb2    = (const float*)d_in[1];
    const float* emb3    = (const float*)d_in[2];
    const float* Wq      = (const float*)d_in[3];
    const float* Wk      = (const float*)d_in[4];
    const float* Wv      = (const float*)d_in[5];
    const float* Wout    = (const float*)d_in[6];
    const float* ln1_g   = (const float*)d_in[7];
    const float* ln1_b   = (const float*)d_in[8];
    const float* lnall_g = (const float*)d_in[9];
    const float* lnall_b = (const float*)d_in[10];
    const float* lnffn_g = (const float*)d_in[11];
    const float* lnffn_b = (const float*)d_in[12];
    const float* fc1_w   = (const float*)d_in[13];
    const float* fc1_b   = (const float*)d_in[14];
    const float* fc2_w   = (const float*)d_in[15];
    const float* fc2_b   = (const float*)d_in[16];
    float* out = (float*)d_out;

    SYM(Yh, __nv_bfloat16, g_Yh)   SYM(Yl, __nv_bfloat16, g_Yl)
    SYM(Yth, __nv_bfloat16, g_Yth) SYM(Ytl, __nv_bfloat16, g_Ytl)
    SYM(Xh, __nv_bfloat16, g_Xh)   SYM(Xl, __nv_bfloat16, g_Xl)
    SYM(Xth, __nv_bfloat16, g_Xth) SYM(Xtl, __nv_bfloat16, g_Xtl)
    SYM(Gth, __nv_bfloat16, g_Gth) SYM(Gtl, __nv_bfloat16, g_Gtl)
    SYM(T1h, __nv_bfloat16, g_T1h) SYM(T1l, __nv_bfloat16, g_T1l)
    SYM(S, float, g_S)
    SYM(Ph, __nv_bfloat16, g_Ph)   SYM(Pl, __nv_bfloat16, g_Pl)
    SYM(Mth, __nv_bfloat16, g_Mth) SYM(Mtl, __nv_bfloat16, g_Mtl)
    SYM(Ch, __nv_bfloat16, g_Ch)   SYM(Cl, __nv_bfloat16, g_Cl)
    SYM(cx2, float, g_cx2)
    SYM(Zh, __nv_bfloat16, g_Zh)   SYM(Zl, __nv_bfloat16, g_Zl)
    SYM(Fh, __nv_bfloat16, g_Fh)   SYM(Fl, __nv_bfloat16, g_Fl)
    SYM(WqTh, __nv_bfloat16, g_WqTh) SYM(WqTl, __nv_bfloat16, g_WqTl)
    SYM(WkTh, __nv_bfloat16, g_WkTh) SYM(WkTl, __nv_bfloat16, g_WkTl)
    SYM(Wvh, __nv_bfloat16, g_Wvh)   SYM(Wvl, __nv_bfloat16, g_Wvl)
    SYM(WoTh, __nv_bfloat16, g_WoTh) SYM(WoTl, __nv_bfloat16, g_WoTl)
    SYM(f1Th, __nv_bfloat16, g_f1Th) SYM(f1Tl, __nv_bfloat16, g_f1Tl)
    SYM(f2Th, __nv_bfloat16, g_f2Th) SYM(f2Tl, __nv_bfloat16, g_f2Tl)
    SYM(scl, float, g_sc)

    cudaFuncSetAttribute(mma_gemm<0, 0>, cudaFuncAttributeMaxDynamicSharedMemorySize, SMEMSZ);
    cudaFuncSetAttribute(mma_gemm<0, 1>, cudaFuncAttributeMaxDynamicSharedMemorySize, SMEMSZ);
    cudaFuncSetAttribute(mma_gemm<1, 0>, cudaFuncAttributeMaxDynamicSharedMemorySize, SMEMSZ);
    cudaFuncSetAttribute(mma_gemm<2, 1>, cudaFuncAttributeMaxDynamicSharedMemorySize, SMEMSZ);
    cudaFuncSetAttribute(mma_gemm<3, 0>, cudaFuncAttributeMaxDynamicSharedMemorySize, SMEMSZ);

    const dim3 t32(32, 8);
    // weight prep: transpose+split / split
    tsplit_k<<<dim3(C2d / 32, C2d / 32, NHd), t32>>>(Wq, WqTh, WqTl, C2d, C2d);
    tsplit_k<<<dim3(KVd / 32, KVd / 32, NHd), t32>>>(Wk, WkTh, WkTl, KVd, KVd);
    tsplit_k<<<dim3(C2d / 32, C2d / 32, 1), t32>>>(Wout, WoTh, WoTl, C2d, C2d);
    tsplit_k<<<dim3(C2E / 32, C2d / 32, 1), t32>>>(fc1_w, f1Th, f1Tl, C2d, C2E);
    tsplit_k<<<dim3(C2d / 32, C2E / 32, 1), t32>>>(fc2_w, f2Th, f2Tl, C2E, C2d);
    psplit_k<<<4096, 256>>>(Wv, Wvh, Wvl, (long)NHd * KVd * KVd / 4);

    // 1. input LayerNorms (split outputs)
    ln_in_kernel<<<BB * NT, 256>>>(emb1, emb2, emb3, lnall_g, lnall_b, ln1_g, ln1_b,
                                   Yh, Yl, Xh, Xl);
    // transposes for step 2
    tb16_k<<<dim3(KVd / 32, NT / 32, BB), t32>>>(Yh, Yth, NT, KVd);
    tb16_k<<<dim3(KVd / 32, NT / 32, BB), t32>>>(Yl, Ytl, NT, KVd);
    tb16_k<<<dim3(C2d / 32, NT / 32, BB), t32>>>(Xh, Xth, NT, C2d);
    tb16_k<<<dim3(C2d / 32, NT / 32, BB), t32>>>(Xl, Xtl, NT, C2d);

    // 2. Gt_b = Yt_b Xt_b^T  [1792,512], K=1024
    mma_gemm<0, 1><<<dim3(C2d / 128, KVd / 128, BB), 256, SMEMSZ>>>(
        Yth, Ytl, Xth, Xtl, nullptr, Gth, Gtl, nullptr, nullptr,
        KVd, C2d, NT, NT, NT,
        (long)KVd * NT, (long)C2d * NT, (long)KVd * C2d, 0, 0, 1, 0, 0, 1.f);

    // 3. T1[b,h] = WqT_h Gt_b^T  [512,1792], K=512
    mma_gemm<0, 1><<<dim3(KVd / 128, C2d / 128, BB * NHd), 256, SMEMSZ>>>(
        WqTh, WqTl, Gth, Gtl, nullptr, T1h, T1l, nullptr, nullptr,
        C2d, KVd, C2d, C2d, C2d,
        (long)C2d * C2d, (long)KVd * C2d, (long)C2d * KVd, 1, 2, 1, 0, 0, 1.f);

    // 4. S[b,h] = T1 WkT_h^T  [512,1792], K=1792 (fp32 out)
    mma_gemm<0, 0><<<dim3(KVd / 128, C2d / 128, BB * NHd), 256, SMEMSZ>>>(
        T1h, T1l, WkTh, WkTl, S, nullptr, nullptr, nullptr, nullptr,
        C2d, KVd, KVd, KVd, KVd,
        (long)C2d * KVd, (long)KVd * KVd, (long)C2d * KVd, 0, 1, 1, 0, 0, 1.f);

    // 5-6. instance-norm stats + row softmax (writes split probs)
    stats_kernel<<<BB * NHd, 1024>>>(S, scl);
    softmax_kernel<<<BB * NHd * C2d, 256>>>(S, scl, Ph, Pl);

    // 7. Mmt_b[c,e] = (1/H) sum_h sum_k P[b,h,c,k] Wv_h[e,k]  [512,1792]
    mma_gemm<0, 1><<<dim3(KVd / 128, C2d / 128, BB), 256, SMEMSZ>>>(
        Ph, Pl, Wvh, Wvl, nullptr, Mth, Mtl, nullptr, nullptr,
        C2d, KVd, KVd, KVd, KVd,
        (long)NHd * C2d * KVd, 0, (long)C2d * KVd, 0, 0,
        NHd, (long)C2d * KVd, (long)KVd * KVd, 1.f / NHd);

    // 8. ctx_b = Y_b Mmt_b^T  [1024,512], K=1792
    mma_gemm<0, 1><<<dim3(C2d / 128, NT / 128, BB), 256, SMEMSZ>>>(
        Yh, Yl, Mth, Mtl, nullptr, Ch, Cl, nullptr, nullptr,
        NT, C2d, KVd, KVd, KVd,
        (long)NT * KVd, (long)C2d * KVd, (long)NT * C2d, 0, 0, 1, 0, 0, 1.f);

    // 9. cx2 = ctx WoutT^T + emb2  [8192,512]
    mma_gemm<1, 0><<<dim3(C2d / 128, BB * NT / 128, 1), 256, SMEMSZ>>>(
        Ch, Cl, WoTh, WoTl, cx2, nullptr, nullptr, nullptr, emb2,
        BB * NT, C2d, C2d, C2d, C2d, 0, 0, 0, 0, 0, 1, 0, 0, 1.f);

    // 10. Z = LN(cx2) (split out)
    ln2_kernel<<<BB * NT, 256>>>(cx2, lnffn_g, lnffn_b, Zh, Zl);

    // 11. F = gelu(Z f1T^T + b1)  [8192,2048]
    mma_gemm<2, 1><<<dim3(C2E / 128, BB * NT / 128, 1), 256, SMEMSZ>>>(
        Zh, Zl, f1Th, f1Tl, nullptr, Fh, Fl, fc1_b, nullptr,
        BB * NT, C2E, C2d, C2d, C2d, 0, 0, 0, 0, 0, 1, 0, 0, 1.f);

    // 12. out = F f2T^T + b2 + cx2  [8192,512]
    mma_gemm<3, 0><<<dim3(C2d / 128, BB * NT / 128, 1), 256, SMEMSZ>>>(
        Fh, Fl, f2Th, f2Tl, out, nullptr, nullptr, fc2_b, cx2,
        BB * NT, C2d, C2E, C2E, C2E, 0, 0, 0, 0, 0, 1, 0, 0, 1.f);
}

// round 9
// speedup vs baseline: 2.7990x; 1.2717x over previous
#include <cuda_runtime.h>
#include <cuda_fp16.h>
#include <math.h>
#include <stdint.h>

// Problem constants
#define BB   8
#define NT   1024
#define C1d  256
#define C2d  512
#define C3d  1024
#define KVd  1792
#define NHd  4
#define C2E  2048

// ===================== scratch (device statics) ==============================
__device__ __half g_Yh [BB*NT*KVd], g_Yl [BB*NT*KVd];     // LN(concat), [b][n][kv]
__device__ __half g_Yth[BB*NT*KVd], g_Ytl[BB*NT*KVd];     // transposed  [b][kv][n]
__device__ __half g_Xh [BB*NT*C2d], g_Xl [BB*NT*C2d];     // LN(emb2)    [b][n][c]
__device__ __half g_Xth[BB*NT*C2d], g_Xtl[BB*NT*C2d];     // transposed  [b][c][n]
__device__ __half g_Gth[BB*KVd*C2d], g_Gtl[BB*KVd*C2d];   // Gt = Yt Xt^T [b][kv][c]
__device__ __half g_T1h[BB*NHd*C2d*KVd], g_T1l[BB*NHd*C2d*KVd];
__device__ float  g_S  [BB*NHd*C2d*KVd];                  // scores fp32
__device__ __half g_Ph [BB*NHd*C2d*KVd], g_Pl [BB*NHd*C2d*KVd]; // probs
__device__ __half g_Mth[BB*C2d*KVd], g_Mtl[BB*C2d*KVd];   // Mmt [b][c][e]
__device__ __half g_Ch [BB*NT*C2d], g_Cl [BB*NT*C2d];     // ctx
__device__ float  g_cx2[BB*NT*C2d];                       // residual fp32
__device__ __half g_Zh [BB*NT*C2d], g_Zl [BB*NT*C2d];     // LN(cx2)
__device__ __half g_Fh [BB*NT*C2E], g_Fl [BB*NT*C2E];     // gelu(fc1)
// weights (pre-transposed + split)
__device__ __half g_WqTh[NHd*C2d*C2d], g_WqTl[NHd*C2d*C2d];
__device__ __half g_WkTh[NHd*KVd*KVd], g_WkTl[NHd*KVd*KVd];
__device__ __half g_Wvh [NHd*KVd*KVd], g_Wvl [NHd*KVd*KVd];
__device__ __half g_WoTh[C2d*C2d],     g_WoTl[C2d*C2d];
__device__ __half g_f1Th[C2E*C2d],     g_f1Tl[C2E*C2d];
__device__ __half g_f2Th[C2d*C2E],     g_f2Tl[C2d*C2E];
__device__ float g_sc[BB*NHd];

// ===================== PTX helpers (baseline sm_80+ only) ====================
__device__ __forceinline__ uint32_t smem_u32(const void* p) {
    uint32_t a;
    asm("{ .reg .u64 t; cvta.to.shared.u64 t, %1; cvt.u32.u64 %0, t; }" : "=r"(a) : "l"(p));
    return a;
}
#define CPA16(d, s)   asm volatile("cp.async.cg.shared.global [%0], [%1], 16;" :: "r"(d), "l"(s))
#define CPA_COMMIT()  asm volatile("cp.async.commit_group;" ::: "memory")
#define CPA_WAIT1()   asm volatile("cp.async.wait_group 1;" ::: "memory")
#define CPA_WAIT0()   asm volatile("cp.async.wait_group 0;" ::: "memory")

#define LDSM4(r, a) \
    asm volatile("ldmatrix.sync.aligned.m8n8.x4.shared.b16 {%0,%1,%2,%3}, [%4];" \
        : "=r"((r)[0]), "=r"((r)[1]), "=r"((r)[2]), "=r"((r)[3]) : "r"(a))

#define MMA16816(C, A, B0, B1) \
    asm volatile("mma.sync.aligned.m16n8k16.row.col.f32.f16.f16.f32 " \
        "{%0,%1,%2,%3}, {%4,%5,%6,%7}, {%8,%9}, {%0,%1,%2,%3};" \
        : "+f"((C)[0]), "+f"((C)[1]), "+f"((C)[2]), "+f"((C)[3]) \
        : "r"((A)[0]), "r"((A)[1]), "r"((A)[2]), "r"((A)[3]), "r"(B0), "r"(B1))

__device__ __forceinline__ void splt(float v, __half& h, __half& l) {
    h = __float2half_rn(v);
    l = __float2half_rn(v - __half2float(h));
}
__device__ __forceinline__ int selidx(int mode, int z) {
    return mode == 0 ? z : (mode == 1 ? (z & 3) : (z >> 2));
}

// ===================== mma.sync split-fp16 GEMM ==============================
// C[M,Nn] = outScale * sum_h A_h[M,K] * B_h[N,K]^T  (+ epilogue)
// PASSES: 2 -> Ah*Bh + Al*Bh (B fp16-rounded);  3 -> + Ah*Bl (B split too)
// EPI: 0 none, 1 +add, 2 +bias,gelu, 3 +bias+add.  OUT: 0 fp32, 1 fp16 hi/lo
// BK=64; smem row stride 144 B (conflict-free for ldmatrix: 144 mod 128 = 16
// cycles all eight 16B banks across an 8-row group).
#define PADB   144                  // bytes per smem row
#define TILEB  (128 * PADB)         // 18432 B per tile
#define SMSZ_P(P) (2 * ((P) + 1) * TILEB)

template<int PASSES, int EPI, int OUT>
__global__ __launch_bounds__(256)
void mma_gemm(const __half* __restrict__ Ahi, const __half* __restrict__ Alo,
              const __half* __restrict__ Bhi, const __half* __restrict__ Blo,
              float* __restrict__ C, __half* __restrict__ Chi, __half* __restrict__ Clo,
              const float* __restrict__ bias, const float* __restrict__ addp,
              int M, int Nn, int K, int lda, int ldb,
              long sA, long sB, long sC, int selA, int selB,
              int nH, long hA, long hB, float outScale)
{
    constexpr int NTL    = (PASSES == 3) ? 4 : 3;       // Ah, Al, Bh[, Bl]
    constexpr uint32_t STB = NTL * TILEB;               // stage bytes

    extern __shared__ char smem[];
    const uint32_t sb = smem_u32(smem);
    const int tid = threadIdx.x, wid = tid >> 5, lane = tid & 31;
    const int z = blockIdx.z;
    const int m0 = blockIdx.y * 128, n0 = blockIdx.x * 128;
    const int warpM = (wid & 3) * 32, warpN = (wid >> 2) * 64;

    const __half* A0h = Ahi + (long)selidx(selA, z) * sA;
    const __half* A0l = Alo + (long)selidx(selA, z) * sA;
    const __half* B0h = Bhi + (long)selidx(selB, z) * sB;
    const __half* B0l = (PASSES == 3) ? (Blo + (long)selidx(selB, z) * sB) : nullptr;

    const int nchK = K >> 6;        // chunks of 64
    const int nch  = nH * nchK;

    const int srow = tid >> 3;      // 0..31  (base row for staging)
    const int sseg = tid & 7;       // 16B segment

    // stage a 64-k chunk of all operand tiles (one commit group)
    auto issue = [&](int ch) {
        const uint32_t so = sb + (uint32_t)(ch & 1) * STB;
        const int h  = ch / nchK;
        const int k0 = (ch - h * nchK) << 6;
        const __half* srcs[4] = { A0h + (long)h * hA, A0l + (long)h * hA,
                                  B0h + (long)h * hB,
                                  (PASSES == 3) ? (B0l + (long)h * hB) : nullptr };
#pragma unroll
        for (int t4 = 0; t4 < NTL; ++t4) {
            const int ld = (t4 < 2) ? lda : ldb;
            const int rb = (t4 < 2) ? m0  : n0;
            const __half* gb = srcs[t4] + (long)(rb + srow) * ld + k0 + sseg * 8;
            const uint32_t tb = so + t4 * TILEB + srow * PADB + sseg * 16;
#pragma unroll
            for (int j = 0; j < 4; ++j)
                CPA16(tb + j * 32 * PADB, gb + (long)(j * 32) * ld);
        }
        CPA_COMMIT();
    };

    float acc[2][8][4];
#pragma unroll
    for (int i = 0; i < 2; ++i)
#pragma unroll
        for (int j = 0; j < 8; ++j)
#pragma unroll
            for (int k = 0; k < 4; ++k) acc[i][j][k] = 0.f;

    issue(0);
    issue(1);

    // ldmatrix lane address components (byte offsets within a tile)
    const uint32_t aRow = (uint32_t)(warpM + (lane & 15)) * PADB + ((lane >> 4) << 4);
    const uint32_t bRow = (uint32_t)(warpN + ((lane >> 4) << 3) + (lane & 7)) * PADB
                        + (((lane >> 3) & 1) << 4);

    for (int ch = 0; ch < nch; ++ch) {
        if (ch < nch - 1) { CPA_WAIT1(); } else { CPA_WAIT0(); }
        __syncthreads();
        const uint32_t so = sb + (uint32_t)(ch & 1) * STB;
#pragma unroll
        for (int ks = 0; ks < 4; ++ks) {
            const uint32_t kb = ks * 32;
            uint32_t ah[2][4], al[2][4], bh[4][4], bl[4][4];
#pragma unroll
            for (int mf = 0; mf < 2; ++mf) {
                const uint32_t ad = so + aRow + (uint32_t)(mf * 16 * PADB) + kb;
                LDSM4(ah[mf], ad);
                LDSM4(al[mf], ad + TILEB);
            }
#pragma unroll
            for (int q = 0; q < 4; ++q) {
                const uint32_t bd = so + 2 * TILEB + bRow + (uint32_t)(q * 16 * PADB) + kb;
                LDSM4(bh[q], bd);
                if (PASSES == 3) LDSM4(bl[q], bd + TILEB);
            }
#pragma unroll
            for (int mf = 0; mf < 2; ++mf)
#pragma unroll
                for (int nf = 0; nf < 8; ++nf) {
                    const uint32_t bh0 = bh[nf >> 1][(nf & 1) * 2];
                    const uint32_t bh1 = bh[nf >> 1][(nf & 1) * 2 + 1];
                    MMA16816(acc[mf][nf], ah[mf], bh0, bh1);
                    MMA16816(acc[mf][nf], al[mf], bh0, bh1);
                    if (PASSES == 3)
                        MMA16816(acc[mf][nf], ah[mf],
                                 bl[nf >> 1][(nf & 1) * 2], bl[nf >> 1][(nf & 1) * 2 + 1]);
                }
        }
        __syncthreads();
        if (ch + 2 < nch) issue(ch + 2);
    }

    // ---- epilogue (register accumulators -> gmem)
    const int rbase = m0 + warpM + (lane >> 2);
    const int cbase = n0 + warpN + (lane & 3) * 2;
#pragma unroll
    for (int mf = 0; mf < 2; ++mf) {
#pragma unroll
        for (int h2 = 0; h2 < 2; ++h2) {
            const long m = rbase + mf * 16 + h2 * 8;
#pragma unroll
            for (int nf = 0; nf < 8; ++nf) {
                const long col = cbase + nf * 8;
                float v0 = acc[mf][nf][h2 * 2]     * outScale;
                float v1 = acc[mf][nf][h2 * 2 + 1] * outScale;
                if (EPI == 1) {
                    const float2 ad = *(const float2*)(addp + m * Nn + col);
                    v0 += ad.x; v1 += ad.y;
                }
                if (EPI == 2) {
                    v0 += bias[col]; v1 += bias[col + 1];
                    v0 = 0.5f * v0 * (1.f + erff(v0 * 0.70710678118654752f));
                    v1 = 0.5f * v1 * (1.f + erff(v1 * 0.70710678118654752f));
                }
                if (EPI == 3) {
                    const float2 ad = *(const float2*)(addp + m * Nn + col);
                    v0 += bias[col]     + ad.x;
                    v1 += bias[col + 1] + ad.y;
                }
                const long idx = (long)z * sC + m * Nn + col;
                if (OUT == 0) {
                    *(float2*)(C + idx) = make_float2(v0, v1);
                } else {
                    __half h0, l0, h1, l1;
                    splt(v0, h0, l0); splt(v1, h1, l1);
                    *(__half2*)(Chi + idx) = __halves2half2(h0, h1);
                    *(__half2*)(Clo + idx) = __halves2half2(l0, l1);
                }
            }
        }
    }
}

// ===================== prep kernels =========================================
// fp32 [Z][R][C] -> hi/lo fp16 [Z][C][R]
__global__ void tsplit_k(const float* __restrict__ in, __half* __restrict__ oh,
                         __half* __restrict__ ol, int R, int Cc)
{
    __shared__ float t[32][33];
    const long zo = (long)blockIdx.z * R * Cc;
    const int c0 = blockIdx.x * 32, r0 = blockIdx.y * 32;
    const int x = threadIdx.x, y = threadIdx.y;
#pragma unroll
    for (int j = 0; j < 32; j += 8) t[y + j][x] = in[zo + (long)(r0 + y + j) * Cc + c0 + x];
    __syncthreads();
#pragma unroll
    for (int j = 0; j < 32; j += 8) {
        float v = t[x][y + j];
        __half h, l; splt(v, h, l);
        const long o = zo + (long)(c0 + y + j) * R + r0 + x;
        oh[o] = h; ol[o] = l;
    }
}

// fp32 -> hi/lo fp16 (same layout)
__global__ void psplit_k(const float* __restrict__ in, __half* __restrict__ oh,
                         __half* __restrict__ ol, long n4)
{
    for (long i = blockIdx.x * blockDim.x + threadIdx.x; i < n4; i += (long)gridDim.x * blockDim.x) {
        float4 v = ((const float4*)in)[i];
        __half hh[4], ll[4];
        splt(v.x, hh[0], ll[0]); splt(v.y, hh[1], ll[1]);
        splt(v.z, hh[2], ll[2]); splt(v.w, hh[3], ll[3]);
        ((uint2*)oh)[i] = *(uint2*)hh;
        ((uint2*)ol)[i] = *(uint2*)ll;
    }
}

// fp16 [Z][R][C] -> [Z][C][R]
__global__ void tb16_k(const __half* __restrict__ in, __half* __restrict__ out,
                       int R, int Cc)
{
    __shared__ __half t[32][33];
    const long zo = (long)blockIdx.z * R * Cc;
    const int c0 = blockIdx.x * 32, r0 = blockIdx.y * 32;
    const int x = threadIdx.x, y = threadIdx.y;
#pragma unroll
    for (int j = 0; j < 32; j += 8) t[y + j][x] = in[zo + (long)(r0 + y + j) * Cc + c0 + x];
    __syncthreads();
#pragma unroll
    for (int j = 0; j < 32; j += 8) out[zo + (long)(c0 + y + j) * R + r0 + x] = t[x][y + j];
}

// input LayerNorms -> split outputs
__global__ void ln_in_kernel(const float* __restrict__ e1, const float* __restrict__ e2,
                             const float* __restrict__ e3,
                             const float* __restrict__ ag, const float* __restrict__ ab,
                             const float* __restrict__ g1, const float* __restrict__ b1,
                             __half* __restrict__ Yh, __half* __restrict__ Yl,
                             __half* __restrict__ Xh, __half* __restrict__ Xl)
{
    const long row = blockIdx.x;
    const int  tid = threadIdx.x;
    const float* p1 = e1 + row * C1d;
    const float* p2 = e2 + row * C2d;
    const float* p3 = e3 + row * C3d;
    __shared__ float sh[256];

    float v[7], s = 0.f, q = 0.f;
#pragma unroll
    for (int j = 0; j < 7; ++j) {
        int i = tid + j * 256;
        float x;
        if (j == 0)      x = p1[i];
        else if (j <= 2) x = p2[i - C1d];
        else             x = p3[i - (C1d + C2d)];
        v[j] = x; s += x; q += x * x;
    }
    sh[tid] = s; __syncthreads();
    for (int o = 128; o; o >>= 1) { if (tid < o) sh[tid] += sh[tid + o]; __syncthreads(); }
    float tot = sh[0]; __syncthreads();
    sh[tid] = q; __syncthreads();
    for (int o = 128; o; o >>= 1) { if (tid < o) sh[tid] += sh[tid + o]; __syncthreads(); }
    float totq = sh[0]; __syncthreads();
    float mean = tot * (1.f / KVd);
    float inv  = rsqrtf(totq * (1.f / KVd) - mean * mean + 1e-6f);
#pragma unroll
    for (int j = 0; j < 7; ++j) {
        int i = tid + j * 256;
        float y = (v[j] - mean) * inv * ag[i] + ab[i];
        __half h, l; splt(y, h, l);
        Yh[row * KVd + i] = h; Yl[row * KVd + i] = l;
    }
    float u0 = p2[tid], u1 = p2[tid + 256];
    s = u0 + u1; q = u0 * u0 + u1 * u1;
    sh[tid] = s; __syncthreads();
    for (int o = 128; o; o >>= 1) { if (tid < o) sh[tid] += sh[tid + o]; __syncthreads(); }
    tot = sh[0]; __syncthreads();
    sh[tid] = q; __syncthreads();
    for (int o = 128; o; o >>= 1) { if (tid < o) sh[tid] += sh[tid + o]; __syncthreads(); }
    totq = sh[0];
    mean = tot * (1.f / C2d);
    inv  = rsqrtf(totq * (1.f / C2d) - mean * mean + 1e-6f);
    {
        float y0 = (u0 - mean) * inv * g1[tid] + b1[tid];
        float y1 = (u1 - mean) * inv * g1[tid + 256] + b1[tid + 256];
        __half h, l;
        splt(y0, h, l); Xh[row * C2d + tid] = h;       Xl[row * C2d + tid] = l;
        splt(y1, h, l); Xh[row * C2d + tid + 256] = h; Xl[row * C2d + tid + 256] = l;
    }
}

__global__ void ln2_kernel(const float* __restrict__ in,
                           const float* __restrict__ g, const float* __restrict__ b,
                           __half* __restrict__ Zh, __half* __restrict__ Zl)
{
    const long row = blockIdx.x;
    const int  tid = threadIdx.x;
    const float* p = in + row * C2d;
    __shared__ float sh[256];
    float u0 = p[tid], u1 = p[tid + 256];
    float s = u0 + u1, q = u0 * u0 + u1 * u1;
    sh[tid] = s; __syncthreads();
    for (int o = 128; o; o >>= 1) { if (tid < o) sh[tid] += sh[tid + o]; __syncthreads(); }
    float tot = sh[0]; __syncthreads();
    sh[tid] = q; __syncthreads();
    for (int o = 128; o; o >>= 1) { if (tid < o) sh[tid] += sh[tid + o]; __syncthreads(); }
    float totq = sh[0];
    float mean = tot * (1.f / C2d);
    float inv  = rsqrtf(totq * (1.f / C2d) - mean * mean + 1e-6f);
    __half h, l;
    splt((u0 - mean) * inv * g[tid] + b[tid], h, l);
    Zh[row * C2d + tid] = h; Zl[row * C2d + tid] = l;
    splt((u1 - mean) * inv * g[tid + 256] + b[tid + 256], h, l);
    Zh[row * C2d + tid + 256] = h; Zl[row * C2d + tid + 256] = l;
}

__global__ void stats_kernel(const float* __restrict__ S, float* __restrict__ scale)
{
    const int z = blockIdx.x, tid = threadIdx.x;
    const float4* p = (const float4*)(S + (long)z * C2d * KVd);
    const int n4 = C2d * KVd / 4;
    float s = 0.f, q = 0.f;
    for (int i = tid; i < n4; i += 1024) {
        float4 v = p[i];
        s += v.x + v.y + v.z + v.w;
        q += v.x * v.x + v.y * v.y + v.z * v.z + v.w * v.w;
    }
    __shared__ float sh[1024];
    sh[tid] = s; __syncthreads();
    for (int o = 512; o; o >>= 1) { if (tid < o) sh[tid] += sh[tid + o]; __syncthreads(); }
    float tot = sh[0]; __syncthreads();
    sh[tid] = q; __syncthreads();
    for (int o = 512; o; o >>= 1) { if (tid < o) sh[tid] += sh[tid + o]; __syncthreads(); }
    float totq = sh[0];
    if (tid == 0) {
        const float cnt = (float)(C2d * KVd);
        float mean = tot / cnt;
        float var  = totq / cnt - mean * mean;
        float a    = rsqrtf((float)KVd);
        scale[z]   = a * rsqrtf(a * a * var + 1e-5f);
    }
}

__global__ void softmax_kernel(const float* __restrict__ S, const float* __restrict__ scale,
                               __half* __restrict__ Ph, __half* __restrict__ Pl)
{
    const long row = blockIdx.x;
    const int  tid = threadIdx.x;
    const float* p = S + row * KVd;
    const float sc = scale[blockIdx.x >> 9];
    __shared__ float sh[256];
    float v[7], mx = -1e30f;
#pragma unroll
    for (int j = 0; j < 7; ++j) { v[j] = p[tid + j * 256]; mx = fmaxf(mx, v[j]); }
    sh[tid] = mx; __syncthreads();
    for (int o = 128; o; o >>= 1) { if (tid < o) sh[tid] = fmaxf(sh[tid], sh[tid + o]); __syncthreads(); }
    mx = sh[0]; __syncthreads();
    float s = 0.f;
#pragma unroll
    for (int j = 0; j < 7; ++j) { v[j] = __expf((v[j] - mx) * sc); s += v[j]; }
    sh[tid] = s; __syncthreads();
    for (int o = 128; o; o >>= 1) { if (tid < o) sh[tid] += sh[tid + o]; __syncthreads(); }
    const float inv = 1.f / sh[0];
#pragma unroll
    for (int j = 0; j < 7; ++j) {
        __half h, l; splt(v[j] * inv, h, l);
        Ph[row * KVd + tid + j * 256] = h;
        Pl[row * KVd + tid + j * 256] = l;
    }
}

// ===================== launcher =============================================
#define SYM(v, t, s) t* v; { void* _p; cudaGetSymbolAddress(&_p, s); v = (t*)_p; }

extern "C" void kernel_launch(void* const* d_in, const int* in_sizes, int n_in,
                              void* d_out, int out_size)
{
    const float* emb1    = (const float*)d_in[0];
    const float* emb2    = (const float*)d_in[1];
    const float* emb3    = (const float*)d_in[2];
    const float* Wq      = (const float*)d_in[3];
    const float* Wk      = (const float*)d_in[4];
    const float* Wv      = (const float*)d_in[5];
    const float* Wout    = (const float*)d_in[6];
    const float* ln1_g   = (const float*)d_in[7];
    const float* ln1_b   = (const float*)d_in[8];
    const float* lnall_g = (const float*)d_in[9];
    const float* lnall_b = (const float*)d_in[10];
    const float* lnffn_g = (const float*)d_in[11];
    const float* lnffn_b = (const float*)d_in[12];
    const float* fc1_w   = (const float*)d_in[13];
    const float* fc1_b   = (const float*)d_in[14];
    const float* fc2_w   = (const float*)d_in[15];
    const float* fc2_b   = (const float*)d_in[16];
    float* out = (float*)d_out;

    SYM(Yh, __half, g_Yh)   SYM(Yl, __half, g_Yl)
    SYM(Yth, __half, g_Yth) SYM(Ytl, __half, g_Ytl)
    SYM(Xh, __half, g_Xh)   SYM(Xl, __half, g_Xl)
    SYM(Xth, __half, g_Xth) SYM(Xtl, __half, g_Xtl)
    SYM(Gth, __half, g_Gth) SYM(Gtl, __half, g_Gtl)
    SYM(T1h, __half, g_T1h) SYM(T1l, __half, g_T1l)
    SYM(S, float, g_S)
    SYM(Ph, __half, g_Ph)   SYM(Pl, __half, g_Pl)
    SYM(Mth, __half, g_Mth) SYM(Mtl, __half, g_Mtl)
    SYM(Ch, __half, g_Ch)   SYM(Cl, __half, g_Cl)
    SYM(cx2, float, g_cx2)
    SYM(Zh, __half, g_Zh)   SYM(Zl, __half, g_Zl)
    SYM(Fh, __half, g_Fh)   SYM(Fl, __half, g_Fl)
    SYM(WqTh, __half, g_WqTh) SYM(WqTl, __half, g_WqTl)
    SYM(WkTh, __half, g_WkTh) SYM(WkTl, __half, g_WkTl)
    SYM(Wvh, __half, g_Wvh)   SYM(Wvl, __half, g_Wvl)
    SYM(WoTh, __half, g_WoTh) SYM(WoTl, __half, g_WoTl)
    SYM(f1Th, __half, g_f1Th) SYM(f1Tl, __half, g_f1Tl)
    SYM(f2Th, __half, g_f2Th) SYM(f2Tl, __half, g_f2Tl)
    SYM(scl, float, g_sc)

    const int SM2 = SMSZ_P(2);   // 110592 B for 2-pass
    const int SM3 = SMSZ_P(3);   // 147456 B for 3-pass
    cudaFuncSetAttribute(mma_gemm<2, 0, 0>, cudaFuncAttributeMaxDynamicSharedMemorySize, SM2);
    cudaFuncSetAttribute(mma_gemm<2, 0, 1>, cudaFuncAttributeMaxDynamicSharedMemorySize, SM2);
    cudaFuncSetAttribute(mma_gemm<3, 0, 1>, cudaFuncAttributeMaxDynamicSharedMemorySize, SM3);
    cudaFuncSetAttribute(mma_gemm<2, 1, 0>, cudaFuncAttributeMaxDynamicSharedMemorySize, SM2);
    cudaFuncSetAttribute(mma_gemm<2, 2, 1>, cudaFuncAttributeMaxDynamicSharedMemorySize, SM2);
    cudaFuncSetAttribute(mma_gemm<2, 3, 0>, cudaFuncAttributeMaxDynamicSharedMemorySize, SM2);

    const dim3 t32(32, 8);
    // weight prep: transpose+split / split
    tsplit_k<<<dim3(C2d / 32, C2d / 32, NHd), t32>>>(Wq, WqTh, WqTl, C2d, C2d);
    tsplit_k<<<dim3(KVd / 32, KVd / 32, NHd), t32>>>(Wk, WkTh, WkTl, KVd, KVd);
    tsplit_k<<<dim3(C2d / 32, C2d / 32, 1), t32>>>(Wout, WoTh, WoTl, C2d, C2d);
    tsplit_k<<<dim3(C2E / 32, C2d / 32, 1), t32>>>(fc1_w, f1Th, f1Tl, C2d, C2E);
    tsplit_k<<<dim3(C2d / 32, C2E / 32, 1), t32>>>(fc2_w, f2Th, f2Tl, C2E, C2d);
    psplit_k<<<4096, 256>>>(Wv, Wvh, Wvl, (long)NHd * KVd * KVd / 4);

    // 1. input LayerNorms (split outputs)
    ln_in_kernel<<<BB * NT, 256>>>(emb1, emb2, emb3, lnall_g, lnall_b, ln1_g, ln1_b,
                                   Yh, Yl, Xh, Xl);
    // transposes for step 2
    tb16_k<<<dim3(KVd / 32, NT / 32, BB), t32>>>(Yh, Yth, NT, KVd);
    tb16_k<<<dim3(KVd / 32, NT / 32, BB), t32>>>(Yl, Ytl, NT, KVd);
    tb16_k<<<dim3(C2d / 32, NT / 32, BB), t32>>>(Xh, Xth, NT, C2d);
    tb16_k<<<dim3(C2d / 32, NT / 32, BB), t32>>>(Xl, Xtl, NT, C2d);

    // 2. Gt_b = Yt_b Xt_b^T  [1792,512], K=1024
    mma_gemm<2, 0, 1><<<dim3(C2d / 128, KVd / 128, BB), 256, SM2>>>(
        Yth, Ytl, Xth, nullptr, nullptr, Gth, Gtl, nullptr, nullptr,
        KVd, C2d, NT, NT, NT,
        (long)KVd * NT, (long)C2d * NT, (long)KVd * C2d, 0, 0, 1, 0, 0, 1.f);

    // 3. T1[b,h] = WqT_h Gt_b^T  [512,1792], K=512  (3-pass: Gt has corr spikes)
    mma_gemm<3, 0, 1><<<dim3(KVd / 128, C2d / 128, BB * NHd), 256, SM3>>>(
        WqTh, WqTl, Gth, Gtl, nullptr, T1h, T1l, nullptr, nullptr,
        C2d, KVd, C2d, C2d, C2d,
        (long)C2d * C2d, (long)KVd * C2d, (long)C2d * KVd, 1, 2, 1, 0, 0, 1.f);

    // 4. S[b,h] = T1 WkT_h^T  [512,1792], K=1792 (fp32 out)
    mma_gemm<2, 0, 0><<<dim3(KVd / 128, C2d / 128, BB * NHd), 256, SM2>>>(
        T1h, T1l, WkTh, nullptr, S, nullptr, nullptr, nullptr, nullptr,
        C2d, KVd, KVd, KVd, KVd,
        (long)C2d * KVd, (long)KVd * KVd, (long)C2d * KVd, 0, 1, 1, 0, 0, 1.f);

    // 5-6. instance-norm stats + row softmax (writes split probs)
    stats_kernel<<<BB * NHd, 1024>>>(S, scl);
    softmax_kernel<<<BB * NHd * C2d, 256>>>(S, scl, Ph, Pl);

    // 7. Mmt_b[c,e] = (1/H) sum_h sum_k P[b,h,c,k] Wv_h[e,k]  [512,1792]
    mma_gemm<2, 0, 1><<<dim3(KVd / 128, C2d / 128, BB), 256, SM2>>>(
        Ph, Pl, Wvh, nullptr, nullptr, Mth, Mtl, nullptr, nullptr,
        C2d, KVd, KVd, KVd, KVd,
        (long)NHd * C2d * KVd, 0, (long)C2d * KVd, 0, 0,
        NHd, (long)C2d * KVd, (long)KVd * KVd, 1.f / NHd);

    // 8. ctx_b = Y_b Mmt_b^T  [1024,512], K=1792
    mma_gemm<2, 0, 1><<<dim3(C2d / 128, NT / 128, BB), 256, SM2>>>(
        Yh, Yl, Mth, nullptr, nullptr, Ch, Cl, nullptr, nullptr,
        NT, C2d, KVd, KVd, KVd,
        (long)NT * KVd, (long)C2d * KVd, (long)NT * C2d, 0, 0, 1, 0, 0, 1.f);

    // 9. cx2 = ctx WoutT^T + emb2  [8192,512]
    mma_gemm<2, 1, 0><<<dim3(C2d / 128, BB * NT / 128, 1), 256, SM2>>>(
        Ch, Cl, WoTh, nullptr, cx2, nullptr, nullptr, nullptr, emb2,
        BB * NT, C2d, C2d, C2d, C2d, 0, 0, 0, 0, 0, 1, 0, 0, 1.f);

    // 10. Z = LN(cx2) (split out)
    ln2_kernel<<<BB * NT, 256>>>(cx2, lnffn_g, lnffn_b, Zh, Zl);

    // 11. F = gelu(Z f1T^T + b1)  [8192,2048]
    mma_gemm<2, 2, 1><<<dim3(C2E / 128, BB * NT / 128, 1), 256, SM2>>>(
        Zh, Zl, f1Th, nullptr, nullptr, Fh, Fl, fc1_b, nullptr,
        BB * NT, C2E, C2d, C2d, C2d, 0, 0, 0, 0, 0, 1, 0, 0, 1.f);

    // 12. out = F f2T^T + b2 + cx2  [8192,512]
    mma_gemm<2, 3, 0><<<dim3(C2d / 128, BB * NT / 128, 1), 256, SM2>>>(
        Fh, Fl, f2Th, nullptr, out, nullptr, nullptr, fc2_b, cx2,
        BB * NT, C2d, C2E, C2E, C2E, 0, 0, 0, 0, 0, 1, 0, 0, 1.f);
}

// round 10
// speedup vs baseline: 3.0455x; 1.0881x over previous
#include <cuda_runtime.h>
#include <cuda_fp16.h>
#include <math.h>
#include <stdint.h>

// Problem constants
#define BB   8
#define NT   1024
#define C1d  256
#define C2d  512
#define C3d  1024
#define KVd  1792
#define NHd  4
#define C2E  2048

// ===================== scratch (device statics) ==============================
__device__ __half g_Yh [BB*NT*KVd], g_Yl [BB*NT*KVd];     // LN(concat), [b][n][kv]
__device__ __half g_Yth[BB*NT*KVd], g_Ytl[BB*NT*KVd];     // transposed  [b][kv][n]
__device__ __half g_Xh [BB*NT*C2d], g_Xl [BB*NT*C2d];     // LN(emb2)    [b][n][c]
__device__ __half g_Xth[BB*NT*C2d], g_Xtl[BB*NT*C2d];     // transposed  [b][c][n]
__device__ __half g_Gth[BB*KVd*C2d], g_Gtl[BB*KVd*C2d];   // Gt = Yt Xt^T [b][kv][c]
__device__ __half g_T1h[BB*NHd*C2d*KVd], g_T1l[BB*NHd*C2d*KVd];
__device__ float  g_S  [BB*NHd*C2d*KVd];                  // scores fp32
__device__ __half g_Ph [BB*NHd*C2d*KVd], g_Pl [BB*NHd*C2d*KVd]; // probs
__device__ __half g_Mth[BB*C2d*KVd], g_Mtl[BB*C2d*KVd];   // Mmt [b][c][e]
__device__ __half g_Ch [BB*NT*C2d], g_Cl [BB*NT*C2d];     // ctx
__device__ float  g_cx2[BB*NT*C2d];                       // residual fp32
__device__ __half g_Zh [BB*NT*C2d], g_Zl [BB*NT*C2d];     // LN(cx2)
__device__ __half g_Fh [BB*NT*C2E], g_Fl [BB*NT*C2E];     // gelu(fc1)
// weights (pre-transposed + split)
__device__ __half g_WqTh[NHd*C2d*C2d], g_WqTl[NHd*C2d*C2d];
__device__ __half g_WkTh[NHd*KVd*KVd], g_WkTl[NHd*KVd*KVd];
__device__ __half g_Wvh [NHd*KVd*KVd], g_Wvl [NHd*KVd*KVd];
__device__ __half g_WoTh[C2d*C2d],     g_WoTl[C2d*C2d];
__device__ __half g_f1Th[C2E*C2d],     g_f1Tl[C2E*C2d];
__device__ __half g_f2Th[C2d*C2E],     g_f2Tl[C2d*C2E];
__device__ float g_sc[BB*NHd];
__device__ float g_part[BB*NHd*32*2];

// ===================== PTX helpers (baseline sm_80+ only) ====================
__device__ __forceinline__ uint32_t smem_u32(const void* p) {
    uint32_t a;
    asm("{ .reg .u64 t; cvta.to.shared.u64 t, %1; cvt.u32.u64 %0, t; }" : "=r"(a) : "l"(p));
    return a;
}
#define CPA16(d, s)   asm volatile("cp.async.cg.shared.global [%0], [%1], 16;" :: "r"(d), "l"(s))
#define CPA_COMMIT()  asm volatile("cp.async.commit_group;" ::: "memory")
#define CPA_WAIT1()   asm volatile("cp.async.wait_group 1;" ::: "memory")
#define CPA_WAIT0()   asm volatile("cp.async.wait_group 0;" ::: "memory")

#define LDSM4(r, a) \
    asm volatile("ldmatrix.sync.aligned.m8n8.x4.shared.b16 {%0,%1,%2,%3}, [%4];" \
        : "=r"((r)[0]), "=r"((r)[1]), "=r"((r)[2]), "=r"((r)[3]) : "r"(a))

#define MMA16816(C, A, B0, B1) \
    asm volatile("mma.sync.aligned.m16n8k16.row.col.f32.f16.f16.f32 " \
        "{%0,%1,%2,%3}, {%4,%5,%6,%7}, {%8,%9}, {%0,%1,%2,%3};" \
        : "+f"((C)[0]), "+f"((C)[1]), "+f"((C)[2]), "+f"((C)[3]) \
        : "r"((A)[0]), "r"((A)[1]), "r"((A)[2]), "r"((A)[3]), "r"(B0), "r"(B1))

__device__ __forceinline__ void splt(float v, __half& h, __half& l) {
    h = __float2half_rn(v);
    l = __float2half_rn(v - __half2float(h));
}
__device__ __forceinline__ int selidx(int mode, int z) {
    return mode == 0 ? z : (mode == 1 ? (z & 3) : (z >> 2));
}

// block reductions (warp shuffle + tiny smem); fixed order -> deterministic
__device__ __forceinline__ float2 bred2(float s, float q, float* sh, int tid, int nw) {
#pragma unroll
    for (int o = 16; o; o >>= 1) {
        s += __shfl_xor_sync(0xffffffffu, s, o);
        q += __shfl_xor_sync(0xffffffffu, q, o);
    }
    if ((tid & 31) == 0) { sh[(tid >> 5) * 2] = s; sh[(tid >> 5) * 2 + 1] = q; }
    __syncthreads();
    float rs = 0.f, rq = 0.f;
    for (int j = 0; j < nw; ++j) { rs += sh[j * 2]; rq += sh[j * 2 + 1]; }
    __syncthreads();
    return make_float2(rs, rq);
}
__device__ __forceinline__ float bmax(float v, float* sh, int tid, int nw) {
#pragma unroll
    for (int o = 16; o; o >>= 1) v = fmaxf(v, __shfl_xor_sync(0xffffffffu, v, o));
    if ((tid & 31) == 0) sh[tid >> 5] = v;
    __syncthreads();
    float r = sh[0];
    for (int j = 1; j < nw; ++j) r = fmaxf(r, sh[j]);
    __syncthreads();
    return r;
}

// ===================== mma.sync split-fp16 GEMM ==============================
// C[M,Nn] = outScale * sum_h A_h[M,K] * B_h[N,K]^T  (+ epilogue)
// PASSES: 2 -> Ah*Bh + Al*Bh (B fp16-rounded);  3 -> + Ah*Bl (B split too)
// EPI: 0 none, 1 +add, 2 +bias,gelu, 3 +bias+add.  OUT: 0 fp32, 1 fp16 hi/lo
// BKE elems per chunk; smem row stride 2*BKE+16 B -> mod 128 = 16, conflict-free
// ldmatrix cycling across 8-row groups.
template<int BKE, int PASSES, int EPI, int OUT>
__global__ __launch_bounds__(256)
void mma_gemm(const __half* __restrict__ Ahi, const __half* __restrict__ Alo,
              const __half* __restrict__ Bhi, const __half* __restrict__ Blo,
              float* __restrict__ C, __half* __restrict__ Chi, __half* __restrict__ Clo,
              const float* __restrict__ bias, const float* __restrict__ addp,
              int M, int Nn, int K, int lda, int ldb,
              long sA, long sB, long sC, int selA, int selB,
              int nH, long hA, long hB, float outScale)
{
    constexpr int PADB  = 2 * BKE + 16;
    constexpr int TILEB = 128 * PADB;
    constexpr int NTL   = (PASSES == 3) ? 4 : 3;       // Ah, Al, Bh[, Bl]
    constexpr uint32_t STB = NTL * TILEB;              // stage bytes
    constexpr int SEGS  = BKE / 8;                     // 16B segments per row
    constexpr int RSTEP = 256 / SEGS;
    constexpr int ITERS = 128 / RSTEP;
    constexpr int KSN   = BKE / 16;

    extern __shared__ char smem[];
    const uint32_t sb = smem_u32(smem);
    const int tid = threadIdx.x, wid = tid >> 5, lane = tid & 31;
    const int z = blockIdx.z;
    const int m0 = blockIdx.y * 128, n0 = blockIdx.x * 128;
    const int warpM = (wid & 3) * 32, warpN = (wid >> 2) * 64;

    const __half* A0h = Ahi + (long)selidx(selA, z) * sA;
    const __half* A0l = Alo + (long)selidx(selA, z) * sA;
    const __half* B0h = Bhi + (long)selidx(selB, z) * sB;
    const __half* B0l = (PASSES == 3) ? (Blo + (long)selidx(selB, z) * sB) : nullptr;

    const int nchK = K / BKE;
    const int nch  = nH * nchK;

    const int srow = tid / SEGS;
    const int sseg = tid % SEGS;

    auto issue = [&](int ch) {
        const uint32_t so = sb + (uint32_t)(ch & 1) * STB;
        const int h  = ch / nchK;
        const int k0 = (ch - h * nchK) * BKE;
        const __half* srcs[4] = { A0h + (long)h * hA, A0l + (long)h * hA,
                                  B0h + (long)h * hB,
                                  (PASSES == 3) ? (B0l + (long)h * hB) : nullptr };
#pragma unroll
        for (int t4 = 0; t4 < NTL; ++t4) {
            const int ld = (t4 < 2) ? lda : ldb;
            const int rb = (t4 < 2) ? m0  : n0;
            const __half* gb = srcs[t4] + (long)(rb + srow) * ld + k0 + sseg * 8;
            const uint32_t tb = so + t4 * TILEB + srow * PADB + sseg * 16;
#pragma unroll
            for (int j = 0; j < ITERS; ++j)
                CPA16(tb + j * RSTEP * PADB, gb + (long)(j * RSTEP) * ld);
        }
        CPA_COMMIT();
    };

    float acc[2][8][4];
#pragma unroll
    for (int i = 0; i < 2; ++i)
#pragma unroll
        for (int j = 0; j < 8; ++j)
#pragma unroll
            for (int k = 0; k < 4; ++k) acc[i][j][k] = 0.f;

    issue(0);
    issue(1);

    const uint32_t aRow = (uint32_t)(warpM + (lane & 15)) * PADB + ((lane >> 4) << 4);
    const uint32_t bRow = (uint32_t)(warpN + ((lane >> 4) << 3) + (lane & 7)) * PADB
                        + (((lane >> 3) & 1) << 4);

    for (int ch = 0; ch < nch; ++ch) {
        if (ch < nch - 1) { CPA_WAIT1(); } else { CPA_WAIT0(); }
        __syncthreads();
        const uint32_t so = sb + (uint32_t)(ch & 1) * STB;
#pragma unroll
        for (int ks = 0; ks < KSN; ++ks) {
            const uint32_t kb = ks * 32;
            uint32_t ah[2][4], al[2][4], bh[4][4], bl[4][4];
#pragma unroll
            for (int mf = 0; mf < 2; ++mf) {
                const uint32_t ad = so + aRow + (uint32_t)(mf * 16 * PADB) + kb;
                LDSM4(ah[mf], ad);
                LDSM4(al[mf], ad + TILEB);
            }
#pragma unroll
            for (int q = 0; q < 4; ++q) {
                const uint32_t bd = so + 2 * TILEB + bRow + (uint32_t)(q * 16 * PADB) + kb;
                LDSM4(bh[q], bd);
                if (PASSES == 3) LDSM4(bl[q], bd + TILEB);
            }
#pragma unroll
            for (int mf = 0; mf < 2; ++mf)
#pragma unroll
                for (int nf = 0; nf < 8; ++nf) {
                    const uint32_t bh0 = bh[nf >> 1][(nf & 1) * 2];
                    const uint32_t bh1 = bh[nf >> 1][(nf & 1) * 2 + 1];
                    MMA16816(acc[mf][nf], ah[mf], bh0, bh1);
                    MMA16816(acc[mf][nf], al[mf], bh0, bh1);
                    if (PASSES == 3)
                        MMA16816(acc[mf][nf], ah[mf],
                                 bl[nf >> 1][(nf & 1) * 2], bl[nf >> 1][(nf & 1) * 2 + 1]);
                }
        }
        __syncthreads();
        if (ch + 2 < nch) issue(ch + 2);
    }

    // ---- epilogue (register accumulators -> gmem)
    const int rbase = m0 + warpM + (lane >> 2);
    const int cbase = n0 + warpN + (lane & 3) * 2;
#pragma unroll
    for (int mf = 0; mf < 2; ++mf) {
#pragma unroll
        for (int h2 = 0; h2 < 2; ++h2) {
            const long m = rbase + mf * 16 + h2 * 8;
#pragma unroll
            for (int nf = 0; nf < 8; ++nf) {
                const long col = cbase + nf * 8;
                float v0 = acc[mf][nf][h2 * 2]     * outScale;
                float v1 = acc[mf][nf][h2 * 2 + 1] * outScale;
                if (EPI == 1) {
                    const float2 ad = *(const float2*)(addp + m * Nn + col);
                    v0 += ad.x; v1 += ad.y;
                }
                if (EPI == 2) {
                    v0 += bias[col]; v1 += bias[col + 1];
                    v0 = 0.5f * v0 * (1.f + erff(v0 * 0.70710678118654752f));
                    v1 = 0.5f * v1 * (1.f + erff(v1 * 0.70710678118654752f));
                }
                if (EPI == 3) {
                    const float2 ad = *(const float2*)(addp + m * Nn + col);
                    v0 += bias[col]     + ad.x;
                    v1 += bias[col + 1] + ad.y;
                }
                const long idx = (long)z * sC + m * Nn + col;
                if (OUT == 0) {
                    *(float2*)(C + idx) = make_float2(v0, v1);
                } else {
                    __half h0, l0, h1, l1;
                    splt(v0, h0, l0); splt(v1, h1, l1);
                    *(__half2*)(Chi + idx) = __halves2half2(h0, h1);
                    *(__half2*)(Clo + idx) = __halves2half2(l0, l1);
                }
            }
        }
    }
}

// ===================== prep kernels (vectorized) =============================
// fp32 [Z][R][C] -> hi/lo fp16 [Z][C][R], 32x64 tiles, 16B gmem transactions
__global__ __launch_bounds__(256)
void tsplit_k(const float* __restrict__ in, __half* __restrict__ oh,
              __half* __restrict__ ol, int R, int Cc)
{
    __shared__ float t[32][65];
    const long zo = (long)blockIdx.z * R * Cc;
    const int c0 = blockIdx.x * 64, r0 = blockIdx.y * 32;
    const int tid = threadIdx.x;
#pragma unroll
    for (int it = 0; it < 2; ++it) {
        const int idx = tid + it * 256;
        const int r = idx >> 4, cs = idx & 15;
        const float4 v = *(const float4*)(in + zo + (long)(r0 + r) * Cc + c0 + cs * 4);
        t[r][cs * 4 + 0] = v.x; t[r][cs * 4 + 1] = v.y;
        t[r][cs * 4 + 2] = v.z; t[r][cs * 4 + 3] = v.w;
    }
    __syncthreads();
    const int c = tid >> 2, rs = tid & 3;
    __align__(16) __half hh[8], ll[8];
#pragma unroll
    for (int j = 0; j < 8; ++j) splt(t[rs * 8 + j][c], hh[j], ll[j]);
    const long o = zo + (long)(c0 + c) * R + r0 + rs * 8;
    *(uint4*)&oh[o] = *(uint4*)hh;
    *(uint4*)&ol[o] = *(uint4*)ll;
}

// fp32 -> hi/lo fp16 (same layout)
__global__ void psplit_k(const float* __restrict__ in, __half* __restrict__ oh,
                         __half* __restrict__ ol, long n4)
{
    for (long i = blockIdx.x * blockDim.x + threadIdx.x; i < n4; i += (long)gridDim.x * blockDim.x) {
        float4 v = ((const float4*)in)[i];
        __half hh[4], ll[4];
        splt(v.x, hh[0], ll[0]); splt(v.y, hh[1], ll[1]);
        splt(v.z, hh[2], ll[2]); splt(v.w, hh[3], ll[3]);
        ((uint2*)oh)[i] = *(uint2*)hh;
        ((uint2*)ol)[i] = *(uint2*)ll;
    }
}

// fp16 [Z][R][C] -> [Z][C][R], 32x64 tiles, 16B transactions
__global__ __launch_bounds__(256)
void tb16_k(const __half* __restrict__ in, __half* __restrict__ out, int R, int Cc)
{
    __shared__ __half t[32][72];
    const long zo = (long)blockIdx.z * R * Cc;
    const int c0 = blockIdx.x * 64, r0 = blockIdx.y * 32;
    const int tid = threadIdx.x;
    {
        const int r = tid >> 3, cs = tid & 7;
        __align__(16) __half v[8];
        *(uint4*)v = *(const uint4*)(in + zo + (long)(r0 + r) * Cc + c0 + cs * 8);
#pragma unroll
        for (int j = 0; j < 8; ++j) t[r][cs * 8 + j] = v[j];
    }
    __syncthreads();
    const int c = tid >> 2, rs = tid & 3;
    __align__(16) __half o8[8];
#pragma unroll
    for (int j = 0; j < 8; ++j) o8[j] = t[rs * 8 + j][c];
    *(uint4*)&out[zo + (long)(c0 + c) * R + r0 + rs * 8] = *(uint4*)o8;
}

// input LayerNorms -> split outputs (224 thr: 448 float4 = 1792 elems)
__global__ __launch_bounds__(224)
void ln_in_kernel(const float* __restrict__ e1, const float* __restrict__ e2,
                  const float* __restrict__ e3,
                  const float* __restrict__ ag, const float* __restrict__ ab,
                  const float* __restrict__ g1, const float* __restrict__ b1,
                  __half* __restrict__ Yh, __half* __restrict__ Yl,
                  __half* __restrict__ Xh, __half* __restrict__ Xl)
{
    const long row = blockIdx.x;
    const int  tid = threadIdx.x;
    const float4* p1 = (const float4*)(e1 + row * C1d);
    const float4* p2 = (const float4*)(e2 + row * C2d);
    const float4* p3 = (const float4*)(e3 + row * C3d);
    __shared__ float sh[16];

    const int f0 = tid, f1 = tid + 224;
    const bool isX = (f0 >= 64) && (f0 < 192);
    float4 a = (f0 < 64) ? p1[f0] : (isX ? p2[f0 - 64] : p3[f0 - 192]);
    float4 b = p3[f1 - 192];

    float s = a.x + a.y + a.z + a.w + b.x + b.y + b.z + b.w;
    float q = a.x * a.x + a.y * a.y + a.z * a.z + a.w * a.w
            + b.x * b.x + b.y * b.y + b.z * b.z + b.w * b.w;
    float2 r = bred2(s, q, sh, tid, 7);
    float mean = r.x * (1.f / KVd);
    float inv  = rsqrtf(r.y * (1.f / KVd) - mean * mean + 1e-6f);

    const float4* g4 = (const float4*)ag;
    const float4* b4 = (const float4*)ab;
    {
        const float4 ga = g4[f0], ba = b4[f0];
        __half hh[4], ll[4];
        splt((a.x - mean) * inv * ga.x + ba.x, hh[0], ll[0]);
        splt((a.y - mean) * inv * ga.y + ba.y, hh[1], ll[1]);
        splt((a.z - mean) * inv * ga.z + ba.z, hh[2], ll[2]);
        splt((a.w - mean) * inv * ga.w + ba.w, hh[3], ll[3]);
        *(uint2*)&Yh[row * KVd + f0 * 4] = *(uint2*)hh;
        *(uint2*)&Yl[row * KVd + f0 * 4] = *(uint2*)ll;
        const float4 gb = g4[f1], bb = b4[f1];
        splt((b.x - mean) * inv * gb.x + bb.x, hh[0], ll[0]);
        splt((b.y - mean) * inv * gb.y + bb.y, hh[1], ll[1]);
        splt((b.z - mean) * inv * gb.z + bb.z, hh[2], ll[2]);
        splt((b.w - mean) * inv * gb.w + bb.w, hh[3], ll[3]);
        *(uint2*)&Yh[row * KVd + f1 * 4] = *(uint2*)hh;
        *(uint2*)&Yl[row * KVd + f1 * 4] = *(uint2*)ll;
    }

    // X = LN(emb2): chunk0 of threads 64..191 covers e2 exactly
    float sX = isX ? (a.x + a.y + a.z + a.w) : 0.f;
    float qX = isX ? (a.x * a.x + a.y * a.y + a.z * a.z + a.w * a.w) : 0.f;
    float2 rX = bred2(sX, qX, sh, tid, 7);
    if (isX) {
        float meanX = rX.x * (1.f / C2d);
        float invX  = rsqrtf(rX.y * (1.f / C2d) - meanX * meanX + 1e-6f);
        const int fx = f0 - 64;
        const float4 gx = ((const float4*)g1)[fx], bx = ((const float4*)b1)[fx];
        __half hh[4], ll[4];
        splt((a.x - meanX) * invX * gx.x + bx.x, hh[0], ll[0]);
        splt((a.y - meanX) * invX * gx.y + bx.y, hh[1], ll[1]);
        splt((a.z - meanX) * invX * gx.z + bx.z, hh[2], ll[2]);
        splt((a.w - meanX) * invX * gx.w + bx.w, hh[3], ll[3]);
        *(uint2*)&Xh[row * C2d + fx * 4] = *(uint2*)hh;
        *(uint2*)&Xl[row * C2d + fx * 4] = *(uint2*)ll;
    }
}

__global__ __launch_bounds__(128)
void ln2_kernel(const float* __restrict__ in,
                const float* __restrict__ g, const float* __restrict__ b,
                __half* __restrict__ Zh, __half* __restrict__ Zl)
{
    const long row = blockIdx.x;
    const int  tid = threadIdx.x;
    __shared__ float sh[8];
    const float4 v = ((const float4*)(in + row * C2d))[tid];
    float s = v.x + v.y + v.z + v.w;
    float q = v.x * v.x + v.y * v.y + v.z * v.z + v.w * v.w;
    float2 r = bred2(s, q, sh, tid, 4);
    float mean = r.x * (1.f / C2d);
    float inv  = rsqrtf(r.y * (1.f / C2d) - mean * mean + 1e-6f);
    const float4 gg = ((const float4*)g)[tid], bb = ((const float4*)b)[tid];
    __half hh[4], ll[4];
    splt((v.x - mean) * inv * gg.x + bb.x, hh[0], ll[0]);
    splt((v.y - mean) * inv * gg.y + bb.y, hh[1], ll[1]);
    splt((v.z - mean) * inv * gg.z + bb.z, hh[2], ll[2]);
    splt((v.w - mean) * inv * gg.w + bb.w, hh[3], ll[3]);
    *(uint2*)&Zh[row * C2d + tid * 4] = *(uint2*)hh;
    *(uint2*)&Zl[row * C2d + tid * 4] = *(uint2*)ll;
}

// stage 1: 32 partial blocks per (b,h) map -> g_part
__global__ __launch_bounds__(256)
void stats1_kernel(const float* __restrict__ S, float* __restrict__ part)
{
    const int z = blockIdx.x >> 5, seg = blockIdx.x & 31;
    const int tid = threadIdx.x;
    const float4* p = (const float4*)(S + (long)z * C2d * KVd) + seg * 7168;
    float s = 0.f, q = 0.f;
#pragma unroll 4
    for (int i = tid; i < 7168; i += 256) {
        float4 v = p[i];
        s += v.x + v.y + v.z + v.w;
        q += v.x * v.x + v.y * v.y + v.z * v.z + v.w * v.w;
    }
    __shared__ float sh[16];
    float2 r = bred2(s, q, sh, tid, 8);
    if (tid == 0) { part[blockIdx.x * 2] = r.x; part[blockIdx.x * 2 + 1] = r.y; }
}

// stage 2: finish per-map variance -> softmax scale
__global__ __launch_bounds__(32)
void stats2_kernel(const float* __restrict__ part, float* __restrict__ scale)
{
    const int z = blockIdx.x, lane = threadIdx.x;
    float s = part[(z * 32 + lane) * 2];
    float q = part[(z * 32 + lane) * 2 + 1];
#pragma unroll
    for (int o = 16; o; o >>= 1) {
        s += __shfl_xor_sync(0xffffffffu, s, o);
        q += __shfl_xor_sync(0xffffffffu, q, o);
    }
    if (lane == 0) {
        const float cnt = (float)(C2d * KVd);
        float mean = s / cnt;
        float var  = q / cnt - mean * mean;
        float a    = rsqrtf((float)KVd);
        scale[z]   = a * rsqrtf(a * a * var + 1e-5f);
    }
}

__global__ __launch_bounds__(224)
void softmax_kernel(const float* __restrict__ S, const float* __restrict__ scale,
                    __half* __restrict__ Ph, __half* __restrict__ Pl)
{
    const long row = blockIdx.x;
    const int  tid = threadIdx.x;
    const float4* p = (const float4*)(S + row * KVd);
    const float sc = scale[blockIdx.x >> 9];
    __shared__ float sh[16];

    float4 v0 = p[tid], v1 = p[tid + 224];
    float mx = fmaxf(fmaxf(fmaxf(v0.x, v0.y), fmaxf(v0.z, v0.w)),
                     fmaxf(fmaxf(v1.x, v1.y), fmaxf(v1.z, v1.w)));
    mx = bmax(mx, sh, tid, 7);

    float e0[4] = { __expf((v0.x - mx) * sc), __expf((v0.y - mx) * sc),
                    __expf((v0.z - mx) * sc), __expf((v0.w - mx) * sc) };
    float e1[4] = { __expf((v1.x - mx) * sc), __expf((v1.y - mx) * sc),
                    __expf((v1.z - mx) * sc), __expf((v1.w - mx) * sc) };
    float s = e0[0] + e0[1] + e0[2] + e0[3] + e1[0] + e1[1] + e1[2] + e1[3];
    float2 r = bred2(s, 0.f, sh, tid, 7);
    const float inv = 1.f / r.x;

    __half hh[4], ll[4];
#pragma unroll
    for (int j = 0; j < 4; ++j) splt(e0[j] * inv, hh[j], ll[j]);
    *(uint2*)&Ph[row * KVd + tid * 4] = *(uint2*)hh;
    *(uint2*)&Pl[row * KVd + tid * 4] = *(uint2*)ll;
#pragma unroll
    for (int j = 0; j < 4; ++j) splt(e1[j] * inv, hh[j], ll[j]);
    *(uint2*)&Ph[row * KVd + (tid + 224) * 4] = *(uint2*)hh;
    *(uint2*)&Pl[row * KVd + (tid + 224) * 4] = *(uint2*)ll;
}

// ===================== launcher =============================================
#define SYM(v, t, s) t* v; { void* _p; cudaGetSymbolAddress(&_p, s); v = (t*)_p; }

extern "C" void kernel_launch(void* const* d_in, const int* in_sizes, int n_in,
                              void* d_out, int out_size)
{
    const float* emb1    = (const float*)d_in[0];
    const float* emb2    = (const float*)d_in[1];
    const float* emb3    = (const float*)d_in[2];
    const float* Wq      = (const float*)d_in[3];
    const float* Wk      = (const float*)d_in[4];
    const float* Wv      = (const float*)d_in[5];
    const float* Wout    = (const float*)d_in[6];
    const float* ln1_g   = (const float*)d_in[7];
    const float* ln1_b   = (const float*)d_in[8];
    const float* lnall_g = (const float*)d_in[9];
    const float* lnall_b = (const float*)d_in[10];
    const float* lnffn_g = (const float*)d_in[11];
    const float* lnffn_b = (const float*)d_in[12];
    const float* fc1_w   = (const float*)d_in[13];
    const float* fc1_b   = (const float*)d_in[14];
    const float* fc2_w   = (const float*)d_in[15];
    const float* fc2_b   = (const float*)d_in[16];
    float* out = (float*)d_out;

    SYM(Yh, __half, g_Yh)   SYM(Yl, __half, g_Yl)
    SYM(Yth, __half, g_Yth) SYM(Ytl, __half, g_Ytl)
    SYM(Xh, __half, g_Xh)   SYM(Xl, __half, g_Xl)
    SYM(Xth, __half, g_Xth) SYM(Xtl, __half, g_Xtl)
    SYM(Gth, __half, g_Gth) SYM(Gtl, __half, g_Gtl)
    SYM(T1h, __half, g_T1h) SYM(T1l, __half, g_T1l)
    SYM(S, float, g_S)
    SYM(Ph, __half, g_Ph)   SYM(Pl, __half, g_Pl)
    SYM(Mth, __half, g_Mth) SYM(Mtl, __half, g_Mtl)
    SYM(Ch, __half, g_Ch)   SYM(Cl, __half, g_Cl)
    SYM(cx2, float, g_cx2)
    SYM(Zh, __half, g_Zh)   SYM(Zl, __half, g_Zl)
    SYM(Fh, __half, g_Fh)   SYM(Fl, __half, g_Fl)
    SYM(WqTh, __half, g_WqTh) SYM(WqTl, __half, g_WqTl)
    SYM(WkTh, __half, g_WkTh) SYM(WkTl, __half, g_WkTl)
    SYM(Wvh, __half, g_Wvh)   SYM(Wvl, __half, g_Wvl)
    SYM(WoTh, __half, g_WoTh) SYM(WoTl, __half, g_WoTl)
    SYM(f1Th, __half, g_f1Th) SYM(f1Tl, __half, g_f1Tl)
    SYM(f2Th, __half, g_f2Th) SYM(f2Tl, __half, g_f2Tl)
    SYM(scl, float, g_sc)     SYM(part, float, g_part)

    const int SMA = 2 * 3 * (128 * (2 * 128 + 16));   // 208896 B, BK128 2-pass
    const int SMB = 2 * 4 * (128 * (2 * 64 + 16));    // 147456 B, BK64 3-pass
    cudaFuncSetAttribute(mma_gemm<128, 2, 0, 0>, cudaFuncAttributeMaxDynamicSharedMemorySize, SMA);
    cudaFuncSetAttribute(mma_gemm<128, 2, 0, 1>, cudaFuncAttributeMaxDynamicSharedMemorySize, SMA);
    cudaFuncSetAttribute(mma_gemm<64, 3, 0, 1>,  cudaFuncAttributeMaxDynamicSharedMemorySize, SMB);
    cudaFuncSetAttribute(mma_gemm<128, 2, 1, 0>, cudaFuncAttributeMaxDynamicSharedMemorySize, SMA);
    cudaFuncSetAttribute(mma_gemm<128, 2, 2, 1>, cudaFuncAttributeMaxDynamicSharedMemorySize, SMA);
    cudaFuncSetAttribute(mma_gemm<128, 2, 3, 0>, cudaFuncAttributeMaxDynamicSharedMemorySize, SMA);

    // weight prep: transpose+split / split (32x64 tiles)
    tsplit_k<<<dim3(C2d / 64, C2d / 32, NHd), 256>>>(Wq, WqTh, WqTl, C2d, C2d);
    tsplit_k<<<dim3(KVd / 64, KVd / 32, NHd), 256>>>(Wk, WkTh, WkTl, KVd, KVd);
    tsplit_k<<<dim3(C2d / 64, C2d / 32, 1), 256>>>(Wout, WoTh, WoTl, C2d, C2d);
    tsplit_k<<<dim3(C2E / 64, C2d / 32, 1), 256>>>(fc1_w, f1Th, f1Tl, C2d, C2E);
    tsplit_k<<<dim3(C2d / 64, C2E / 32, 1), 256>>>(fc2_w, f2Th, f2Tl, C2E, C2d);
    psplit_k<<<4096, 256>>>(Wv, Wvh, Wvl, (long)NHd * KVd * KVd / 4);

    // 1. input LayerNorms (split outputs)
    ln_in_kernel<<<BB * NT, 224>>>(emb1, emb2, emb3, lnall_g, lnall_b, ln1_g, ln1_b,
                                   Yh, Yl, Xh, Xl);
    // transposes for step 2
    tb16_k<<<dim3(KVd / 64, NT / 32, BB), 256>>>(Yh, Yth, NT, KVd);
    tb16_k<<<dim3(KVd / 64, NT / 32, BB), 256>>>(Yl, Ytl, NT, KVd);
    tb16_k<<<dim3(C2d / 64, NT / 32, BB), 256>>>(Xh, Xth, NT, C2d);
    tb16_k<<<dim3(C2d / 64, NT / 32, BB), 256>>>(Xl, Xtl, NT, C2d);

    // 2. Gt_b = Yt_b Xt_b^T  [1792,512], K=1024
    mma_gemm<128, 2, 0, 1><<<dim3(C2d / 128, KVd / 128, BB), 256, SMA>>>(
        Yth, Ytl, Xth, nullptr, nullptr, Gth, Gtl, nullptr, nullptr,
        KVd, C2d, NT, NT, NT,
        (long)KVd * NT, (long)C2d * NT, (long)KVd * C2d, 0, 0, 1, 0, 0, 1.f);

    // 3. T1[b,h] = WqT_h Gt_b^T  [512,1792], K=512  (3-pass: Gt has corr spikes)
    mma_gemm<64, 3, 0, 1><<<dim3(KVd / 128, C2d / 128, BB * NHd), 256, SMB>>>(
        WqTh, WqTl, Gth, Gtl, nullptr, T1h, T1l, nullptr, nullptr,
        C2d, KVd, C2d, C2d, C2d,
        (long)C2d * C2d, (long)KVd * C2d, (long)C2d * KVd, 1, 2, 1, 0, 0, 1.f);

    // 4. S[b,h] = T1 WkT_h^T  [512,1792], K=1792 (fp32 out)
    mma_gemm<128, 2, 0, 0><<<dim3(KVd / 128, C2d / 128, BB * NHd), 256, SMA>>>(
        T1h, T1l, WkTh, nullptr, S, nullptr, nullptr, nullptr, nullptr,
        C2d, KVd, KVd, KVd, KVd,
        (long)C2d * KVd, (long)KVd * KVd, (long)C2d * KVd, 0, 1, 1, 0, 0, 1.f);

    // 5-6. instance-norm stats (two-stage) + row softmax (split probs)
    stats1_kernel<<<BB * NHd * 32, 256>>>(S, part);
    stats2_kernel<<<BB * NHd, 32>>>(part, scl);
    softmax_kernel<<<BB * NHd * C2d, 224>>>(S, scl, Ph, Pl);

    // 7. Mmt_b[c,e] = (1/H) sum_h sum_k P[b,h,c,k] Wv_h[e,k]  [512,1792]
    mma_gemm<128, 2, 0, 1><<<dim3(KVd / 128, C2d / 128, BB), 256, SMA>>>(
        Ph, Pl, Wvh, nullptr, nullptr, Mth, Mtl, nullptr, nullptr,
        C2d, KVd, KVd, KVd, KVd,
        (long)NHd * C2d * KVd, 0, (long)C2d * KVd, 0, 0,
        NHd, (long)C2d * KVd, (long)KVd * KVd, 1.f / NHd);

    // 8. ctx_b = Y_b Mmt_b^T  [1024,512], K=1792
    mma_gemm<128, 2, 0, 1><<<dim3(C2d / 128, NT / 128, BB), 256, SMA>>>(
        Yh, Yl, Mth, nullptr, nullptr, Ch, Cl, nullptr, nullptr,
        NT, C2d, KVd, KVd, KVd,
        (long)NT * KVd, (long)C2d * KVd, (long)NT * C2d, 0, 0, 1, 0, 0, 1.f);

    // 9. cx2 = ctx WoutT^T + emb2  [8192,512]
    mma_gemm<128, 2, 1, 0><<<dim3(C2d / 128, BB * NT / 128, 1), 256, SMA>>>(
        Ch, Cl, WoTh, nullptr, cx2, nullptr, nullptr, nullptr, emb2,
        BB * NT, C2d, C2d, C2d, C2d, 0, 0, 0, 0, 0, 1, 0, 0, 1.f);

    // 10. Z = LN(cx2) (split out)
    ln2_kernel<<<BB * NT, 128>>>(cx2, lnffn_g, lnffn_b, Zh, Zl);

    // 11. F = gelu(Z f1T^T + b1)  [8192,2048]
    mma_gemm<128, 2, 2, 1><<<dim3(C2E / 128, BB * NT / 128, 1), 256, SMA>>>(
        Zh, Zl, f1Th, nullptr, nullptr, Fh, Fl, fc1_b, nullptr,
        BB * NT, C2E, C2d, C2d, C2d, 0, 0, 0, 0, 0, 1, 0, 0, 1.f);

    // 12. out = F f2T^T + b2 + cx2  [8192,512]
    mma_gemm<128, 2, 3, 0><<<dim3(C2d / 128, BB * NT / 128, 1), 256, SMA>>>(
        Fh, Fl, f2Th, nullptr, out, nullptr, nullptr, fc2_b, cx2,
        BB * NT, C2d, C2E, C2E, C2E, 0, 0, 0, 0, 0, 1, 0, 0, 1.f);
}

// round 11
// speedup vs baseline: 4.9631x; 1.6297x over previous
#include <cuda_runtime.h>
#include <cuda_fp16.h>
#include <math.h>
#include <stdint.h>

// Problem constants
#define BB   8
#define NT   1024
#define C1d  256
#define C2d  512
#define C3d  1024
#define KVd  1792
#define NHd  4
#define C2E  2048

// ===================== scratch (device statics) ==============================
__device__ __half g_Yh [BB*NT*KVd];                       // LN(concat)  [b][n][kv]
__device__ __half g_Yth[BB*NT*KVd];                       // transposed  [b][kv][n]
__device__ __half g_Xh [BB*NT*C2d];                       // LN(emb2)    [b][n][c]
__device__ __half g_Xth[BB*NT*C2d];                       // transposed  [b][c][n]
__device__ __half g_Gth[BB*KVd*C2d], g_Gtl[BB*KVd*C2d];   // Gt split (spiky!)
__device__ __half g_T1h[BB*NHd*C2d*KVd];
__device__ float  g_S  [BB*NHd*C2d*KVd];                  // scores fp32
__device__ __half g_Ph [BB*NHd*C2d*KVd];                  // probs
__device__ __half g_Mth[BB*C2d*KVd];                      // Mmt [b][c][e]
__device__ __half g_Ch [BB*NT*C2d];                       // ctx
__device__ float  g_cx2[BB*NT*C2d];                       // residual fp32
__device__ __half g_Zh [BB*NT*C2d];                       // LN(cx2)
__device__ __half g_Fh [BB*NT*C2E];                       // gelu(fc1)
// weights (pre-transposed + rounded to fp16)
__device__ __half g_WqTh[NHd*C2d*C2d];
__device__ __half g_WkTh[NHd*KVd*KVd];
__device__ __half g_Wvh [NHd*KVd*KVd];
__device__ __half g_WoTh[C2d*C2d];
__device__ __half g_f1Th[C2E*C2d];
__device__ __half g_f2Th[C2d*C2E];
__device__ float g_sc[BB*NHd];
__device__ float g_part[BB*NHd*32*2];

// ===================== PTX helpers (baseline sm_80+ only) ====================
__device__ __forceinline__ uint32_t smem_u32(const void* p) {
    uint32_t a;
    asm("{ .reg .u64 t; cvta.to.shared.u64 t, %1; cvt.u32.u64 %0, t; }" : "=r"(a) : "l"(p));
    return a;
}
#define CPA16(d, s)   asm volatile("cp.async.cg.shared.global [%0], [%1], 16;" :: "r"(d), "l"(s))
#define CPA_COMMIT()  asm volatile("cp.async.commit_group;" ::: "memory")
#define CPA_WAIT1()   asm volatile("cp.async.wait_group 1;" ::: "memory")
#define CPA_WAIT0()   asm volatile("cp.async.wait_group 0;" ::: "memory")

#define LDSM4(r, a) \
    asm volatile("ldmatrix.sync.aligned.m8n8.x4.shared.b16 {%0,%1,%2,%3}, [%4];" \
        : "=r"((r)[0]), "=r"((r)[1]), "=r"((r)[2]), "=r"((r)[3]) : "r"(a))

#define MMA16816(C, A, B0, B1) \
    asm volatile("mma.sync.aligned.m16n8k16.row.col.f32.f16.f16.f32 " \
        "{%0,%1,%2,%3}, {%4,%5,%6,%7}, {%8,%9}, {%0,%1,%2,%3};" \
        : "+f"((C)[0]), "+f"((C)[1]), "+f"((C)[2]), "+f"((C)[3]) \
        : "r"((A)[0]), "r"((A)[1]), "r"((A)[2]), "r"((A)[3]), "r"(B0), "r"(B1))

__device__ __forceinline__ void splt(float v, __half& h, __half& l) {
    h = __float2half_rn(v);
    l = __float2half_rn(v - __half2float(h));
}
__device__ __forceinline__ int selidx(int mode, int z) {
    return mode == 0 ? z : (mode == 1 ? (z & 3) : (z >> 2));
}

// block reductions (warp shuffle + tiny smem); fixed order -> deterministic
__device__ __forceinline__ float2 bred2(float s, float q, float* sh, int tid, int nw) {
#pragma unroll
    for (int o = 16; o; o >>= 1) {
        s += __shfl_xor_sync(0xffffffffu, s, o);
        q += __shfl_xor_sync(0xffffffffu, q, o);
    }
    if ((tid & 31) == 0) { sh[(tid >> 5) * 2] = s; sh[(tid >> 5) * 2 + 1] = q; }
    __syncthreads();
    float rs = 0.f, rq = 0.f;
    for (int j = 0; j < nw; ++j) { rs += sh[j * 2]; rq += sh[j * 2 + 1]; }
    __syncthreads();
    return make_float2(rs, rq);
}
__device__ __forceinline__ float bmax(float v, float* sh, int tid, int nw) {
#pragma unroll
    for (int o = 16; o; o >>= 1) v = fmaxf(v, __shfl_xor_sync(0xffffffffu, v, o));
    if ((tid & 31) == 0) sh[tid >> 5] = v;
    __syncthreads();
    float r = sh[0];
    for (int j = 1; j < nw; ++j) r = fmaxf(r, sh[j]);
    __syncthreads();
    return r;
}

// ===================== mma.sync fp16 GEMM ====================================
// C[M,Nn] = outScale * sum_h A_h[M,K] * B_h[N,K]^T  (+ epilogue)
// MODE: 0 -> 1-pass (A,B fp16-rounded);  1 -> 2-pass B-split (A*Bh + A*Bl)
// EPI: 0 none, 1 +add, 2 +bias,gelu, 3 +bias+add.
// OUT: 0 fp32, 1 fp16 hi+lo, 2 fp16 rounded
// BKE elems per chunk; smem row stride 2*BKE+16 B -> mod 128 = 16, conflict-free
// ldmatrix cycling across 8-row groups.
template<int BKE, int MODE, int EPI, int OUT>
__global__ __launch_bounds__(256)
void mma_gemm(const __half* __restrict__ Ahi,
              const __half* __restrict__ Bhi, const __half* __restrict__ Blo,
              float* __restrict__ C, __half* __restrict__ Chi, __half* __restrict__ Clo,
              const float* __restrict__ bias, const float* __restrict__ addp,
              int M, int Nn, int K, int lda, int ldb,
              long sA, long sB, long sC, int selA, int selB,
              int nH, long hA, long hB, float outScale)
{
    constexpr int PADB  = 2 * BKE + 16;
    constexpr int TILEB = 128 * PADB;
    constexpr int NTL   = 2 + MODE;                    // A, Bh[, Bl]
    constexpr uint32_t STB = NTL * TILEB;              // stage bytes
    constexpr int SEGS  = BKE / 8;                     // 16B segments per row
    constexpr int RSTEP = 256 / SEGS;
    constexpr int ITERS = 128 / RSTEP;
    constexpr int KSN   = BKE / 16;

    extern __shared__ char smem[];
    const uint32_t sb = smem_u32(smem);
    const int tid = threadIdx.x, wid = tid >> 5, lane = tid & 31;
    const int z = blockIdx.z;
    const int m0 = blockIdx.y * 128, n0 = blockIdx.x * 128;
    const int warpM = (wid & 3) * 32, warpN = (wid >> 2) * 64;

    const __half* A0h = Ahi + (long)selidx(selA, z) * sA;
    const __half* B0h = Bhi + (long)selidx(selB, z) * sB;
    const __half* B0l = (MODE == 1) ? (Blo + (long)selidx(selB, z) * sB) : nullptr;

    const int nchK = K / BKE;
    const int nch  = nH * nchK;

    const int srow = tid / SEGS;
    const int sseg = tid % SEGS;

    auto issue = [&](int ch) {
        const uint32_t so = sb + (uint32_t)(ch & 1) * STB;
        const int h  = ch / nchK;
        const int k0 = (ch - h * nchK) * BKE;
        const __half* srcs[3] = { A0h + (long)h * hA, B0h + (long)h * hB,
                                  (MODE == 1) ? (B0l + (long)h * hB) : nullptr };
#pragma unroll
        for (int t4 = 0; t4 < NTL; ++t4) {
            const int ld = (t4 == 0) ? lda : ldb;
            const int rb = (t4 == 0) ? m0  : n0;
            const __half* gb = srcs[t4] + (long)(rb + srow) * ld + k0 + sseg * 8;
            const uint32_t tb = so + t4 * TILEB + srow * PADB + sseg * 16;
#pragma unroll
            for (int j = 0; j < ITERS; ++j)
                CPA16(tb + j * RSTEP * PADB, gb + (long)(j * RSTEP) * ld);
        }
        CPA_COMMIT();
    };

    float acc[2][8][4];
#pragma unroll
    for (int i = 0; i < 2; ++i)
#pragma unroll
        for (int j = 0; j < 8; ++j)
#pragma unroll
            for (int k = 0; k < 4; ++k) acc[i][j][k] = 0.f;

    issue(0);
    issue(1);

    const uint32_t aRow = (uint32_t)(warpM + (lane & 15)) * PADB + ((lane >> 4) << 4);
    const uint32_t bRow = (uint32_t)(warpN + ((lane >> 4) << 3) + (lane & 7)) * PADB
                        + (((lane >> 3) & 1) << 4);

    for (int ch = 0; ch < nch; ++ch) {
        if (ch < nch - 1) { CPA_WAIT1(); } else { CPA_WAIT0(); }
        __syncthreads();
        const uint32_t so = sb + (uint32_t)(ch & 1) * STB;
#pragma unroll
        for (int ks = 0; ks < KSN; ++ks) {
            const uint32_t kb = ks * 32;
            uint32_t ah[2][4], bh[4][4], bl[4][4];
#pragma unroll
            for (int mf = 0; mf < 2; ++mf)
                LDSM4(ah[mf], so + aRow + (uint32_t)(mf * 16 * PADB) + kb);
#pragma unroll
            for (int q = 0; q < 4; ++q) {
                const uint32_t bd = so + TILEB + bRow + (uint32_t)(q * 16 * PADB) + kb;
                LDSM4(bh[q], bd);
                if (MODE == 1) LDSM4(bl[q], bd + TILEB);
            }
#pragma unroll
            for (int mf = 0; mf < 2; ++mf)
#pragma unroll
                for (int nf = 0; nf < 8; ++nf) {
                    MMA16816(acc[mf][nf], ah[mf],
                             bh[nf >> 1][(nf & 1) * 2], bh[nf >> 1][(nf & 1) * 2 + 1]);
                    if (MODE == 1)
                        MMA16816(acc[mf][nf], ah[mf],
                                 bl[nf >> 1][(nf & 1) * 2], bl[nf >> 1][(nf & 1) * 2 + 1]);
                }
        }
        __syncthreads();
        if (ch + 2 < nch) issue(ch + 2);
    }

    // ---- epilogue (register accumulators -> gmem)
    const int rbase = m0 + warpM + (lane >> 2);
    const int cbase = n0 + warpN + (lane & 3) * 2;
#pragma unroll
    for (int mf = 0; mf < 2; ++mf) {
#pragma unroll
        for (int h2 = 0; h2 < 2; ++h2) {
            const long m = rbase + mf * 16 + h2 * 8;
#pragma unroll
            for (int nf = 0; nf < 8; ++nf) {
                const long col = cbase + nf * 8;
                float v0 = acc[mf][nf][h2 * 2]     * outScale;
                float v1 = acc[mf][nf][h2 * 2 + 1] * outScale;
                if (EPI == 1) {
                    const float2 ad = *(const float2*)(addp + m * Nn + col);
                    v0 += ad.x; v1 += ad.y;
                }
                if (EPI == 2) {
                    v0 += bias[col]; v1 += bias[col + 1];
                    v0 = 0.5f * v0 * (1.f + erff(v0 * 0.70710678118654752f));
                    v1 = 0.5f * v1 * (1.f + erff(v1 * 0.70710678118654752f));
                }
                if (EPI == 3) {
                    const float2 ad = *(const float2*)(addp + m * Nn + col);
                    v0 += bias[col]     + ad.x;
                    v1 += bias[col + 1] + ad.y;
                }
                const long idx = (long)z * sC + m * Nn + col;
                if (OUT == 0) {
                    *(float2*)(C + idx) = make_float2(v0, v1);
                } else if (OUT == 1) {
                    __half h0, l0, h1, l1;
                    splt(v0, h0, l0); splt(v1, h1, l1);
                    *(__half2*)(Chi + idx) = __halves2half2(h0, h1);
                    *(__half2*)(Clo + idx) = __halves2half2(l0, l1);
                } else {
                    *(__half2*)(Chi + idx) =
                        __halves2half2(__float2half_rn(v0), __float2half_rn(v1));
                }
            }
        }
    }
}

// ===================== prep kernels (vectorized) =============================
// fp32 [Z][R][C] -> fp16 [Z][C][R] (rounded), 32x64 tiles, 16B transactions
__global__ __launch_bounds__(256)
void tround_k(const float* __restrict__ in, __half* __restrict__ oh, int R, int Cc)
{
    __shared__ float t[32][65];
    const long zo = (long)blockIdx.z * R * Cc;
    const int c0 = blockIdx.x * 64, r0 = blockIdx.y * 32;
    const int tid = threadIdx.x;
#pragma unroll
    for (int it = 0; it < 2; ++it) {
        const int idx = tid + it * 256;
        const int r = idx >> 4, cs = idx & 15;
        const float4 v = *(const float4*)(in + zo + (long)(r0 + r) * Cc + c0 + cs * 4);
        t[r][cs * 4 + 0] = v.x; t[r][cs * 4 + 1] = v.y;
        t[r][cs * 4 + 2] = v.z; t[r][cs * 4 + 3] = v.w;
    }
    __syncthreads();
    const int c = tid >> 2, rs = tid & 3;
    __align__(16) __half hh[8];
#pragma unroll
    for (int j = 0; j < 8; ++j) hh[j] = __float2half_rn(t[rs * 8 + j][c]);
    *(uint4*)&oh[zo + (long)(c0 + c) * R + r0 + rs * 8] = *(uint4*)hh;
}

// fp32 -> fp16 rounded (same layout)
__global__ void pround_k(const float* __restrict__ in, __half* __restrict__ oh, long n4)
{
    for (long i = blockIdx.x * blockDim.x + threadIdx.x; i < n4; i += (long)gridDim.x * blockDim.x) {
        float4 v = ((const float4*)in)[i];
        __half hh[4] = { __float2half_rn(v.x), __float2half_rn(v.y),
                         __float2half_rn(v.z), __float2half_rn(v.w) };
        ((uint2*)oh)[i] = *(uint2*)hh;
    }
}

// fp16 [Z][R][C] -> [Z][C][R], 32x64 tiles, 16B transactions
__global__ __launch_bounds__(256)
void tb16_k(const __half* __restrict__ in, __half* __restrict__ out, int R, int Cc)
{
    __shared__ __half t[32][72];
    const long zo = (long)blockIdx.z * R * Cc;
    const int c0 = blockIdx.x * 64, r0 = blockIdx.y * 32;
    const int tid = threadIdx.x;
    {
        const int r = tid >> 3, cs = tid & 7;
        __align__(16) __half v[8];
        *(uint4*)v = *(const uint4*)(in + zo + (long)(r0 + r) * Cc + c0 + cs * 8);
#pragma unroll
        for (int j = 0; j < 8; ++j) t[r][cs * 8 + j] = v[j];
    }
    __syncthreads();
    const int c = tid >> 2, rs = tid & 3;
    __align__(16) __half o8[8];
#pragma unroll
    for (int j = 0; j < 8; ++j) o8[j] = t[rs * 8 + j][c];
    *(uint4*)&out[zo + (long)(c0 + c) * R + r0 + rs * 8] = *(uint4*)o8;
}

// input LayerNorms -> rounded fp16 outputs (224 thr: 448 float4 = 1792 elems)
__global__ __launch_bounds__(224)
void ln_in_kernel(const float* __restrict__ e1, const float* __restrict__ e2,
                  const float* __restrict__ e3,
                  const float* __restrict__ ag, const float* __restrict__ ab,
                  const float* __restrict__ g1, const float* __restrict__ b1,
                  __half* __restrict__ Yh, __half* __restrict__ Xh)
{
    const long row = blockIdx.x;
    const int  tid = threadIdx.x;
    const float4* p1 = (const float4*)(e1 + row * C1d);
    const float4* p2 = (const float4*)(e2 + row * C2d);
    const float4* p3 = (const float4*)(e3 + row * C3d);
    __shared__ float sh[16];

    const int f0 = tid, f1 = tid + 224;
    const bool isX = (f0 >= 64) && (f0 < 192);
    float4 a = (f0 < 64) ? p1[f0] : (isX ? p2[f0 - 64] : p3[f0 - 192]);
    float4 b = p3[f1 - 192];

    float s = a.x + a.y + a.z + a.w + b.x + b.y + b.z + b.w;
    float q = a.x * a.x + a.y * a.y + a.z * a.z + a.w * a.w
            + b.x * b.x + b.y * b.y + b.z * b.z + b.w * b.w;
    float2 r = bred2(s, q, sh, tid, 7);
    float mean = r.x * (1.f / KVd);
    float inv  = rsqrtf(r.y * (1.f / KVd) - mean * mean + 1e-6f);

    const float4* g4 = (const float4*)ag;
    const float4* b4 = (const float4*)ab;
    {
        const float4 ga = g4[f0], ba = b4[f0];
        __half hh[4];
        hh[0] = __float2half_rn((a.x - mean) * inv * ga.x + ba.x);
        hh[1] = __float2half_rn((a.y - mean) * inv * ga.y + ba.y);
        hh[2] = __float2half_rn((a.z - mean) * inv * ga.z + ba.z);
        hh[3] = __float2half_rn((a.w - mean) * inv * ga.w + ba.w);
        *(uint2*)&Yh[row * KVd + f0 * 4] = *(uint2*)hh;
        const float4 gb = g4[f1], bb = b4[f1];
        hh[0] = __float2half_rn((b.x - mean) * inv * gb.x + bb.x);
        hh[1] = __float2half_rn((b.y - mean) * inv * gb.y + bb.y);
        hh[2] = __float2half_rn((b.z - mean) * inv * gb.z + bb.z);
        hh[3] = __float2half_rn((b.w - mean) * inv * gb.w + bb.w);
        *(uint2*)&Yh[row * KVd + f1 * 4] = *(uint2*)hh;
    }

    // X = LN(emb2): chunk0 of threads 64..191 covers e2 exactly
    float sX = isX ? (a.x + a.y + a.z + a.w) : 0.f;
    float qX = isX ? (a.x * a.x + a.y * a.y + a.z * a.z + a.w * a.w) : 0.f;
    float2 rX = bred2(sX, qX, sh, tid, 7);
    if (isX) {
        float meanX = rX.x * (1.f / C2d);
        float invX  = rsqrtf(rX.y * (1.f / C2d) - meanX * meanX + 1e-6f);
        const int fx = f0 - 64;
        const float4 gx = ((const float4*)g1)[fx], bx = ((const float4*)b1)[fx];
        __half hh[4];
        hh[0] = __float2half_rn((a.x - meanX) * invX * gx.x + bx.x);
        hh[1] = __float2half_rn((a.y - meanX) * invX * gx.y + bx.y);
        hh[2] = __float2half_rn((a.z - meanX) * invX * gx.z + bx.z);
        hh[3] = __float2half_rn((a.w - meanX) * invX * gx.w + bx.w);
        *(uint2*)&Xh[row * C2d + fx * 4] = *(uint2*)hh;
    }
}

__global__ __launch_bounds__(128)
void ln2_kernel(const float* __restrict__ in,
                const float* __restrict__ g, const float* __restrict__ b,
                __half* __restrict__ Zh)
{
    const long row = blockIdx.x;
    const int  tid = threadIdx.x;
    __shared__ float sh[8];
    const float4 v = ((const float4*)(in + row * C2d))[tid];
    float s = v.x + v.y + v.z + v.w;
    float q = v.x * v.x + v.y * v.y + v.z * v.z + v.w * v.w;
    float2 r = bred2(s, q, sh, tid, 4);
    float mean = r.x * (1.f / C2d);
    float inv  = rsqrtf(r.y * (1.f / C2d) - mean * mean + 1e-6f);
    const float4 gg = ((const float4*)g)[tid], bb = ((const float4*)b)[tid];
    __half hh[4];
    hh[0] = __float2half_rn((v.x - mean) * inv * gg.x + bb.x);
    hh[1] = __float2half_rn((v.y - mean) * inv * gg.y + bb.y);
    hh[2] = __float2half_rn((v.z - mean) * inv * gg.z + bb.z);
    hh[3] = __float2half_rn((v.w - mean) * inv * gg.w + bb.w);
    *(uint2*)&Zh[row * C2d + tid * 4] = *(uint2*)hh;
}

// stage 1: 32 partial blocks per (b,h) map -> g_part
__global__ __launch_bounds__(256)
void stats1_kernel(const float* __restrict__ S, float* __restrict__ part)
{
    const int z = blockIdx.x >> 5, seg = blockIdx.x & 31;
    const int tid = threadIdx.x;
    const float4* p = (const float4*)(S + (long)z * C2d * KVd) + seg * 7168;
    float s = 0.f, q = 0.f;
#pragma unroll 4
    for (int i = tid; i < 7168; i += 256) {
        float4 v = p[i];
        s += v.x + v.y + v.z + v.w;
        q += v.x * v.x + v.y * v.y + v.z * v.z + v.w * v.w;
    }
    __shared__ float sh[16];
    float2 r = bred2(s, q, sh, tid, 8);
    if (tid == 0) { part[blockIdx.x * 2] = r.x; part[blockIdx.x * 2 + 1] = r.y; }
}

// stage 2: finish per-map variance -> softmax scale
__global__ __launch_bounds__(32)
void stats2_kernel(const float* __restrict__ part, float* __restrict__ scale)
{
    const int z = blockIdx.x, lane = threadIdx.x;
    float s = part[(z * 32 + lane) * 2];
    float q = part[(z * 32 + lane) * 2 + 1];
#pragma unroll
    for (int o = 16; o; o >>= 1) {
        s += __shfl_xor_sync(0xffffffffu, s, o);
        q += __shfl_xor_sync(0xffffffffu, q, o);
    }
    if (lane == 0) {
        const float cnt = (float)(C2d * KVd);
        float mean = s / cnt;
        float var  = q / cnt - mean * mean;
        float a    = rsqrtf((float)KVd);
        scale[z]   = a * rsqrtf(a * a * var + 1e-5f);
    }
}

__global__ __launch_bounds__(224)
void softmax_kernel(const float* __restrict__ S, const float* __restrict__ scale,
                    __half* __restrict__ Ph)
{
    const long row = blockIdx.x;
    const int  tid = threadIdx.x;
    const float4* p = (const float4*)(S + row * KVd);
    const float sc = scale[blockIdx.x >> 9];
    __shared__ float sh[16];

    float4 v0 = p[tid], v1 = p[tid + 224];
    float mx = fmaxf(fmaxf(fmaxf(v0.x, v0.y), fmaxf(v0.z, v0.w)),
                     fmaxf(fmaxf(v1.x, v1.y), fmaxf(v1.z, v1.w)));
    mx = bmax(mx, sh, tid, 7);

    float e0[4] = { __expf((v0.x - mx) * sc), __expf((v0.y - mx) * sc),
                    __expf((v0.z - mx) * sc), __expf((v0.w - mx) * sc) };
    float e1[4] = { __expf((v1.x - mx) * sc), __expf((v1.y - mx) * sc),
                    __expf((v1.z - mx) * sc), __expf((v1.w - mx) * sc) };
    float s = e0[0] + e0[1] + e0[2] + e0[3] + e1[0] + e1[1] + e1[2] + e1[3];
    float2 r = bred2(s, 0.f, sh, tid, 7);
    const float inv = 1.f / r.x;

    __half hh[4];
#pragma unroll
    for (int j = 0; j < 4; ++j) hh[j] = __float2half_rn(e0[j] * inv);
    *(uint2*)&Ph[row * KVd + tid * 4] = *(uint2*)hh;
#pragma unroll
    for (int j = 0; j < 4; ++j) hh[j] = __float2half_rn(e1[j] * inv);
    *(uint2*)&Ph[row * KVd + (tid + 224) * 4] = *(uint2*)hh;
}

// ===================== launcher =============================================
#define SYM(v, t, s) t* v; { void* _p; cudaGetSymbolAddress(&_p, s); v = (t*)_p; }

extern "C" void kernel_launch(void* const* d_in, const int* in_sizes, int n_in,
                              void* d_out, int out_size)
{
    const float* emb1    = (const float*)d_in[0];
    const float* emb2    = (const float*)d_in[1];
    const float* emb3    = (const float*)d_in[2];
    const float* Wq      = (const float*)d_in[3];
    const float* Wk      = (const float*)d_in[4];
    const float* Wv      = (const float*)d_in[5];
    const float* Wout    = (const float*)d_in[6];
    const float* ln1_g   = (const float*)d_in[7];
    const float* ln1_b   = (const float*)d_in[8];
    const float* lnall_g = (const float*)d_in[9];
    const float* lnall_b = (const float*)d_in[10];
    const float* lnffn_g = (const float*)d_in[11];
    const float* lnffn_b = (const float*)d_in[12];
    const float* fc1_w   = (const float*)d_in[13];
    const float* fc1_b   = (const float*)d_in[14];
    const float* fc2_w   = (const float*)d_in[15];
    const float* fc2_b   = (const float*)d_in[16];
    float* out = (float*)d_out;

    SYM(Yh, __half, g_Yh)   SYM(Yth, __half, g_Yth)
    SYM(Xh, __half, g_Xh)   SYM(Xth, __half, g_Xth)
    SYM(Gth, __half, g_Gth) SYM(Gtl, __half, g_Gtl)
    SYM(T1h, __half, g_T1h)
    SYM(S, float, g_S)
    SYM(Ph, __half, g_Ph)
    SYM(Mth, __half, g_Mth)
    SYM(Ch, __half, g_Ch)
    SYM(cx2, float, g_cx2)
    SYM(Zh, __half, g_Zh)
    SYM(Fh, __half, g_Fh)
    SYM(WqTh, __half, g_WqTh)
    SYM(WkTh, __half, g_WkTh)
    SYM(Wvh, __half, g_Wvh)
    SYM(WoTh, __half, g_WoTh)
    SYM(f1Th, __half, g_f1Th)
    SYM(f2Th, __half, g_f2Th)
    SYM(scl, float, g_sc)     SYM(part, float, g_part)

    const int SM1 = 2 * 2 * (128 * (2 * 128 + 16));   // 139264 B, 1-pass
    const int SM2 = 2 * 3 * (128 * (2 * 128 + 16));   // 208896 B, B-split 2-pass
    cudaFuncSetAttribute(mma_gemm<128, 0, 0, 0>, cudaFuncAttributeMaxDynamicSharedMemorySize, SM1);
    cudaFuncSetAttribute(mma_gemm<128, 0, 0, 1>, cudaFuncAttributeMaxDynamicSharedMemorySize, SM1);
    cudaFuncSetAttribute(mma_gemm<128, 0, 0, 2>, cudaFuncAttributeMaxDynamicSharedMemorySize, SM1);
    cudaFuncSetAttribute(mma_gemm<128, 1, 0, 2>, cudaFuncAttributeMaxDynamicSharedMemorySize, SM2);
    cudaFuncSetAttribute(mma_gemm<128, 0, 1, 0>, cudaFuncAttributeMaxDynamicSharedMemorySize, SM1);
    cudaFuncSetAttribute(mma_gemm<128, 0, 2, 2>, cudaFuncAttributeMaxDynamicSharedMemorySize, SM1);
    cudaFuncSetAttribute(mma_gemm<128, 0, 3, 0>, cudaFuncAttributeMaxDynamicSharedMemorySize, SM1);

    // weight prep: transpose+round / round (hi only)
    tround_k<<<dim3(C2d / 64, C2d / 32, NHd), 256>>>(Wq, WqTh, C2d, C2d);
    tround_k<<<dim3(KVd / 64, KVd / 32, NHd), 256>>>(Wk, WkTh, KVd, KVd);
    tround_k<<<dim3(C2d / 64, C2d / 32, 1), 256>>>(Wout, WoTh, C2d, C2d);
    tround_k<<<dim3(C2E / 64, C2d / 32, 1), 256>>>(fc1_w, f1Th, C2d, C2E);
    tround_k<<<dim3(C2d / 64, C2E / 32, 1), 256>>>(fc2_w, f2Th, C2E, C2d);
    pround_k<<<4096, 256>>>(Wv, Wvh, (long)NHd * KVd * KVd / 4);

    // 1. input LayerNorms
    ln_in_kernel<<<BB * NT, 224>>>(emb1, emb2, emb3, lnall_g, lnall_b, ln1_g, ln1_b,
                                   Yh, Xh);
    // transposes for step 2
    tb16_k<<<dim3(KVd / 64, NT / 32, BB), 256>>>(Yh, Yth, NT, KVd);
    tb16_k<<<dim3(C2d / 64, NT / 32, BB), 256>>>(Xh, Xth, NT, C2d);

    // 2. Gt_b = Yt_b Xt_b^T  [1792,512], K=1024 (split out: Gt has corr spikes)
    mma_gemm<128, 0, 0, 1><<<dim3(C2d / 128, KVd / 128, BB), 256, SM1>>>(
        Yth, Xth, nullptr, nullptr, Gth, Gtl, nullptr, nullptr,
        KVd, C2d, NT, NT, NT,
        (long)KVd * NT, (long)C2d * NT, (long)KVd * C2d, 0, 0, 1, 0, 0, 1.f);

    // 3. T1[b,h] = WqT_h Gt_b^T  [512,1792], K=512  (B-split 2-pass)
    mma_gemm<128, 1, 0, 2><<<dim3(KVd / 128, C2d / 128, BB * NHd), 256, SM2>>>(
        WqTh, Gth, Gtl, nullptr, T1h, nullptr, nullptr, nullptr,
        C2d, KVd, C2d, C2d, C2d,
        (long)C2d * C2d, (long)KVd * C2d, (long)C2d * KVd, 1, 2, 1, 0, 0, 1.f);

    // 4. S[b,h] = T1 WkT_h^T  [512,1792], K=1792 (fp32 out)
    mma_gemm<128, 0, 0, 0><<<dim3(KVd / 128, C2d / 128, BB * NHd), 256, SM1>>>(
        T1h, WkTh, nullptr, S, nullptr, nullptr, nullptr, nullptr,
        C2d, KVd, KVd, KVd, KVd,
        (long)C2d * KVd, (long)KVd * KVd, (long)C2d * KVd, 0, 1, 1, 0, 0, 1.f);

    // 5-6. instance-norm stats (two-stage) + row softmax
    stats1_kernel<<<BB * NHd * 32, 256>>>(S, part);
    stats2_kernel<<<BB * NHd, 32>>>(part, scl);
    softmax_kernel<<<BB * NHd * C2d, 224>>>(S, scl, Ph);

    // 7. Mmt_b[c,e] = (1/H) sum_h sum_k P[b,h,c,k] Wv_h[e,k]  [512,1792]
    mma_gemm<128, 0, 0, 2><<<dim3(KVd / 128, C2d / 128, BB), 256, SM1>>>(
        Ph, Wvh, nullptr, nullptr, Mth, nullptr, nullptr, nullptr,
        C2d, KVd, KVd, KVd, KVd,
        (long)NHd * C2d * KVd, 0, (long)C2d * KVd, 0, 0,
        NHd, (long)C2d * KVd, (long)KVd * KVd, 1.f / NHd);

    // 8. ctx_b = Y_b Mmt_b^T  [1024,512], K=1792
    mma_gemm<128, 0, 0, 2><<<dim3(C2d / 128, NT / 128, BB), 256, SM1>>>(
        Yh, Mth, nullptr, nullptr, Ch, nullptr, nullptr, nullptr,
        NT, C2d, KVd, KVd, KVd,
        (long)NT * KVd, (long)C2d * KVd, (long)NT * C2d, 0, 0, 1, 0, 0, 1.f);

    // 9. cx2 = ctx WoutT^T + emb2  [8192,512]
    mma_gemm<128, 0, 1, 0><<<dim3(C2d / 128, BB * NT / 128, 1), 256, SM1>>>(
        Ch, WoTh, nullptr, cx2, nullptr, nullptr, nullptr, emb2,
        BB * NT, C2d, C2d, C2d, C2d, 0, 0, 0, 0, 0, 1, 0, 0, 1.f);

    // 10. Z = LN(cx2)
    ln2_kernel<<<BB * NT, 128>>>(cx2, lnffn_g, lnffn_b, Zh);

    // 11. F = gelu(Z f1T^T + b1)  [8192,2048]
    mma_gemm<128, 0, 2, 2><<<dim3(C2E / 128, BB * NT / 128, 1), 256, SM1>>>(
        Zh, f1Th, nullptr, nullptr, Fh, nullptr, fc1_b, nullptr,
        BB * NT, C2E, C2d, C2d, C2d, 0, 0, 0, 0, 0, 1, 0, 0, 1.f);

    // 12. out = F f2T^T + b2 + cx2  [8192,512]
    mma_gemm<128, 0, 3, 0><<<dim3(C2d / 128, BB * NT / 128, 1), 256, SM1>>>(
        Fh, f2Th, nullptr, out, nullptr, nullptr, fc2_b, cx2,
        BB * NT, C2d, C2E, C2E, C2E, 0, 0, 0, 0, 0, 1, 0, 0, 1.f);
}

// round 12
// speedup vs baseline: 5.0030x; 1.0080x over previous
#include <cuda_runtime.h>
#include <cuda_fp16.h>
#include <math.h>
#include <stdint.h>

// Problem constants
#define BB   8
#define NT   1024
#define C1d  256
#define C2d  512
#define C3d  1024
#define KVd  1792
#define NHd  4
#define C2E  2048

// ===================== scratch (device statics) ==============================
__device__ __half g_Yh [BB*NT*KVd];                       // LN(concat)  [b][n][kv]
__device__ __half g_Yth[BB*NT*KVd];                       // transposed  [b][kv][n]
__device__ __half g_Xh [BB*NT*C2d];                       // LN(emb2)    [b][n][c]
__device__ __half g_Xth[BB*NT*C2d];                       // transposed  [b][c][n]
__device__ __half g_Gth[BB*KVd*C2d], g_Gtl[BB*KVd*C2d];   // Gt split (spiky!)
__device__ __half g_T1h[BB*NHd*C2d*KVd];
__device__ __half g_Sh [BB*NHd*C2d*KVd];                  // scores fp16
__device__ __half g_Ph [BB*NHd*C2d*KVd];                  // probs
__device__ __half g_Mth[BB*C2d*KVd];                      // Mmt [b][c][e]
__device__ __half g_Ch [BB*NT*C2d];                       // ctx
__device__ float  g_cx2[BB*NT*C2d];                       // residual fp32
__device__ __half g_Zh [BB*NT*C2d];                       // LN(cx2)
__device__ __half g_Fh [BB*NT*C2E];                       // gelu(fc1)
// weights (pre-transposed + rounded to fp16)
__device__ __half g_WqTh[NHd*C2d*C2d];
__device__ __half g_WkTh[NHd*KVd*KVd];
__device__ __half g_Wvh [NHd*KVd*KVd];
__device__ __half g_WoTh[C2d*C2d];
__device__ __half g_f1Th[C2E*C2d];
__device__ __half g_f2Th[C2d*C2E];
__device__ float g_sc[BB*NHd];
__device__ float g_part[BB*NHd*56*2];

// ===================== PTX helpers (baseline sm_80+ only) ====================
__device__ __forceinline__ uint32_t smem_u32(const void* p) {
    uint32_t a;
    asm("{ .reg .u64 t; cvta.to.shared.u64 t, %1; cvt.u32.u64 %0, t; }" : "=r"(a) : "l"(p));
    return a;
}
#define CPA16(d, s)   asm volatile("cp.async.cg.shared.global [%0], [%1], 16;" :: "r"(d), "l"(s))
#define CPA_COMMIT()  asm volatile("cp.async.commit_group;" ::: "memory")
#define CPA_WAIT1()   asm volatile("cp.async.wait_group 1;" ::: "memory")
#define CPA_WAIT0()   asm volatile("cp.async.wait_group 0;" ::: "memory")

#define LDSM4(r, a) \
    asm volatile("ldmatrix.sync.aligned.m8n8.x4.shared.b16 {%0,%1,%2,%3}, [%4];" \
        : "=r"((r)[0]), "=r"((r)[1]), "=r"((r)[2]), "=r"((r)[3]) : "r"(a))

#define MMA16816(C, A, B0, B1) \
    asm volatile("mma.sync.aligned.m16n8k16.row.col.f32.f16.f16.f32 " \
        "{%0,%1,%2,%3}, {%4,%5,%6,%7}, {%8,%9}, {%0,%1,%2,%3};" \
        : "+f"((C)[0]), "+f"((C)[1]), "+f"((C)[2]), "+f"((C)[3]) \
        : "r"((A)[0]), "r"((A)[1]), "r"((A)[2]), "r"((A)[3]), "r"(B0), "r"(B1))

__device__ __forceinline__ void splt(float v, __half& h, __half& l) {
    h = __float2half_rn(v);
    l = __float2half_rn(v - __half2float(h));
}
__device__ __forceinline__ int selidx(int mode, int z) {
    return mode == 0 ? z : (mode == 1 ? (z & 3) : (z >> 2));
}

// block reductions (warp shuffle + tiny smem); fixed order -> deterministic
__device__ __forceinline__ float2 bred2(float s, float q, float* sh, int tid, int nw) {
#pragma unroll
    for (int o = 16; o; o >>= 1) {
        s += __shfl_xor_sync(0xffffffffu, s, o);
        q += __shfl_xor_sync(0xffffffffu, q, o);
    }
    if ((tid & 31) == 0) { sh[(tid >> 5) * 2] = s; sh[(tid >> 5) * 2 + 1] = q; }
    __syncthreads();
    float rs = 0.f, rq = 0.f;
    for (int j = 0; j < nw; ++j) { rs += sh[j * 2]; rq += sh[j * 2 + 1]; }
    __syncthreads();
    return make_float2(rs, rq);
}
__device__ __forceinline__ float bmax(float v, float* sh, int tid, int nw) {
#pragma unroll
    for (int o = 16; o; o >>= 1) v = fmaxf(v, __shfl_xor_sync(0xffffffffu, v, o));
    if ((tid & 31) == 0) sh[tid >> 5] = v;
    __syncthreads();
    float r = sh[0];
    for (int j = 1; j < nw; ++j) r = fmaxf(r, sh[j]);
    __syncthreads();
    return r;
}

// ===================== mma.sync fp16 GEMM ====================================
// C[M,Nn] = outScale * sum_h A_h[M,K] * B_h[N,K]^T  (+ epilogue)
// MODE: 0 -> 1-pass (A,B fp16-rounded);  1 -> 2-pass B-split (A*Bh + A*Bl)
// EPI: 0 none, 1 +add, 2 +bias,gelu, 3 +bias+add.
// OUT: 0 fp32, 1 fp16 hi+lo, 2 fp16 rounded
// STATS: 1 -> per-CTA sum/sumsq of outputs -> C (as partials buffer)
// BKE elems per chunk; smem row stride 2*BKE+16 B -> mod 128 = 16, conflict-free
// ldmatrix cycling across 8-row groups.
template<int BKE, int MODE, int EPI, int OUT, int STATS>
__global__ __launch_bounds__(256)
void mma_gemm(const __half* __restrict__ Ahi,
              const __half* __restrict__ Bhi, const __half* __restrict__ Blo,
              float* __restrict__ C, __half* __restrict__ Chi, __half* __restrict__ Clo,
              const float* __restrict__ bias, const float* __restrict__ addp,
              int M, int Nn, int K, int lda, int ldb,
              long sA, long sB, long sC, int selA, int selB,
              int nH, long hA, long hB, float outScale)
{
    constexpr int PADB  = 2 * BKE + 16;
    constexpr int TILEB = 128 * PADB;
    constexpr int NTL   = 2 + MODE;                    // A, Bh[, Bl]
    constexpr uint32_t STB = NTL * TILEB;              // stage bytes
    constexpr int SEGS  = BKE / 8;                     // 16B segments per row
    constexpr int RSTEP = 256 / SEGS;
    constexpr int ITERS = 128 / RSTEP;
    constexpr int KSN   = BKE / 16;

    extern __shared__ char smem[];
    const uint32_t sb = smem_u32(smem);
    const int tid = threadIdx.x, wid = tid >> 5, lane = tid & 31;
    const int z = blockIdx.z;
    const int m0 = blockIdx.y * 128, n0 = blockIdx.x * 128;
    const int warpM = (wid & 3) * 32, warpN = (wid >> 2) * 64;

    const __half* A0h = Ahi + (long)selidx(selA, z) * sA;
    const __half* B0h = Bhi + (long)selidx(selB, z) * sB;
    const __half* B0l = (MODE == 1) ? (Blo + (long)selidx(selB, z) * sB) : nullptr;

    const int nchK = K / BKE;
    const int nch  = nH * nchK;

    const int srow = tid / SEGS;
    const int sseg = tid % SEGS;

    auto issue = [&](int ch) {
        const uint32_t so = sb + (uint32_t)(ch & 1) * STB;
        const int h  = ch / nchK;
        const int k0 = (ch - h * nchK) * BKE;
        const __half* srcs[3] = { A0h + (long)h * hA, B0h + (long)h * hB,
                                  (MODE == 1) ? (B0l + (long)h * hB) : nullptr };
#pragma unroll
        for (int t4 = 0; t4 < NTL; ++t4) {
            const int ld = (t4 == 0) ? lda : ldb;
            const int rb = (t4 == 0) ? m0  : n0;
            const __half* gb = srcs[t4] + (long)(rb + srow) * ld + k0 + sseg * 8;
            const uint32_t tb = so + t4 * TILEB + srow * PADB + sseg * 16;
#pragma unroll
            for (int j = 0; j < ITERS; ++j)
                CPA16(tb + j * RSTEP * PADB, gb + (long)(j * RSTEP) * ld);
        }
        CPA_COMMIT();
    };

    float acc[2][8][4];
#pragma unroll
    for (int i = 0; i < 2; ++i)
#pragma unroll
        for (int j = 0; j < 8; ++j)
#pragma unroll
            for (int k = 0; k < 4; ++k) acc[i][j][k] = 0.f;

    issue(0);
    issue(1);

    const uint32_t aRow = (uint32_t)(warpM + (lane & 15)) * PADB + ((lane >> 4) << 4);
    const uint32_t bRow = (uint32_t)(warpN + ((lane >> 4) << 3) + (lane & 7)) * PADB
                        + (((lane >> 3) & 1) << 4);

    for (int ch = 0; ch < nch; ++ch) {
        if (ch < nch - 1) { CPA_WAIT1(); } else { CPA_WAIT0(); }
        __syncthreads();
        const uint32_t so = sb + (uint32_t)(ch & 1) * STB;
#pragma unroll
        for (int ks = 0; ks < KSN; ++ks) {
            const uint32_t kb = ks * 32;
            uint32_t ah[2][4], bh[4][4], bl[4][4];
#pragma unroll
            for (int mf = 0; mf < 2; ++mf)
                LDSM4(ah[mf], so + aRow + (uint32_t)(mf * 16 * PADB) + kb);
#pragma unroll
            for (int q = 0; q < 4; ++q) {
                const uint32_t bd = so + TILEB + bRow + (uint32_t)(q * 16 * PADB) + kb;
                LDSM4(bh[q], bd);
                if (MODE == 1) LDSM4(bl[q], bd + TILEB);
            }
#pragma unroll
            for (int mf = 0; mf < 2; ++mf)
#pragma unroll
                for (int nf = 0; nf < 8; ++nf) {
                    MMA16816(acc[mf][nf], ah[mf],
                             bh[nf >> 1][(nf & 1) * 2], bh[nf >> 1][(nf & 1) * 2 + 1]);
                    if (MODE == 1)
                        MMA16816(acc[mf][nf], ah[mf],
                                 bl[nf >> 1][(nf & 1) * 2], bl[nf >> 1][(nf & 1) * 2 + 1]);
                }
        }
        __syncthreads();
        if (ch + 2 < nch) issue(ch + 2);
    }

    // ---- epilogue (register accumulators -> gmem)
    const int rbase = m0 + warpM + (lane >> 2);
    const int cbase = n0 + warpN + (lane & 3) * 2;
    float ssum = 0.f, ssq = 0.f;
#pragma unroll
    for (int mf = 0; mf < 2; ++mf) {
#pragma unroll
        for (int h2 = 0; h2 < 2; ++h2) {
            const long m = rbase + mf * 16 + h2 * 8;
#pragma unroll
            for (int nf = 0; nf < 8; ++nf) {
                const long col = cbase + nf * 8;
                float v0 = acc[mf][nf][h2 * 2]     * outScale;
                float v1 = acc[mf][nf][h2 * 2 + 1] * outScale;
                if (EPI == 1) {
                    const float2 ad = *(const float2*)(addp + m * Nn + col);
                    v0 += ad.x; v1 += ad.y;
                }
                if (EPI == 2) {
                    v0 += bias[col]; v1 += bias[col + 1];
                    v0 = 0.5f * v0 * (1.f + erff(v0 * 0.70710678118654752f));
                    v1 = 0.5f * v1 * (1.f + erff(v1 * 0.70710678118654752f));
                }
                if (EPI == 3) {
                    const float2 ad = *(const float2*)(addp + m * Nn + col);
                    v0 += bias[col]     + ad.x;
                    v1 += bias[col + 1] + ad.y;
                }
                if (STATS) { ssum += v0 + v1; ssq += v0 * v0 + v1 * v1; }
                const long idx = (long)z * sC + m * Nn + col;
                if (OUT == 0) {
                    *(float2*)(C + idx) = make_float2(v0, v1);
                } else if (OUT == 1) {
                    __half h0, l0, h1, l1;
                    splt(v0, h0, l0); splt(v1, h1, l1);
                    *(__half2*)(Chi + idx) = __halves2half2(h0, h1);
                    *(__half2*)(Clo + idx) = __halves2half2(l0, l1);
                } else {
                    *(__half2*)(Chi + idx) =
                        __halves2half2(__float2half_rn(v0), __float2half_rn(v1));
                }
            }
        }
    }
    if (STATS) {
        __shared__ float sred[16];
        float s = ssum, q = ssq;
#pragma unroll
        for (int o = 16; o; o >>= 1) {
            s += __shfl_xor_sync(0xffffffffu, s, o);
            q += __shfl_xor_sync(0xffffffffu, q, o);
        }
        if (lane == 0) { sred[wid * 2] = s; sred[wid * 2 + 1] = q; }
        __syncthreads();
        if (tid == 0) {
            float rs = 0.f, rq = 0.f;
#pragma unroll
            for (int j = 0; j < 8; ++j) { rs += sred[j * 2]; rq += sred[j * 2 + 1]; }
            const long t = (long)z * 56 + blockIdx.y * gridDim.x + blockIdx.x;
            C[t * 2] = rs; C[t * 2 + 1] = rq;
        }
    }
}

// ===================== prep kernels (vectorized) =============================
// fp32 [Z][R][C] -> fp16 [Z][C][R] (rounded), 32x64 tiles, 16B transactions
__global__ __launch_bounds__(256)
void tround_k(const float* __restrict__ in, __half* __restrict__ oh, int R, int Cc)
{
    __shared__ float t[32][65];
    const long zo = (long)blockIdx.z * R * Cc;
    const int c0 = blockIdx.x * 64, r0 = blockIdx.y * 32;
    const int tid = threadIdx.x;
#pragma unroll
    for (int it = 0; it < 2; ++it) {
        const int idx = tid + it * 256;
        const int r = idx >> 4, cs = idx & 15;
        const float4 v = *(const float4*)(in + zo + (long)(r0 + r) * Cc + c0 + cs * 4);
        t[r][cs * 4 + 0] = v.x; t[r][cs * 4 + 1] = v.y;
        t[r][cs * 4 + 2] = v.z; t[r][cs * 4 + 3] = v.w;
    }
    __syncthreads();
    const int c = tid >> 2, rs = tid & 3;
    __align__(16) __half hh[8];
#pragma unroll
    for (int j = 0; j < 8; ++j) hh[j] = __float2half_rn(t[rs * 8 + j][c]);
    *(uint4*)&oh[zo + (long)(c0 + c) * R + r0 + rs * 8] = *(uint4*)hh;
}

// fp32 -> fp16 rounded (same layout)
__global__ void pround_k(const float* __restrict__ in, __half* __restrict__ oh, long n4)
{
    for (long i = blockIdx.x * blockDim.x + threadIdx.x; i < n4; i += (long)gridDim.x * blockDim.x) {
        float4 v = ((const float4*)in)[i];
        __half hh[4] = { __float2half_rn(v.x), __float2half_rn(v.y),
                         __float2half_rn(v.z), __float2half_rn(v.w) };
        ((uint2*)oh)[i] = *(uint2*)hh;
    }
}

// fp16 [Z][R][C] -> [Z][C][R], 32x64 tiles, 16B transactions
__global__ __launch_bounds__(256)
void tb16_k(const __half* __restrict__ in, __half* __restrict__ out, int R, int Cc)
{
    __shared__ __half t[32][72];
    const long zo = (long)blockIdx.z * R * Cc;
    const int c0 = blockIdx.x * 64, r0 = blockIdx.y * 32;
    const int tid = threadIdx.x;
    {
        const int r = tid >> 3, cs = tid & 7;
        __align__(16) __half v[8];
        *(uint4*)v = *(const uint4*)(in + zo + (long)(r0 + r) * Cc + c0 + cs * 8);
#pragma unroll
        for (int j = 0; j < 8; ++j) t[r][cs * 8 + j] = v[j];
    }
    __syncthreads();
    const int c = tid >> 2, rs = tid & 3;
    __align__(16) __half o8[8];
#pragma unroll
    for (int j = 0; j < 8; ++j) o8[j] = t[rs * 8 + j][c];
    *(uint4*)&out[zo + (long)(c0 + c) * R + r0 + rs * 8] = *(uint4*)o8;
}

// input LayerNorms -> rounded fp16 outputs (224 thr: 448 float4 = 1792 elems)
__global__ __launch_bounds__(224)
void ln_in_kernel(const float* __restrict__ e1, const float* __restrict__ e2,
                  const float* __restrict__ e3,
                  const float* __restrict__ ag, const float* __restrict__ ab,
                  const float* __restrict__ g1, const float* __restrict__ b1,
                  __half* __restrict__ Yh, __half* __restrict__ Xh)
{
    const long row = blockIdx.x;
    const int  tid = threadIdx.x;
    const float4* p1 = (const float4*)(e1 + row * C1d);
    const float4* p2 = (const float4*)(e2 + row * C2d);
    const float4* p3 = (const float4*)(e3 + row * C3d);
    __shared__ float sh[16];

    const int f0 = tid, f1 = tid + 224;
    const bool isX = (f0 >= 64) && (f0 < 192);
    float4 a = (f0 < 64) ? p1[f0] : (isX ? p2[f0 - 64] : p3[f0 - 192]);
    float4 b = p3[f1 - 192];

    float s = a.x + a.y + a.z + a.w + b.x + b.y + b.z + b.w;
    float q = a.x * a.x + a.y * a.y + a.z * a.z + a.w * a.w
            + b.x * b.x + b.y * b.y + b.z * b.z + b.w * b.w;
    float2 r = bred2(s, q, sh, tid, 7);
    float mean = r.x * (1.f / KVd);
    float inv  = rsqrtf(r.y * (1.f / KVd) - mean * mean + 1e-6f);

    const float4* g4 = (const float4*)ag;
    const float4* b4 = (const float4*)ab;
    {
        const float4 ga = g4[f0], ba = b4[f0];
        __half hh[4];
        hh[0] = __float2half_rn((a.x - mean) * inv * ga.x + ba.x);
        hh[1] = __float2half_rn((a.y - mean) * inv * ga.y + ba.y);
        hh[2] = __float2half_rn((a.z - mean) * inv * ga.z + ba.z);
        hh[3] = __float2half_rn((a.w - mean) * inv * ga.w + ba.w);
        *(uint2*)&Yh[row * KVd + f0 * 4] = *(uint2*)hh;
        const float4 gb = g4[f1], bb = b4[f1];
        hh[0] = __float2half_rn((b.x - mean) * inv * gb.x + bb.x);
        hh[1] = __float2half_rn((b.y - mean) * inv * gb.y + bb.y);
        hh[2] = __float2half_rn((b.z - mean) * inv * gb.z + bb.z);
        hh[3] = __float2half_rn((b.w - mean) * inv * gb.w + bb.w);
        *(uint2*)&Yh[row * KVd + f1 * 4] = *(uint2*)hh;
    }

    // X = LN(emb2): chunk0 of threads 64..191 covers e2 exactly
    float sX = isX ? (a.x + a.y + a.z + a.w) : 0.f;
    float qX = isX ? (a.x * a.x + a.y * a.y + a.z * a.z + a.w * a.w) : 0.f;
    float2 rX = bred2(sX, qX, sh, tid, 7);
    if (isX) {
        float meanX = rX.x * (1.f / C2d);
        float invX  = rsqrtf(rX.y * (1.f / C2d) - meanX * meanX + 1e-6f);
        const int fx = f0 - 64;
        const float4 gx = ((const float4*)g1)[fx], bx = ((const float4*)b1)[fx];
        __half hh[4];
        hh[0] = __float2half_rn((a.x - meanX) * invX * gx.x + bx.x);
        hh[1] = __float2half_rn((a.y - meanX) * invX * gx.y + bx.y);
        hh[2] = __float2half_rn((a.z - meanX) * invX * gx.z + bx.z);
        hh[3] = __float2half_rn((a.w - meanX) * invX * gx.w + bx.w);
        *(uint2*)&Xh[row * C2d + fx * 4] = *(uint2*)hh;
    }
}

__global__ __launch_bounds__(128)
void ln2_kernel(const float* __restrict__ in,
                const float* __restrict__ g, const float* __restrict__ b,
                __half* __restrict__ Zh)
{
    const long row = blockIdx.x;
    const int  tid = threadIdx.x;
    __shared__ float sh[8];
    const float4 v = ((const float4*)(in + row * C2d))[tid];
    float s = v.x + v.y + v.z + v.w;
    float q = v.x * v.x + v.y * v.y + v.z * v.z + v.w * v.w;
    float2 r = bred2(s, q, sh, tid, 4);
    float mean = r.x * (1.f / C2d);
    float inv  = rsqrtf(r.y * (1.f / C2d) - mean * mean + 1e-6f);
    const float4 gg = ((const float4*)g)[tid], bb = ((const float4*)b)[tid];
    __half hh[4];
    hh[0] = __float2half_rn((v.x - mean) * inv * gg.x + bb.x);
    hh[1] = __float2half_rn((v.y - mean) * inv * gg.y + bb.y);
    hh[2] = __float2half_rn((v.z - mean) * inv * gg.z + bb.z);
    hh[3] = __float2half_rn((v.w - mean) * inv * gg.w + bb.w);
    *(uint2*)&Zh[row * C2d + tid * 4] = *(uint2*)hh;
}

// finish per-map variance from 56 per-tile partials -> softmax scale
__global__ __launch_bounds__(32)
void stats2_kernel(const float* __restrict__ part, float* __restrict__ scale)
{
    const int z = blockIdx.x, lane = threadIdx.x;
    float s = 0.f, q = 0.f;
#pragma unroll
    for (int j = 0; j < 2; ++j) {
        const int i = lane + j * 32;
        if (i < 56) { s += part[((long)z * 56 + i) * 2]; q += part[((long)z * 56 + i) * 2 + 1]; }
    }
#pragma unroll
    for (int o = 16; o; o >>= 1) {
        s += __shfl_xor_sync(0xffffffffu, s, o);
        q += __shfl_xor_sync(0xffffffffu, q, o);
    }
    if (lane == 0) {
        const float cnt = (float)(C2d * KVd);
        float mean = s / cnt;
        float var  = q / cnt - mean * mean;
        float a    = rsqrtf((float)KVd);
        scale[z]   = a * rsqrtf(a * a * var + 1e-5f);
    }
}

__global__ __launch_bounds__(224)
void softmax_kernel(const __half* __restrict__ Sh, const float* __restrict__ scale,
                    __half* __restrict__ Ph)
{
    const long row = blockIdx.x;
    const int  tid = threadIdx.x;
    const __half* p = Sh + row * KVd;
    const float sc = scale[blockIdx.x >> 9];
    __shared__ float sh[16];

    __align__(16) __half v8[8];
    *(uint4*)v8 = *(const uint4*)(p + tid * 8);
    float f[8];
#pragma unroll
    for (int j = 0; j < 8; ++j) f[j] = __half2float(v8[j]);
    float mx = f[0];
#pragma unroll
    for (int j = 1; j < 8; ++j) mx = fmaxf(mx, f[j]);
    mx = bmax(mx, sh, tid, 7);

    float e[8], s = 0.f;
#pragma unroll
    for (int j = 0; j < 8; ++j) { e[j] = __expf((f[j] - mx) * sc); s += e[j]; }
    float2 r = bred2(s, 0.f, sh, tid, 7);
    const float inv = 1.f / r.x;

#pragma unroll
    for (int j = 0; j < 8; ++j) v8[j] = __float2half_rn(e[j] * inv);
    *(uint4*)&Ph[row * KVd + tid * 8] = *(uint4*)v8;
}

// ===================== launcher =============================================
#define SYM(v, t, s) t* v; { void* _p; cudaGetSymbolAddress(&_p, s); v = (t*)_p; }

extern "C" void kernel_launch(void* const* d_in, const int* in_sizes, int n_in,
                              void* d_out, int out_size)
{
    const float* emb1    = (const float*)d_in[0];
    const float* emb2    = (const float*)d_in[1];
    const float* emb3    = (const float*)d_in[2];
    const float* Wq      = (const float*)d_in[3];
    const float* Wk      = (const float*)d_in[4];
    const float* Wv      = (const float*)d_in[5];
    const float* Wout    = (const float*)d_in[6];
    const float* ln1_g   = (const float*)d_in[7];
    const float* ln1_b   = (const float*)d_in[8];
    const float* lnall_g = (const float*)d_in[9];
    const float* lnall_b = (const float*)d_in[10];
    const float* lnffn_g = (const float*)d_in[11];
    const float* lnffn_b = (const float*)d_in[12];
    const float* fc1_w   = (const float*)d_in[13];
    const float* fc1_b   = (const float*)d_in[14];
    const float* fc2_w   = (const float*)d_in[15];
    const float* fc2_b   = (const float*)d_in[16];
    float* out = (float*)d_out;

    SYM(Yh, __half, g_Yh)   SYM(Yth, __half, g_Yth)
    SYM(Xh, __half, g_Xh)   SYM(Xth, __half, g_Xth)
    SYM(Gth, __half, g_Gth) SYM(Gtl, __half, g_Gtl)
    SYM(T1h, __half, g_T1h)
    SYM(Sh, __half, g_Sh)
    SYM(Ph, __half, g_Ph)
    SYM(Mth, __half, g_Mth)
    SYM(Ch, __half, g_Ch)
    SYM(cx2, float, g_cx2)
    SYM(Zh, __half, g_Zh)
    SYM(Fh, __half, g_Fh)
    SYM(WqTh, __half, g_WqTh)
    SYM(WkTh, __half, g_WkTh)
    SYM(Wvh, __half, g_Wvh)
    SYM(WoTh, __half, g_WoTh)
    SYM(f1Th, __half, g_f1Th)
    SYM(f2Th, __half, g_f2Th)
    SYM(scl, float, g_sc)     SYM(part, float, g_part)

    const int SM1 = 2 * 2 * (128 * (2 * 128 + 16));   // 139264 B, 1-pass
    const int SM2 = 2 * 3 * (128 * (2 * 128 + 16));   // 208896 B, B-split 2-pass
    cudaFuncSetAttribute(mma_gemm<128, 0, 0, 1, 0>, cudaFuncAttributeMaxDynamicSharedMemorySize, SM1);
    cudaFuncSetAttribute(mma_gemm<128, 1, 0, 2, 0>, cudaFuncAttributeMaxDynamicSharedMemorySize, SM2);
    cudaFuncSetAttribute(mma_gemm<128, 0, 0, 2, 1>, cudaFuncAttributeMaxDynamicSharedMemorySize, SM1);
    cudaFuncSetAttribute(mma_gemm<128, 0, 0, 2, 0>, cudaFuncAttributeMaxDynamicSharedMemorySize, SM1);
    cudaFuncSetAttribute(mma_gemm<128, 0, 1, 0, 0>, cudaFuncAttributeMaxDynamicSharedMemorySize, SM1);
    cudaFuncSetAttribute(mma_gemm<128, 0, 2, 2, 0>, cudaFuncAttributeMaxDynamicSharedMemorySize, SM1);
    cudaFuncSetAttribute(mma_gemm<128, 0, 3, 0, 0>, cudaFuncAttributeMaxDynamicSharedMemorySize, SM1);

    // weight prep: transpose+round / round
    tround_k<<<dim3(C2d / 64, C2d / 32, NHd), 256>>>(Wq, WqTh, C2d, C2d);
    tround_k<<<dim3(KVd / 64, KVd / 32, NHd), 256>>>(Wk, WkTh, KVd, KVd);
    tround_k<<<dim3(C2d / 64, C2d / 32, 1), 256>>>(Wout, WoTh, C2d, C2d);
    tround_k<<<dim3(C2E / 64, C2d / 32, 1), 256>>>(fc1_w, f1Th, C2d, C2E);
    tround_k<<<dim3(C2d / 64, C2E / 32, 1), 256>>>(fc2_w, f2Th, C2E, C2d);
    pround_k<<<4096, 256>>>(Wv, Wvh, (long)NHd * KVd * KVd / 4);

    // 1. input LayerNorms
    ln_in_kernel<<<BB * NT, 224>>>(emb1, emb2, emb3, lnall_g, lnall_b, ln1_g, ln1_b,
                                   Yh, Xh);
    // transposes for step 2
    tb16_k<<<dim3(KVd / 64, NT / 32, BB), 256>>>(Yh, Yth, NT, KVd);
    tb16_k<<<dim3(C2d / 64, NT / 32, BB), 256>>>(Xh, Xth, NT, C2d);

    // 2. Gt_b = Yt_b Xt_b^T  [1792,512], K=1024 (split out: Gt has corr spikes)
    mma_gemm<128, 0, 0, 1, 0><<<dim3(C2d / 128, KVd / 128, BB), 256, SM1>>>(
        Yth, Xth, nullptr, nullptr, Gth, Gtl, nullptr, nullptr,
        KVd, C2d, NT, NT, NT,
        (long)KVd * NT, (long)C2d * NT, (long)KVd * C2d, 0, 0, 1, 0, 0, 1.f);

    // 3. T1[b,h] = WqT_h Gt_b^T  [512,1792], K=512  (B-split 2-pass)
    mma_gemm<128, 1, 0, 2, 0><<<dim3(KVd / 128, C2d / 128, BB * NHd), 256, SM2>>>(
        WqTh, Gth, Gtl, nullptr, T1h, nullptr, nullptr, nullptr,
        C2d, KVd, C2d, C2d, C2d,
        (long)C2d * C2d, (long)KVd * C2d, (long)C2d * KVd, 1, 2, 1, 0, 0, 1.f);

    // 4. S[b,h] = T1 WkT_h^T  [512,1792], K=1792 (fp16 out + fused stats partials)
    mma_gemm<128, 0, 0, 2, 1><<<dim3(KVd / 128, C2d / 128, BB * NHd), 256, SM1>>>(
        T1h, WkTh, nullptr, part, Sh, nullptr, nullptr, nullptr,
        C2d, KVd, KVd, KVd, KVd,
        (long)C2d * KVd, (long)KVd * KVd, (long)C2d * KVd, 0, 1, 1, 0, 0, 1.f);

    // 5-6. finish stats + row softmax
    stats2_kernel<<<BB * NHd, 32>>>(part, scl);
    softmax_kernel<<<BB * NHd * C2d, 224>>>(Sh, scl, Ph);

    // 7. Mmt_b[c,e] = (1/H) sum_h sum_k P[b,h,c,k] Wv_h[e,k]  [512,1792]
    mma_gemm<128, 0, 0, 2, 0><<<dim3(KVd / 128, C2d / 128, BB), 256, SM1>>>(
        Ph, Wvh, nullptr, nullptr, Mth, nullptr, nullptr, nullptr,
        C2d, KVd, KVd, KVd, KVd,
        (long)NHd * C2d * KVd, 0, (long)C2d * KVd, 0, 0,
        NHd, (long)C2d * KVd, (long)KVd * KVd, 1.f / NHd);

    // 8. ctx_b = Y_b Mmt_b^T  [1024,512], K=1792
    mma_gemm<128, 0, 0, 2, 0><<<dim3(C2d / 128, NT / 128, BB), 256, SM1>>>(
        Yh, Mth, nullptr, nullptr, Ch, nullptr, nullptr, nullptr,
        NT, C2d, KVd, KVd, KVd,
        (long)NT * KVd, (long)C2d * KVd, (long)NT * C2d, 0, 0, 1, 0, 0, 1.f);

    // 9. cx2 = ctx WoutT^T + emb2  [8192,512]
    mma_gemm<128, 0, 1, 0, 0><<<dim3(C2d / 128, BB * NT / 128, 1), 256, SM1>>>(
        Ch, WoTh, nullptr, cx2, nullptr, nullptr, nullptr, emb2,
        BB * NT, C2d, C2d, C2d, C2d, 0, 0, 0, 0, 0, 1, 0, 0, 1.f);

    // 10. Z = LN(cx2)
    ln2_kernel<<<BB * NT, 128>>>(cx2, lnffn_g, lnffn_b, Zh);

    // 11. F = gelu(Z f1T^T + b1)  [8192,2048]
    mma_gemm<128, 0, 2, 2, 0><<<dim3(C2E / 128, BB * NT / 128, 1), 256, SM1>>>(
        Zh, f1Th, nullptr, nullptr, Fh, nullptr, fc1_b, nullptr,
        BB * NT, C2E, C2d, C2d, C2d, 0, 0, 0, 0, 0, 1, 0, 0, 1.f);

    // 12. out = F f2T^T + b2 + cx2  [8192,512]
    mma_gemm<128, 0, 3, 0, 0><<<dim3(C2d / 128, BB * NT / 128, 1), 256, SM1>>>(
        Fh, f2Th, nullptr, out, nullptr, nullptr, fc2_b, cx2,
        BB * NT, C2d, C2E, C2E, C2E, 0, 0, 0, 0, 0, 1, 0, 0, 1.f);
}

// round 13
// speedup vs baseline: 5.0046x; 1.0003x over previous
#include <cuda_runtime.h>
#include <cuda_fp16.h>
#include <math.h>
#include <stdint.h>

// Problem constants
#define BB   8
#define NT   1024
#define C1d  256
#define C2d  512
#define C3d  1024
#define KVd  1792
#define NHd  4
#define C2E  2048

// ===================== scratch (device statics) ==============================
__device__ __half g_Yh [BB*NT*KVd];                       // LN(concat)  [b][n][kv]
__device__ __half g_Yth[BB*NT*KVd];                       // transposed  [b][kv][n]
__device__ __half g_Xh [BB*NT*C2d];                       // LN(emb2)    [b][n][c]
__device__ __half g_Xth[BB*NT*C2d];                       // transposed  [b][c][n]
__device__ __half g_Gth[BB*KVd*C2d], g_Gtl[BB*KVd*C2d];   // Gt split (spiky!)
__device__ __half g_T1h[BB*NHd*C2d*KVd];
__device__ __half g_Sh [BB*NHd*C2d*KVd];                  // scores fp16
__device__ __half g_Ph [BB*NHd*C2d*KVd];                  // probs
__device__ __half g_Mth[BB*C2d*KVd];                      // Mmt [b][c][e]
__device__ __half g_Ch [BB*NT*C2d];                       // ctx
__device__ float  g_cx2[BB*NT*C2d];                       // residual fp32
__device__ __half g_Zh [BB*NT*C2d];                       // LN(cx2)
__device__ __half g_Fh [BB*NT*C2E];                       // gelu(fc1)
// weights (pre-transposed + rounded to fp16)
__device__ __half g_WqTh[NHd*C2d*C2d];
__device__ __half g_WkTh[NHd*KVd*KVd];
__device__ __half g_Wvh [NHd*KVd*KVd];
__device__ __half g_WoTh[C2d*C2d];
__device__ __half g_f1Th[C2E*C2d];
__device__ __half g_f2Th[C2d*C2E];
__device__ float g_sc[BB*NHd];
__device__ float g_part[BB*NHd*56*2];

// ===================== PTX helpers (baseline sm_80+ only) ====================
__device__ __forceinline__ uint32_t smem_u32(const void* p) {
    uint32_t a;
    asm("{ .reg .u64 t; cvta.to.shared.u64 t, %1; cvt.u32.u64 %0, t; }" : "=r"(a) : "l"(p));
    return a;
}
#define CPA16(d, s)   asm volatile("cp.async.cg.shared.global [%0], [%1], 16;" :: "r"(d), "l"(s))
#define CPA_COMMIT()  asm volatile("cp.async.commit_group;" ::: "memory")
#define CPA_WAIT1()   asm volatile("cp.async.wait_group 1;" ::: "memory")
#define CPA_WAIT0()   asm volatile("cp.async.wait_group 0;" ::: "memory")

#define LDSM4(r, a) \
    asm volatile("ldmatrix.sync.aligned.m8n8.x4.shared.b16 {%0,%1,%2,%3}, [%4];" \
        : "=r"((r)[0]), "=r"((r)[1]), "=r"((r)[2]), "=r"((r)[3]) : "r"(a))

#define MMA16816(C, A, B0, B1) \
    asm volatile("mma.sync.aligned.m16n8k16.row.col.f32.f16.f16.f32 " \
        "{%0,%1,%2,%3}, {%4,%5,%6,%7}, {%8,%9}, {%0,%1,%2,%3};" \
        : "+f"((C)[0]), "+f"((C)[1]), "+f"((C)[2]), "+f"((C)[3]) \
        : "r"((A)[0]), "r"((A)[1]), "r"((A)[2]), "r"((A)[3]), "r"(B0), "r"(B1))

__device__ __forceinline__ void splt(float v, __half& h, __half& l) {
    h = __float2half_rn(v);
    l = __float2half_rn(v - __half2float(h));
}
__device__ __forceinline__ int selidx(int mode, int z) {
    return mode == 0 ? z : (mode == 1 ? (z & 3) : (z >> 2));
}

// block reductions (warp shuffle + tiny smem); fixed order -> deterministic
__device__ __forceinline__ float2 bred2(float s, float q, float* sh, int tid, int nw) {
#pragma unroll
    for (int o = 16; o; o >>= 1) {
        s += __shfl_xor_sync(0xffffffffu, s, o);
        q += __shfl_xor_sync(0xffffffffu, q, o);
    }
    if ((tid & 31) == 0) { sh[(tid >> 5) * 2] = s; sh[(tid >> 5) * 2 + 1] = q; }
    __syncthreads();
    float rs = 0.f, rq = 0.f;
    for (int j = 0; j < nw; ++j) { rs += sh[j * 2]; rq += sh[j * 2 + 1]; }
    __syncthreads();
    return make_float2(rs, rq);
}
__device__ __forceinline__ float bmax(float v, float* sh, int tid, int nw) {
#pragma unroll
    for (int o = 16; o; o >>= 1) v = fmaxf(v, __shfl_xor_sync(0xffffffffu, v, o));
    if ((tid & 31) == 0) sh[tid >> 5] = v;
    __syncthreads();
    float r = sh[0];
    for (int j = 1; j < nw; ++j) r = fmaxf(r, sh[j]);
    __syncthreads();
    return r;
}

// ===================== mma.sync fp16 GEMM ====================================
// C[M,Nn] = outScale * sum_h A_h[M,K] * B_h[N,K]^T  (+ epilogue)
// BM: CTA M-tile (128 or 256); N-tile fixed 128. Warp layout 4(M) x 2(N).
// MODE: 0 -> 1-pass (A,B fp16-rounded);  1 -> 2-pass B-split (A*Bh + A*Bl)
// EPI: 0 none, 1 +add, 2 +bias,gelu, 3 +bias+add.
// OUT: 0 fp32, 1 fp16 hi+lo, 2 fp16 rounded
// STATS: 1 -> per-CTA sum/sumsq of outputs -> C (as partials buffer)
// smem row stride 2*BKE+16 B -> mod 128 = 16, conflict-free ldmatrix cycling.
template<int BM, int BKE, int MODE, int EPI, int OUT, int STATS>
__global__ __launch_bounds__(256)
void mma_gemm(const __half* __restrict__ Ahi,
              const __half* __restrict__ Bhi, const __half* __restrict__ Blo,
              float* __restrict__ C, __half* __restrict__ Chi, __half* __restrict__ Clo,
              const float* __restrict__ bias, const float* __restrict__ addp,
              int M, int Nn, int K, int lda, int ldb,
              long sA, long sB, long sC, int selA, int selB,
              int nH, long hA, long hB, float outScale)
{
    constexpr int PADB  = 2 * BKE + 16;
    constexpr int TILEA = BM * PADB;
    constexpr int TILEB = 128 * PADB;
    constexpr uint32_t STB = TILEA + (1 + MODE) * TILEB;   // stage bytes
    constexpr int SEGS  = BKE / 8;                         // 16B segments per row
    constexpr int RSTEP = 256 / SEGS;                      // rows staged per iter
    constexpr int KSN   = BKE / 16;
    constexpr int MF    = BM / 64;                         // 16-row frags per warp

    extern __shared__ char smem[];
    const uint32_t sb = smem_u32(smem);
    const int tid = threadIdx.x, wid = tid >> 5, lane = tid & 31;
    const int z = blockIdx.z;
    const int m0 = blockIdx.y * BM, n0 = blockIdx.x * 128;
    const int warpM = (wid & 3) * (BM / 4), warpN = (wid >> 2) * 64;

    const __half* A0h = Ahi + (long)selidx(selA, z) * sA;
    const __half* B0h = Bhi + (long)selidx(selB, z) * sB;
    const __half* B0l = (MODE == 1) ? (Blo + (long)selidx(selB, z) * sB) : nullptr;

    const int nchK = K / BKE;
    const int nch  = nH * nchK;

    const int srow = tid / SEGS;
    const int sseg = tid % SEGS;

    auto issue = [&](int ch) {
        const uint32_t so = sb + (uint32_t)(ch & 1) * STB;
        const int h  = ch / nchK;
        const int k0 = (ch - h * nchK) * BKE;
        {   // A tile: BM rows
            const __half* gb = A0h + (long)h * hA + (long)(m0 + srow) * lda + k0 + sseg * 8;
            const uint32_t tb = so + srow * PADB + sseg * 16;
#pragma unroll
            for (int j = 0; j < BM / RSTEP; ++j)
                CPA16(tb + j * RSTEP * PADB, gb + (long)(j * RSTEP) * lda);
        }
        {   // Bh tile: 128 rows
            const __half* gb = B0h + (long)h * hB + (long)(n0 + srow) * ldb + k0 + sseg * 8;
            const uint32_t tb = so + TILEA + srow * PADB + sseg * 16;
#pragma unroll
            for (int j = 0; j < 128 / RSTEP; ++j)
                CPA16(tb + j * RSTEP * PADB, gb + (long)(j * RSTEP) * ldb);
        }
        if (MODE == 1) {
            const __half* gb = B0l + (long)h * hB + (long)(n0 + srow) * ldb + k0 + sseg * 8;
            const uint32_t tb = so + TILEA + TILEB + srow * PADB + sseg * 16;
#pragma unroll
            for (int j = 0; j < 128 / RSTEP; ++j)
                CPA16(tb + j * RSTEP * PADB, gb + (long)(j * RSTEP) * ldb);
        }
        CPA_COMMIT();
    };

    float acc[MF][8][4];
#pragma unroll
    for (int i = 0; i < MF; ++i)
#pragma unroll
        for (int j = 0; j < 8; ++j)
#pragma unroll
            for (int k = 0; k < 4; ++k) acc[i][j][k] = 0.f;

    issue(0);
    issue(1);

    const uint32_t aRow = (uint32_t)(warpM + (lane & 15)) * PADB + ((lane >> 4) << 4);
    const uint32_t bRow = (uint32_t)(warpN + ((lane >> 4) << 3) + (lane & 7)) * PADB
                        + (((lane >> 3) & 1) << 4);

    for (int ch = 0; ch < nch; ++ch) {
        if (ch < nch - 1) { CPA_WAIT1(); } else { CPA_WAIT0(); }
        __syncthreads();
        const uint32_t so = sb + (uint32_t)(ch & 1) * STB;
#pragma unroll
        for (int ks = 0; ks < KSN; ++ks) {
            const uint32_t kb = ks * 32;
            uint32_t ah[MF][4], bh[4][4], bl[4][4];
#pragma unroll
            for (int mf = 0; mf < MF; ++mf)
                LDSM4(ah[mf], so + aRow + (uint32_t)(mf * 16 * PADB) + kb);
#pragma unroll
            for (int q = 0; q < 4; ++q) {
                const uint32_t bd = so + TILEA + bRow + (uint32_t)(q * 16 * PADB) + kb;
                LDSM4(bh[q], bd);
                if (MODE == 1) LDSM4(bl[q], bd + TILEB);
            }
#pragma unroll
            for (int mf = 0; mf < MF; ++mf)
#pragma unroll
                for (int nf = 0; nf < 8; ++nf) {
                    MMA16816(acc[mf][nf], ah[mf],
                             bh[nf >> 1][(nf & 1) * 2], bh[nf >> 1][(nf & 1) * 2 + 1]);
                    if (MODE == 1)
                        MMA16816(acc[mf][nf], ah[mf],
                                 bl[nf >> 1][(nf & 1) * 2], bl[nf >> 1][(nf & 1) * 2 + 1]);
                }
        }
        __syncthreads();
        if (ch + 2 < nch) issue(ch + 2);
    }

    // ---- epilogue (register accumulators -> gmem)
    const int rbase = m0 + warpM + (lane >> 2);
    const int cbase = n0 + warpN + (lane & 3) * 2;
    float ssum = 0.f, ssq = 0.f;
#pragma unroll
    for (int mf = 0; mf < MF; ++mf) {
#pragma unroll
        for (int h2 = 0; h2 < 2; ++h2) {
            const long m = rbase + mf * 16 + h2 * 8;
#pragma unroll
            for (int nf = 0; nf < 8; ++nf) {
                const long col = cbase + nf * 8;
                float v0 = acc[mf][nf][h2 * 2]     * outScale;
                float v1 = acc[mf][nf][h2 * 2 + 1] * outScale;
                if (EPI == 1) {
                    const float2 ad = *(const float2*)(addp + m * Nn + col);
                    v0 += ad.x; v1 += ad.y;
                }
                if (EPI == 2) {
                    v0 += bias[col]; v1 += bias[col + 1];
                    v0 = 0.5f * v0 * (1.f + erff(v0 * 0.70710678118654752f));
                    v1 = 0.5f * v1 * (1.f + erff(v1 * 0.70710678118654752f));
                }
                if (EPI == 3) {
                    const float2 ad = *(const float2*)(addp + m * Nn + col);
                    v0 += bias[col]     + ad.x;
                    v1 += bias[col + 1] + ad.y;
                }
                if (STATS) { ssum += v0 + v1; ssq += v0 * v0 + v1 * v1; }
                const long idx = (long)z * sC + m * Nn + col;
                if (OUT == 0) {
                    *(float2*)(C + idx) = make_float2(v0, v1);
                } else if (OUT == 1) {
                    __half h0, l0, h1, l1;
                    splt(v0, h0, l0); splt(v1, h1, l1);
                    *(__half2*)(Chi + idx) = __halves2half2(h0, h1);
                    *(__half2*)(Clo + idx) = __halves2half2(l0, l1);
                } else {
                    *(__half2*)(Chi + idx) =
                        __halves2half2(__float2half_rn(v0), __float2half_rn(v1));
                }
            }
        }
    }
    if (STATS) {
        __shared__ float sred[16];
        float s = ssum, q = ssq;
#pragma unroll
        for (int o = 16; o; o >>= 1) {
            s += __shfl_xor_sync(0xffffffffu, s, o);
            q += __shfl_xor_sync(0xffffffffu, q, o);
        }
        if (lane == 0) { sred[wid * 2] = s; sred[wid * 2 + 1] = q; }
        __syncthreads();
        if (tid == 0) {
            float rs = 0.f, rq = 0.f;
#pragma unroll
            for (int j = 0; j < 8; ++j) { rs += sred[j * 2]; rq += sred[j * 2 + 1]; }
            const long t = (long)z * (gridDim.x * gridDim.y)
                         + blockIdx.y * gridDim.x + blockIdx.x;
            C[t * 2] = rs; C[t * 2 + 1] = rq;
        }
    }
}

// ===================== prep kernels (vectorized) =============================
// fp32 [Z][R][C] -> fp16 [Z][C][R] (rounded), 32x64 tiles, 16B transactions
__global__ __launch_bounds__(256)
void tround_k(const float* __restrict__ in, __half* __restrict__ oh, int R, int Cc)
{
    __shared__ float t[32][65];
    const long zo = (long)blockIdx.z * R * Cc;
    const int c0 = blockIdx.x * 64, r0 = blockIdx.y * 32;
    const int tid = threadIdx.x;
#pragma unroll
    for (int it = 0; it < 2; ++it) {
        const int idx = tid + it * 256;
        const int r = idx >> 4, cs = idx & 15;
        const float4 v = *(const float4*)(in + zo + (long)(r0 + r) * Cc + c0 + cs * 4);
        t[r][cs * 4 + 0] = v.x; t[r][cs * 4 + 1] = v.y;
        t[r][cs * 4 + 2] = v.z; t[r][cs * 4 + 3] = v.w;
    }
    __syncthreads();
    const int c = tid >> 2, rs = tid & 3;
    __align__(16) __half hh[8];
#pragma unroll
    for (int j = 0; j < 8; ++j) hh[j] = __float2half_rn(t[rs * 8 + j][c]);
    *(uint4*)&oh[zo + (long)(c0 + c) * R + r0 + rs * 8] = *(uint4*)hh;
}

// fp32 -> fp16 rounded (same layout)
__global__ void pround_k(const float* __restrict__ in, __half* __restrict__ oh, long n4)
{
    for (long i = blockIdx.x * blockDim.x + threadIdx.x; i < n4; i += (long)gridDim.x * blockDim.x) {
        float4 v = ((const float4*)in)[i];
        __half hh[4] = { __float2half_rn(v.x), __float2half_rn(v.y),
                         __float2half_rn(v.z), __float2half_rn(v.w) };
        ((uint2*)oh)[i] = *(uint2*)hh;
    }
}

// fp16 [Z][R][C] -> [Z][C][R], 32x64 tiles, 16B transactions
__global__ __launch_bounds__(256)
void tb16_k(const __half* __restrict__ in, __half* __restrict__ out, int R, int Cc)
{
    __shared__ __half t[32][72];
    const long zo = (long)blockIdx.z * R * Cc;
    const int c0 = blockIdx.x * 64, r0 = blockIdx.y * 32;
    const int tid = threadIdx.x;
    {
        const int r = tid >> 3, cs = tid & 7;
        __align__(16) __half v[8];
        *(uint4*)v = *(const uint4*)(in + zo + (long)(r0 + r) * Cc + c0 + cs * 8);
#pragma unroll
        for (int j = 0; j < 8; ++j) t[r][cs * 8 + j] = v[j];
    }
    __syncthreads();
    const int c = tid >> 2, rs = tid & 3;
    __align__(16) __half o8[8];
#pragma unroll
    for (int j = 0; j < 8; ++j) o8[j] = t[rs * 8 + j][c];
    *(uint4*)&out[zo + (long)(c0 + c) * R + r0 + rs * 8] = *(uint4*)o8;
}

// input LayerNorms -> rounded fp16 outputs (224 thr: 448 float4 = 1792 elems)
__global__ __launch_bounds__(224)
void ln_in_kernel(const float* __restrict__ e1, const float* __restrict__ e2,
                  const float* __restrict__ e3,
                  const float* __restrict__ ag, const float* __restrict__ ab,
                  const float* __restrict__ g1, const float* __restrict__ b1,
                  __half* __restrict__ Yh, __half* __restrict__ Xh)
{
    const long row = blockIdx.x;
    const int  tid = threadIdx.x;
    const float4* p1 = (const float4*)(e1 + row * C1d);
    const float4* p2 = (const float4*)(e2 + row * C2d);
    const float4* p3 = (const float4*)(e3 + row * C3d);
    __shared__ float sh[16];

    const int f0 = tid, f1 = tid + 224;
    const bool isX = (f0 >= 64) && (f0 < 192);
    float4 a = (f0 < 64) ? p1[f0] : (isX ? p2[f0 - 64] : p3[f0 - 192]);
    float4 b = p3[f1 - 192];

    float s = a.x + a.y + a.z + a.w + b.x + b.y + b.z + b.w;
    float q = a.x * a.x + a.y * a.y + a.z * a.z + a.w * a.w
            + b.x * b.x + b.y * b.y + b.z * b.z + b.w * b.w;
    float2 r = bred2(s, q, sh, tid, 7);
    float mean = r.x * (1.f / KVd);
    float inv  = rsqrtf(r.y * (1.f / KVd) - mean * mean + 1e-6f);

    const float4* g4 = (const float4*)ag;
    const float4* b4 = (const float4*)ab;
    {
        const float4 ga = g4[f0], ba = b4[f0];
        __half hh[4];
        hh[0] = __float2half_rn((a.x - mean) * inv * ga.x + ba.x);
        hh[1] = __float2half_rn((a.y - mean) * inv * ga.y + ba.y);
        hh[2] = __float2half_rn((a.z - mean) * inv * ga.z + ba.z);
        hh[3] = __float2half_rn((a.w - mean) * inv * ga.w + ba.w);
        *(uint2*)&Yh[row * KVd + f0 * 4] = *(uint2*)hh;
        const float4 gb = g4[f1], bb = b4[f1];
        hh[0] = __float2half_rn((b.x - mean) * inv * gb.x + bb.x);
        hh[1] = __float2half_rn((b.y - mean) * inv * gb.y + bb.y);
        hh[2] = __float2half_rn((b.z - mean) * inv * gb.z + bb.z);
        hh[3] = __float2half_rn((b.w - mean) * inv * gb.w + bb.w);
        *(uint2*)&Yh[row * KVd + f1 * 4] = *(uint2*)hh;
    }

    // X = LN(emb2): chunk0 of threads 64..191 covers e2 exactly
    float sX = isX ? (a.x + a.y + a.z + a.w) : 0.f;
    float qX = isX ? (a.x * a.x + a.y * a.y + a.z * a.z + a.w * a.w) : 0.f;
    float2 rX = bred2(sX, qX, sh, tid, 7);
    if (isX) {
        float meanX = rX.x * (1.f / C2d);
        float invX  = rsqrtf(rX.y * (1.f / C2d) - meanX * meanX + 1e-6f);
        const int fx = f0 - 64;
        const float4 gx = ((const float4*)g1)[fx], bx = ((const float4*)b1)[fx];
        __half hh[4];
        hh[0] = __float2half_rn((a.x - meanX) * invX * gx.x + bx.x);
        hh[1] = __float2half_rn((a.y - meanX) * invX * gx.y + bx.y);
        hh[2] = __float2half_rn((a.z - meanX) * invX * gx.z + bx.z);
        hh[3] = __float2half_rn((a.w - meanX) * invX * gx.w + bx.w);
        *(uint2*)&Xh[row * C2d + fx * 4] = *(uint2*)hh;
    }
}

__global__ __launch_bounds__(128)
void ln2_kernel(const float* __restrict__ in,
                const float* __restrict__ g, const float* __restrict__ b,
                __half* __restrict__ Zh)
{
    const long row = blockIdx.x;
    const int  tid = threadIdx.x;
    __shared__ float sh[8];
    const float4 v = ((const float4*)(in + row * C2d))[tid];
    float s = v.x + v.y + v.z + v.w;
    float q = v.x * v.x + v.y * v.y + v.z * v.z + v.w * v.w;
    float2 r = bred2(s, q, sh, tid, 4);
    float mean = r.x * (1.f / C2d);
    float inv  = rsqrtf(r.y * (1.f / C2d) - mean * mean + 1e-6f);
    const float4 gg = ((const float4*)g)[tid], bb = ((const float4*)b)[tid];
    __half hh[4];
    hh[0] = __float2half_rn((v.x - mean) * inv * gg.x + bb.x);
    hh[1] = __float2half_rn((v.y - mean) * inv * gg.y + bb.y);
    hh[2] = __float2half_rn((v.z - mean) * inv * gg.z + bb.z);
    hh[3] = __float2half_rn((v.w - mean) * inv * gg.w + bb.w);
    *(uint2*)&Zh[row * C2d + tid * 4] = *(uint2*)hh;
}

// finish per-map variance from 28 per-tile partials -> softmax scale
__global__ __launch_bounds__(32)
void stats2_kernel(const float* __restrict__ part, float* __restrict__ scale)
{
    const int z = blockIdx.x, lane = threadIdx.x;
    float s = 0.f, q = 0.f;
    if (lane < 28) {
        s = part[((long)z * 28 + lane) * 2];
        q = part[((long)z * 28 + lane) * 2 + 1];
    }
#pragma unroll
    for (int o = 16; o; o >>= 1) {
        s += __shfl_xor_sync(0xffffffffu, s, o);
        q += __shfl_xor_sync(0xffffffffu, q, o);
    }
    if (lane == 0) {
        const float cnt = (float)(C2d * KVd);
        float mean = s / cnt;
        float var  = q / cnt - mean * mean;
        float a    = rsqrtf((float)KVd);
        scale[z]   = a * rsqrtf(a * a * var + 1e-5f);
    }
}

__global__ __launch_bounds__(224)
void softmax_kernel(const __half* __restrict__ Sh, const float* __restrict__ scale,
                    __half* __restrict__ Ph)
{
    const long row = blockIdx.x;
    const int  tid = threadIdx.x;
    const __half* p = Sh + row * KVd;
    const float sc = scale[blockIdx.x >> 9];
    __shared__ float sh[16];

    __align__(16) __half v8[8];
    *(uint4*)v8 = *(const uint4*)(p + tid * 8);
    float f[8];
#pragma unroll
    for (int j = 0; j < 8; ++j) f[j] = __half2float(v8[j]);
    float mx = f[0];
#pragma unroll
    for (int j = 1; j < 8; ++j) mx = fmaxf(mx, f[j]);
    mx = bmax(mx, sh, tid, 7);

    float e[8], s = 0.f;
#pragma unroll
    for (int j = 0; j < 8; ++j) { e[j] = __expf((f[j] - mx) * sc); s += e[j]; }
    float2 r = bred2(s, 0.f, sh, tid, 7);
    const float inv = 1.f / r.x;

#pragma unroll
    for (int j = 0; j < 8; ++j) v8[j] = __float2half_rn(e[j] * inv);
    *(uint4*)&Ph[row * KVd + tid * 8] = *(uint4*)v8;
}

// ===================== launcher =============================================
#define SYM(v, t, s) t* v; { void* _p; cudaGetSymbolAddress(&_p, s); v = (t*)_p; }

extern "C" void kernel_launch(void* const* d_in, const int* in_sizes, int n_in,
                              void* d_out, int out_size)
{
    const float* emb1    = (const float*)d_in[0];
    const float* emb2    = (const float*)d_in[1];
    const float* emb3    = (const float*)d_in[2];
    const float* Wq      = (const float*)d_in[3];
    const float* Wk      = (const float*)d_in[4];
    const float* Wv      = (const float*)d_in[5];
    const float* Wout    = (const float*)d_in[6];
    const float* ln1_g   = (const float*)d_in[7];
    const float* ln1_b   = (const float*)d_in[8];
    const float* lnall_g = (const float*)d_in[9];
    const float* lnall_b = (const float*)d_in[10];
    const float* lnffn_g = (const float*)d_in[11];
    const float* lnffn_b = (const float*)d_in[12];
    const float* fc1_w   = (const float*)d_in[13];
    const float* fc1_b   = (const float*)d_in[14];
    const float* fc2_w   = (const float*)d_in[15];
    const float* fc2_b   = (const float*)d_in[16];
    float* out = (float*)d_out;

    SYM(Yh, __half, g_Yh)   SYM(Yth, __half, g_Yth)
    SYM(Xh, __half, g_Xh)   SYM(Xth, __half, g_Xth)
    SYM(Gth, __half, g_Gth) SYM(Gtl, __half, g_Gtl)
    SYM(T1h, __half, g_T1h)
    SYM(Sh, __half, g_Sh)
    SYM(Ph, __half, g_Ph)
    SYM(Mth, __half, g_Mth)
    SYM(Ch, __half, g_Ch)
    SYM(cx2, float, g_cx2)
    SYM(Zh, __half, g_Zh)
    SYM(Fh, __half, g_Fh)
    SYM(WqTh, __half, g_WqTh)
    SYM(WkTh, __half, g_WkTh)
    SYM(Wvh, __half, g_Wvh)
    SYM(WoTh, __half, g_WoTh)
    SYM(f1Th, __half, g_f1Th)
    SYM(f2Th, __half, g_f2Th)
    SYM(scl, float, g_sc)     SYM(part, float, g_part)

    const int SMA = 2 * ((256 + 128) * (2 * 128 + 16));   // 208896 B, BM256 1-pass
    const int SMB = 2 * ((128 + 256) * (2 * 128 + 16));   // 208896 B, BM128 2-pass
    cudaFuncSetAttribute(mma_gemm<256, 128, 0, 0, 1, 0>, cudaFuncAttributeMaxDynamicSharedMemorySize, SMA);
    cudaFuncSetAttribute(mma_gemm<128, 128, 1, 0, 2, 0>, cudaFuncAttributeMaxDynamicSharedMemorySize, SMB);
    cudaFuncSetAttribute(mma_gemm<256, 128, 0, 0, 2, 1>, cudaFuncAttributeMaxDynamicSharedMemorySize, SMA);
    cudaFuncSetAttribute(mma_gemm<256, 128, 0, 0, 2, 0>, cudaFuncAttributeMaxDynamicSharedMemorySize, SMA);
    cudaFuncSetAttribute(mma_gemm<256, 128, 0, 1, 0, 0>, cudaFuncAttributeMaxDynamicSharedMemorySize, SMA);
    cudaFuncSetAttribute(mma_gemm<256, 128, 0, 2, 2, 0>, cudaFuncAttributeMaxDynamicSharedMemorySize, SMA);
    cudaFuncSetAttribute(mma_gemm<256, 128, 0, 3, 0, 0>, cudaFuncAttributeMaxDynamicSharedMemorySize, SMA);

    // --- launches 0..4: GEMM2's dependencies (puts GEMM2 at ncu's -s 5 slot)
    ln_in_kernel<<<BB * NT, 224>>>(emb1, emb2, emb3, lnall_g, lnall_b, ln1_g, ln1_b,
                                   Yh, Xh);
    tb16_k<<<dim3(KVd / 64, NT / 32, BB), 256>>>(Yh, Yth, NT, KVd);
    tb16_k<<<dim3(C2d / 64, NT / 32, BB), 256>>>(Xh, Xth, NT, C2d);
    tround_k<<<dim3(C2d / 64, C2d / 32, NHd), 256>>>(Wq, WqTh, C2d, C2d);
    tround_k<<<dim3(KVd / 64, KVd / 32, NHd), 256>>>(Wk, WkTh, KVd, KVd);

    // 2. Gt_b = Yt_b Xt_b^T  [1792,512], K=1024 (split out: Gt has corr spikes)
    mma_gemm<256, 128, 0, 0, 1, 0><<<dim3(C2d / 128, KVd / 256, BB), 256, SMA>>>(
        Yth, Xth, nullptr, nullptr, Gth, Gtl, nullptr, nullptr,
        KVd, C2d, NT, NT, NT,
        (long)KVd * NT, (long)C2d * NT, (long)KVd * C2d, 0, 0, 1, 0, 0, 1.f);

    // remaining weight prep (needed from GEMM7/9/11/12 on)
    tround_k<<<dim3(C2d / 64, C2d / 32, 1), 256>>>(Wout, WoTh, C2d, C2d);
    tround_k<<<dim3(C2E / 64, C2d / 32, 1), 256>>>(fc1_w, f1Th, C2d, C2E);
    tround_k<<<dim3(C2d / 64, C2E / 32, 1), 256>>>(fc2_w, f2Th, C2E, C2d);
    pround_k<<<4096, 256>>>(Wv, Wvh, (long)NHd * KVd * KVd / 4);

    // 3. T1[b,h] = WqT_h Gt_b^T  [512,1792], K=512  (B-split 2-pass, BM128)
    mma_gemm<128, 128, 1, 0, 2, 0><<<dim3(KVd / 128, C2d / 128, BB * NHd), 256, SMB>>>(
        WqTh, Gth, Gtl, nullptr, T1h, nullptr, nullptr, nullptr,
        C2d, KVd, C2d, C2d, C2d,
        (long)C2d * C2d, (long)KVd * C2d, (long)C2d * KVd, 1, 2, 1, 0, 0, 1.f);

    // 4. S[b,h] = T1 WkT_h^T  [512,1792], K=1792 (fp16 out + fused stats partials)
    mma_gemm<256, 128, 0, 0, 2, 1><<<dim3(KVd / 128, C2d / 256, BB * NHd), 256, SMA>>>(
        T1h, WkTh, nullptr, part, Sh, nullptr, nullptr, nullptr,
        C2d, KVd, KVd, KVd, KVd,
        (long)C2d * KVd, (long)KVd * KVd, (long)C2d * KVd, 0, 1, 1, 0, 0, 1.f);

    // 5-6. finish stats + row softmax
    stats2_kernel<<<BB * NHd, 32>>>(part, scl);
    softmax_kernel<<<BB * NHd * C2d, 224>>>(Sh, scl, Ph);

    // 7. Mmt_b[c,e] = (1/H) sum_h sum_k P[b,h,c,k] Wv_h[e,k]  [512,1792]
    mma_gemm<256, 128, 0, 0, 2, 0><<<dim3(KVd / 128, C2d / 256, BB), 256, SMA>>>(
        Ph, Wvh, nullptr, nullptr, Mth, nullptr, nullptr, nullptr,
        C2d, KVd, KVd, KVd, KVd,
        (long)NHd * C2d * KVd, 0, (long)C2d * KVd, 0, 0,
        NHd, (long)C2d * KVd, (long)KVd * KVd, 1.f / NHd);

    // 8. ctx_b = Y_b Mmt_b^T  [1024,512], K=1792
    mma_gemm<256, 128, 0, 0, 2, 0><<<dim3(C2d / 128, NT / 256, BB), 256, SMA>>>(
        Yh, Mth, nullptr, nullptr, Ch, nullptr, nullptr, nullptr,
        NT, C2d, KVd, KVd, KVd,
        (long)NT * KVd, (long)C2d * KVd, (long)NT * C2d, 0, 0, 1, 0, 0, 1.f);

    // 9. cx2 = ctx WoutT^T + emb2  [8192,512]
    mma_gemm<256, 128, 0, 1, 0, 0><<<dim3(C2d / 128, BB * NT / 256, 1), 256, SMA>>>(
        Ch, WoTh, nullptr, cx2, nullptr, nullptr, nullptr, emb2,
        BB * NT, C2d, C2d, C2d, C2d, 0, 0, 0, 0, 0, 1, 0, 0, 1.f);

    // 10. Z = LN(cx2)
    ln2_kernel<<<BB * NT, 128>>>(cx2, lnffn_g, lnffn_b, Zh);

    // 11. F = gelu(Z f1T^T + b1)  [8192,2048]
    mma_gemm<256, 128, 0, 2, 2, 0><<<dim3(C2E / 128, BB * NT / 256, 1), 256, SMA>>>(
        Zh, f1Th, nullptr, nullptr, Fh, nullptr, fc1_b, nullptr,
        BB * NT, C2E, C2d, C2d, C2d, 0, 0, 0, 0, 0, 1, 0, 0, 1.f);

    // 12. out = F f2T^T + b2 + cx2  [8192,512]
    mma_gemm<256, 128, 0, 3, 0, 0><<<dim3(C2d / 128, BB * NT / 256, 1), 256, SMA>>>(
        Fh, f2Th, nullptr, out, nullptr, nullptr, fc2_b, cx2,
        BB * NT, C2d, C2E, C2E, C2E, 0, 0, 0, 0, 0, 1, 0, 0, 1.f);
}

// round 14
// speedup vs baseline: 5.0489x; 1.0088x over previous
#include <cuda_runtime.h>
#include <cuda_fp16.h>
#include <math.h>
#include <stdint.h>

// Problem constants
#define BB   8
#define NT   1024
#define C1d  256
#define C2d  512
#define C3d  1024
#define KVd  1792
#define NHd  4
#define C2E  2048

// ===================== scratch (device statics) ==============================
__device__ __half g_Yh [BB*NT*KVd];                       // LN(concat)  [b][n][kv]
__device__ __half g_Yth[BB*NT*KVd];                       // transposed  [b][kv][n]
__device__ __half g_Xh [BB*NT*C2d];                       // LN(emb2)    [b][n][c]
__device__ __half g_Xth[BB*NT*C2d];                       // transposed  [b][c][n]
__device__ __half g_Gth[BB*KVd*C2d], g_Gtl[BB*KVd*C2d];   // Gt split (spiky!)
__device__ __half g_T1h[BB*NHd*C2d*KVd];
__device__ __half g_Sh [BB*NHd*C2d*KVd];                  // scores fp16
__device__ __half g_Ph [BB*NHd*C2d*KVd];                  // probs
__device__ __half g_Mth[BB*C2d*KVd];                      // Mmt [b][c][e]
__device__ __half g_Ch [BB*NT*C2d];                       // ctx
__device__ float  g_cx2[BB*NT*C2d];                       // residual fp32
__device__ __half g_Zh [BB*NT*C2d];                       // LN(cx2)
__device__ __half g_Fh [BB*NT*C2E];                       // gelu(fc1)
// weights (pre-transposed + rounded to fp16)
__device__ __half g_WqTh[NHd*C2d*C2d];
__device__ __half g_WkTh[NHd*KVd*KVd];
__device__ __half g_Wvh [NHd*KVd*KVd];
__device__ __half g_WoTh[C2d*C2d];
__device__ __half g_f1Th[C2E*C2d];
__device__ __half g_f2Th[C2d*C2E];
__device__ float g_sc[BB*NHd];
__device__ float g_part[BB*NHd*56*2];

// ===================== PTX helpers (baseline sm_80+ only) ====================
__device__ __forceinline__ uint32_t smem_u32(const void* p) {
    uint32_t a;
    asm("{ .reg .u64 t; cvta.to.shared.u64 t, %1; cvt.u32.u64 %0, t; }" : "=r"(a) : "l"(p));
    return a;
}
#define CPA16(d, s)   asm volatile("cp.async.cg.shared.global [%0], [%1], 16;" :: "r"(d), "l"(s))
#define CPA_COMMIT()  asm volatile("cp.async.commit_group;" ::: "memory")
#define CPA_WAIT2()   asm volatile("cp.async.wait_group 2;" ::: "memory")
#define CPA_WAIT1()   asm volatile("cp.async.wait_group 1;" ::: "memory")
#define CPA_WAIT0()   asm volatile("cp.async.wait_group 0;" ::: "memory")

#define LDSM4(r, a) \
    asm volatile("ldmatrix.sync.aligned.m8n8.x4.shared.b16 {%0,%1,%2,%3}, [%4];" \
        : "=r"((r)[0]), "=r"((r)[1]), "=r"((r)[2]), "=r"((r)[3]) : "r"(a))

#define MMA16816(C, A, B0, B1) \
    asm volatile("mma.sync.aligned.m16n8k16.row.col.f32.f16.f16.f32 " \
        "{%0,%1,%2,%3}, {%4,%5,%6,%7}, {%8,%9}, {%0,%1,%2,%3};" \
        : "+f"((C)[0]), "+f"((C)[1]), "+f"((C)[2]), "+f"((C)[3]) \
        : "r"((A)[0]), "r"((A)[1]), "r"((A)[2]), "r"((A)[3]), "r"(B0), "r"(B1))

__device__ __forceinline__ void splt(float v, __half& h, __half& l) {
    h = __float2half_rn(v);
    l = __float2half_rn(v - __half2float(h));
}
__device__ __forceinline__ int selidx(int mode, int z) {
    return mode == 0 ? z : (mode == 1 ? (z & 3) : (z >> 2));
}

// block reductions (warp shuffle + tiny smem); fixed order -> deterministic
__device__ __forceinline__ float2 bred2(float s, float q, float* sh, int tid, int nw) {
#pragma unroll
    for (int o = 16; o; o >>= 1) {
        s += __shfl_xor_sync(0xffffffffu, s, o);
        q += __shfl_xor_sync(0xffffffffu, q, o);
    }
    if ((tid & 31) == 0) { sh[(tid >> 5) * 2] = s; sh[(tid >> 5) * 2 + 1] = q; }
    __syncthreads();
    float rs = 0.f, rq = 0.f;
    for (int j = 0; j < nw; ++j) { rs += sh[j * 2]; rq += sh[j * 2 + 1]; }
    __syncthreads();
    return make_float2(rs, rq);
}
__device__ __forceinline__ float bmax(float v, float* sh, int tid, int nw) {
#pragma unroll
    for (int o = 16; o; o >>= 1) v = fmaxf(v, __shfl_xor_sync(0xffffffffu, v, o));
    if ((tid & 31) == 0) sh[tid >> 5] = v;
    __syncthreads();
    float r = sh[0];
    for (int j = 1; j < nw; ++j) r = fmaxf(r, sh[j]);
    __syncthreads();
    return r;
}

// ===================== mma.sync fp16 GEMM ====================================
// C[M,Nn] = outScale * sum_h A_h[M,K] * B_h[N,K]^T  (+ epilogue)
// BM: CTA M-tile; N-tile 128. Warp layout 4(M) x 2(N). STG: pipeline stages.
// MODE: 0 -> 1-pass (A,B fp16-rounded);  1 -> 2-pass B-split (A*Bh + A*Bl)
// EPI: 0 none, 1 +add, 2 +bias,gelu, 3 +bias+add.
// OUT: 0 fp32, 1 fp16 hi+lo, 2 fp16 rounded
// STATS: 1 -> per-CTA sum/sumsq of outputs -> C (as partials buffer)
// smem row stride 2*BKE+16 B -> mod 128 = 16, conflict-free ldmatrix cycling.
template<int BM, int BKE, int STG, int MODE, int EPI, int OUT, int STATS>
__global__ __launch_bounds__(256)
void mma_gemm(const __half* __restrict__ Ahi,
              const __half* __restrict__ Bhi, const __half* __restrict__ Blo,
              float* __restrict__ C, __half* __restrict__ Chi, __half* __restrict__ Clo,
              const float* __restrict__ bias, const float* __restrict__ addp,
              int M, int Nn, int K, int lda, int ldb,
              long sA, long sB, long sC, int selA, int selB,
              int nH, long hA, long hB, float outScale)
{
    constexpr int PADB  = 2 * BKE + 16;
    constexpr int TILEA = BM * PADB;
    constexpr int TILEB = 128 * PADB;
    constexpr uint32_t STB = TILEA + (1 + MODE) * TILEB;   // stage bytes
    constexpr int SEGS  = BKE / 8;                         // 16B segments per row
    constexpr int RSTEP = 256 / SEGS;                      // rows staged per iter
    constexpr int KSN   = BKE / 16;
    constexpr int MF    = BM / 64;                         // 16-row frags per warp

    extern __shared__ char smem[];
    const uint32_t sb = smem_u32(smem);
    const int tid = threadIdx.x, wid = tid >> 5, lane = tid & 31;
    const int z = blockIdx.z;
    const int m0 = blockIdx.y * BM, n0 = blockIdx.x * 128;
    const int warpM = (wid & 3) * (BM / 4), warpN = (wid >> 2) * 64;

    const __half* A0h = Ahi + (long)selidx(selA, z) * sA;
    const __half* B0h = Bhi + (long)selidx(selB, z) * sB;
    const __half* B0l = (MODE == 1) ? (Blo + (long)selidx(selB, z) * sB) : nullptr;

    const int nchK = K / BKE;
    const int nch  = nH * nchK;

    const int srow = tid / SEGS;
    const int sseg = tid % SEGS;

    auto issue = [&](int ch, int buf) {
        const uint32_t so = sb + (uint32_t)buf * STB;
        const int h  = ch / nchK;
        const int k0 = (ch - h * nchK) * BKE;
        {   // A tile: BM rows
            const __half* gb = A0h + (long)h * hA + (long)(m0 + srow) * lda + k0 + sseg * 8;
            const uint32_t tb = so + srow * PADB + sseg * 16;
#pragma unroll
            for (int j = 0; j < BM / RSTEP; ++j)
                CPA16(tb + j * RSTEP * PADB, gb + (long)(j * RSTEP) * lda);
        }
        {   // Bh tile: 128 rows
            const __half* gb = B0h + (long)h * hB + (long)(n0 + srow) * ldb + k0 + sseg * 8;
            const uint32_t tb = so + TILEA + srow * PADB + sseg * 16;
#pragma unroll
            for (int j = 0; j < 128 / RSTEP; ++j)
                CPA16(tb + j * RSTEP * PADB, gb + (long)(j * RSTEP) * ldb);
        }
        if (MODE == 1) {
            const __half* gb = B0l + (long)h * hB + (long)(n0 + srow) * ldb + k0 + sseg * 8;
            const uint32_t tb = so + TILEA + TILEB + srow * PADB + sseg * 16;
#pragma unroll
            for (int j = 0; j < 128 / RSTEP; ++j)
                CPA16(tb + j * RSTEP * PADB, gb + (long)(j * RSTEP) * ldb);
        }
        CPA_COMMIT();
    };

    float acc[MF][8][4];
#pragma unroll
    for (int i = 0; i < MF; ++i)
#pragma unroll
        for (int j = 0; j < 8; ++j)
#pragma unroll
            for (int k = 0; k < 4; ++k) acc[i][j][k] = 0.f;

#pragma unroll
    for (int p = 0; p < STG; ++p) issue(p, p);

    const uint32_t aRow = (uint32_t)(warpM + (lane & 15)) * PADB + ((lane >> 4) << 4);
    const uint32_t bRow = (uint32_t)(warpN + ((lane >> 4) << 3) + (lane & 7)) * PADB
                        + (((lane >> 3) & 1) << 4);

    int buf = 0;
    for (int ch = 0; ch < nch; ++ch) {
        const int rem = nch - 1 - ch;         // groups still issuable/pending beyond ch
        if (STG == 3) {
            if (rem >= 2) { CPA_WAIT2(); } else if (rem == 1) { CPA_WAIT1(); } else { CPA_WAIT0(); }
        } else {
            if (rem >= 1) { CPA_WAIT1(); } else { CPA_WAIT0(); }
        }
        __syncthreads();
        const uint32_t so = sb + (uint32_t)buf * STB;
#pragma unroll
        for (int ks = 0; ks < KSN; ++ks) {
            const uint32_t kb = ks * 32;
            uint32_t ah[MF][4], bh[4][4], bl[4][4];
#pragma unroll
            for (int mf = 0; mf < MF; ++mf)
                LDSM4(ah[mf], so + aRow + (uint32_t)(mf * 16 * PADB) + kb);
#pragma unroll
            for (int q = 0; q < 4; ++q) {
                const uint32_t bd = so + TILEA + bRow + (uint32_t)(q * 16 * PADB) + kb;
                LDSM4(bh[q], bd);
                if (MODE == 1) LDSM4(bl[q], bd + TILEB);
            }
#pragma unroll
            for (int mf = 0; mf < MF; ++mf)
#pragma unroll
                for (int nf = 0; nf < 8; ++nf) {
                    MMA16816(acc[mf][nf], ah[mf],
                             bh[nf >> 1][(nf & 1) * 2], bh[nf >> 1][(nf & 1) * 2 + 1]);
                    if (MODE == 1)
                        MMA16816(acc[mf][nf], ah[mf],
                                 bl[nf >> 1][(nf & 1) * 2], bl[nf >> 1][(nf & 1) * 2 + 1]);
                }
        }
        __syncthreads();
        if (ch + STG < nch) issue(ch + STG, buf);
        buf = (buf + 1 == STG) ? 0 : buf + 1;
    }

    // ---- epilogue (register accumulators -> gmem)
    const int rbase = m0 + warpM + (lane >> 2);
    const int cbase = n0 + warpN + (lane & 3) * 2;
    float ssum = 0.f, ssq = 0.f;
#pragma unroll
    for (int mf = 0; mf < MF; ++mf) {
#pragma unroll
        for (int h2 = 0; h2 < 2; ++h2) {
            const long m = rbase + mf * 16 + h2 * 8;
#pragma unroll
            for (int nf = 0; nf < 8; ++nf) {
                const long col = cbase + nf * 8;
                float v0 = acc[mf][nf][h2 * 2]     * outScale;
                float v1 = acc[mf][nf][h2 * 2 + 1] * outScale;
                if (EPI == 1) {
                    const float2 ad = *(const float2*)(addp + m * Nn + col);
                    v0 += ad.x; v1 += ad.y;
                }
                if (EPI == 2) {
                    v0 += bias[col]; v1 += bias[col + 1];
                    v0 = 0.5f * v0 * (1.f + erff(v0 * 0.70710678118654752f));
                    v1 = 0.5f * v1 * (1.f + erff(v1 * 0.70710678118654752f));
                }
                if (EPI == 3) {
                    const float2 ad = *(const float2*)(addp + m * Nn + col);
                    v0 += bias[col]     + ad.x;
                    v1 += bias[col + 1] + ad.y;
                }
                if (STATS) { ssum += v0 + v1; ssq += v0 * v0 + v1 * v1; }
                const long idx = (long)z * sC + m * Nn + col;
                if (OUT == 0) {
                    *(float2*)(C + idx) = make_float2(v0, v1);
                } else if (OUT == 1) {
                    __half h0, l0, h1, l1;
                    splt(v0, h0, l0); splt(v1, h1, l1);
                    *(__half2*)(Chi + idx) = __halves2half2(h0, h1);
                    *(__half2*)(Clo + idx) = __halves2half2(l0, l1);
                } else {
                    *(__half2*)(Chi + idx) =
                        __halves2half2(__float2half_rn(v0), __float2half_rn(v1));
                }
            }
        }
    }
    if (STATS) {
        __shared__ float sred[16];
        float s = ssum, q = ssq;
#pragma unroll
        for (int o = 16; o; o >>= 1) {
            s += __shfl_xor_sync(0xffffffffu, s, o);
            q += __shfl_xor_sync(0xffffffffu, q, o);
        }
        if (lane == 0) { sred[wid * 2] = s; sred[wid * 2 + 1] = q; }
        __syncthreads();
        if (tid == 0) {
            float rs = 0.f, rq = 0.f;
#pragma unroll
            for (int j = 0; j < 8; ++j) { rs += sred[j * 2]; rq += sred[j * 2 + 1]; }
            const long t = (long)z * (gridDim.x * gridDim.y)
                         + blockIdx.y * gridDim.x + blockIdx.x;
            C[t * 2] = rs; C[t * 2 + 1] = rq;
        }
    }
}

// ===================== prep kernels (vectorized) =============================
// fp32 [Z][R][C] -> fp16 [Z][C][R] (rounded), 32x64 tiles, 16B transactions
__global__ __launch_bounds__(256)
void tround_k(const float* __restrict__ in, __half* __restrict__ oh, int R, int Cc)
{
    __shared__ float t[32][65];
    const long zo = (long)blockIdx.z * R * Cc;
    const int c0 = blockIdx.x * 64, r0 = blockIdx.y * 32;
    const int tid = threadIdx.x;
#pragma unroll
    for (int it = 0; it < 2; ++it) {
        const int idx = tid + it * 256;
        const int r = idx >> 4, cs = idx & 15;
        const float4 v = *(const float4*)(in + zo + (long)(r0 + r) * Cc + c0 + cs * 4);
        t[r][cs * 4 + 0] = v.x; t[r][cs * 4 + 1] = v.y;
        t[r][cs * 4 + 2] = v.z; t[r][cs * 4 + 3] = v.w;
    }
    __syncthreads();
    const int c = tid >> 2, rs = tid & 3;
    __align__(16) __half hh[8];
#pragma unroll
    for (int j = 0; j < 8; ++j) hh[j] = __float2half_rn(t[rs * 8 + j][c]);
    *(uint4*)&oh[zo + (long)(c0 + c) * R + r0 + rs * 8] = *(uint4*)hh;
}

// fp32 -> fp16 rounded (same layout)
__global__ void pround_k(const float* __restrict__ in, __half* __restrict__ oh, long n4)
{
    for (long i = blockIdx.x * blockDim.x + threadIdx.x; i < n4; i += (long)gridDim.x * blockDim.x) {
        float4 v = ((const float4*)in)[i];
        __half hh[4] = { __float2half_rn(v.x), __float2half_rn(v.y),
                         __float2half_rn(v.z), __float2half_rn(v.w) };
        ((uint2*)oh)[i] = *(uint2*)hh;
    }
}

// fp16 [Z][R][C] -> [Z][C][R], 32x64 tiles, 16B transactions
__global__ __launch_bounds__(256)
void tb16_k(const __half* __restrict__ in, __half* __restrict__ out, int R, int Cc)
{
    __shared__ __half t[32][72];
    const long zo = (long)blockIdx.z * R * Cc;
    const int c0 = blockIdx.x * 64, r0 = blockIdx.y * 32;
    const int tid = threadIdx.x;
    {
        const int r = tid >> 3, cs = tid & 7;
        __align__(16) __half v[8];
        *(uint4*)v = *(const uint4*)(in + zo + (long)(r0 + r) * Cc + c0 + cs * 8);
#pragma unroll
        for (int j = 0; j < 8; ++j) t[r][cs * 8 + j] = v[j];
    }
    __syncthreads();
    const int c = tid >> 2, rs = tid & 3;
    __align__(16) __half o8[8];
#pragma unroll
    for (int j = 0; j < 8; ++j) o8[j] = t[rs * 8 + j][c];
    *(uint4*)&out[zo + (long)(c0 + c) * R + r0 + rs * 8] = *(uint4*)o8;
}

// input LayerNorms -> rounded fp16 outputs (224 thr: 448 float4 = 1792 elems)
__global__ __launch_bounds__(224)
void ln_in_kernel(const float* __restrict__ e1, const float* __restrict__ e2,
                  const float* __restrict__ e3,
                  const float* __restrict__ ag, const float* __restrict__ ab,
                  const float* __restrict__ g1, const float* __restrict__ b1,
                  __half* __restrict__ Yh, __half* __restrict__ Xh)
{
    const long row = blockIdx.x;
    const int  tid = threadIdx.x;
    const float4* p1 = (const float4*)(e1 + row * C1d);
    const float4* p2 = (const float4*)(e2 + row * C2d);
    const float4* p3 = (const float4*)(e3 + row * C3d);
    __shared__ float sh[16];

    const int f0 = tid, f1 = tid + 224;
    const bool isX = (f0 >= 64) && (f0 < 192);
    float4 a = (f0 < 64) ? p1[f0] : (isX ? p2[f0 - 64] : p3[f0 - 192]);
    float4 b = p3[f1 - 192];

    float s = a.x + a.y + a.z + a.w + b.x + b.y + b.z + b.w;
    float q = a.x * a.x + a.y * a.y + a.z * a.z + a.w * a.w
            + b.x * b.x + b.y * b.y + b.z * b.z + b.w * b.w;
    float2 r = bred2(s, q, sh, tid, 7);
    float mean = r.x * (1.f / KVd);
    float inv  = rsqrtf(r.y * (1.f / KVd) - mean * mean + 1e-6f);

    const float4* g4 = (const float4*)ag;
    const float4* b4 = (const float4*)ab;
    {
        const float4 ga = g4[f0], ba = b4[f0];
        __half hh[4];
        hh[0] = __float2half_rn((a.x - mean) * inv * ga.x + ba.x);
        hh[1] = __float2half_rn((a.y - mean) * inv * ga.y + ba.y);
        hh[2] = __float2half_rn((a.z - mean) * inv * ga.z + ba.z);
        hh[3] = __float2half_rn((a.w - mean) * inv * ga.w + ba.w);
        *(uint2*)&Yh[row * KVd + f0 * 4] = *(uint2*)hh;
        const float4 gb = g4[f1], bb = b4[f1];
        hh[0] = __float2half_rn((b.x - mean) * inv * gb.x + bb.x);
        hh[1] = __float2half_rn((b.y - mean) * inv * gb.y + bb.y);
        hh[2] = __float2half_rn((b.z - mean) * inv * gb.z + bb.z);
        hh[3] = __float2half_rn((b.w - mean) * inv * gb.w + bb.w);
        *(uint2*)&Yh[row * KVd + f1 * 4] = *(uint2*)hh;
    }

    // X = LN(emb2): chunk0 of threads 64..191 covers e2 exactly
    float sX = isX ? (a.x + a.y + a.z + a.w) : 0.f;
    float qX = isX ? (a.x * a.x + a.y * a.y + a.z * a.z + a.w * a.w) : 0.f;
    float2 rX = bred2(sX, qX, sh, tid, 7);
    if (isX) {
        float meanX = rX.x * (1.f / C2d);
        float invX  = rsqrtf(rX.y * (1.f / C2d) - meanX * meanX + 1e-6f);
        const int fx = f0 - 64;
        const float4 gx = ((const float4*)g1)[fx], bx = ((const float4*)b1)[fx];
        __half hh[4];
        hh[0] = __float2half_rn((a.x - meanX) * invX * gx.x + bx.x);
        hh[1] = __float2half_rn((a.y - meanX) * invX * gx.y + bx.y);
        hh[2] = __float2half_rn((a.z - meanX) * invX * gx.z + bx.z);
        hh[3] = __float2half_rn((a.w - meanX) * invX * gx.w + bx.w);
        *(uint2*)&Xh[row * C2d + fx * 4] = *(uint2*)hh;
    }
}

__global__ __launch_bounds__(128)
void ln2_kernel(const float* __restrict__ in,
                const float* __restrict__ g, const float* __restrict__ b,
                __half* __restrict__ Zh)
{
    const long row = blockIdx.x;
    const int  tid = threadIdx.x;
    __shared__ float sh[8];
    const float4 v = ((const float4*)(in + row * C2d))[tid];
    float s = v.x + v.y + v.z + v.w;
    float q = v.x * v.x + v.y * v.y + v.z * v.z + v.w * v.w;
    float2 r = bred2(s, q, sh, tid, 4);
    float mean = r.x * (1.f / C2d);
    float inv  = rsqrtf(r.y * (1.f / C2d) - mean * mean + 1e-6f);
    const float4 gg = ((const float4*)g)[tid], bb = ((const float4*)b)[tid];
    __half hh[4];
    hh[0] = __float2half_rn((v.x - mean) * inv * gg.x + bb.x);
    hh[1] = __float2half_rn((v.y - mean) * inv * gg.y + bb.y);
    hh[2] = __float2half_rn((v.z - mean) * inv * gg.z + bb.z);
    hh[3] = __float2half_rn((v.w - mean) * inv * gg.w + bb.w);
    *(uint2*)&Zh[row * C2d + tid * 4] = *(uint2*)hh;
}

// finish per-map variance from 56 per-tile partials -> softmax scale
__global__ __launch_bounds__(32)
void stats2_kernel(const float* __restrict__ part, float* __restrict__ scale)
{
    const int z = blockIdx.x, lane = threadIdx.x;
    float s = 0.f, q = 0.f;
#pragma unroll
    for (int j = 0; j < 2; ++j) {
        const int i = lane + j * 32;
        if (i < 56) { s += part[((long)z * 56 + i) * 2]; q += part[((long)z * 56 + i) * 2 + 1]; }
    }
#pragma unroll
    for (int o = 16; o; o >>= 1) {
        s += __shfl_xor_sync(0xffffffffu, s, o);
        q += __shfl_xor_sync(0xffffffffu, q, o);
    }
    if (lane == 0) {
        const float cnt = (float)(C2d * KVd);
        float mean = s / cnt;
        float var  = q / cnt - mean * mean;
        float a    = rsqrtf((float)KVd);
        scale[z]   = a * rsqrtf(a * a * var + 1e-5f);
    }
}

__global__ __launch_bounds__(224)
void softmax_kernel(const __half* __restrict__ Sh, const float* __restrict__ scale,
                    __half* __restrict__ Ph)
{
    const long row = blockIdx.x;
    const int  tid = threadIdx.x;
    const __half* p = Sh + row * KVd;
    const float sc = scale[blockIdx.x >> 9];
    __shared__ float sh[16];

    __align__(16) __half v8[8];
    *(uint4*)v8 = *(const uint4*)(p + tid * 8);
    float f[8];
#pragma unroll
    for (int j = 0; j < 8; ++j) f[j] = __half2float(v8[j]);
    float mx = f[0];
#pragma unroll
    for (int j = 1; j < 8; ++j) mx = fmaxf(mx, f[j]);
    mx = bmax(mx, sh, tid, 7);

    float e[8], s = 0.f;
#pragma unroll
    for (int j = 0; j < 8; ++j) { e[j] = __expf((f[j] - mx) * sc); s += e[j]; }
    float2 r = bred2(s, 0.f, sh, tid, 7);
    const float inv = 1.f / r.x;

#pragma unroll
    for (int j = 0; j < 8; ++j) v8[j] = __float2half_rn(e[j] * inv);
    *(uint4*)&Ph[row * KVd + tid * 8] = *(uint4*)v8;
}

// ===================== launcher =============================================
#define SYM(v, t, s) t* v; { void* _p; cudaGetSymbolAddress(&_p, s); v = (t*)_p; }

extern "C" void kernel_launch(void* const* d_in, const int* in_sizes, int n_in,
                              void* d_out, int out_size)
{
    const float* emb1    = (const float*)d_in[0];
    const float* emb2    = (const float*)d_in[1];
    const float* emb3    = (const float*)d_in[2];
    const float* Wq      = (const float*)d_in[3];
    const float* Wk      = (const float*)d_in[4];
    const float* Wv      = (const float*)d_in[5];
    const float* Wout    = (const float*)d_in[6];
    const float* ln1_g   = (const float*)d_in[7];
    const float* ln1_b   = (const float*)d_in[8];
    const float* lnall_g = (const float*)d_in[9];
    const float* lnall_b = (const float*)d_in[10];
    const float* lnffn_g = (const float*)d_in[11];
    const float* lnffn_b = (const float*)d_in[12];
    const float* fc1_w   = (const float*)d_in[13];
    const float* fc1_b   = (const float*)d_in[14];
    const float* fc2_w   = (const float*)d_in[15];
    const float* fc2_b   = (const float*)d_in[16];
    float* out = (float*)d_out;

    SYM(Yh, __half, g_Yh)   SYM(Yth, __half, g_Yth)
    SYM(Xh, __half, g_Xh)   SYM(Xth, __half, g_Xth)
    SYM(Gth, __half, g_Gth) SYM(Gtl, __half, g_Gtl)
    SYM(T1h, __half, g_T1h)
    SYM(Sh, __half, g_Sh)
    SYM(Ph, __half, g_Ph)
    SYM(Mth, __half, g_Mth)
    SYM(Ch, __half, g_Ch)
    SYM(cx2, float, g_cx2)
    SYM(Zh, __half, g_Zh)
    SYM(Fh, __half, g_Fh)
    SYM(WqTh, __half, g_WqTh)
    SYM(WkTh, __half, g_WkTh)
    SYM(Wvh, __half, g_Wvh)
    SYM(WoTh, __half, g_WoTh)
    SYM(f1Th, __half, g_f1Th)
    SYM(f2Th, __half, g_f2Th)
    SYM(scl, float, g_sc)     SYM(part, float, g_part)

    const int SMA = 3 * ((128 + 128) * (2 * 128 + 16));   // 208896 B, BM128 3-stage 1-pass
    const int SMB = 2 * ((128 + 256) * (2 * 128 + 16));   // 208896 B, BM128 2-stage 2-pass
    cudaFuncSetAttribute(mma_gemm<128, 128, 3, 0, 0, 1, 0>, cudaFuncAttributeMaxDynamicSharedMemorySize, SMA);
    cudaFuncSetAttribute(mma_gemm<128, 128, 2, 1, 0, 2, 0>, cudaFuncAttributeMaxDynamicSharedMemorySize, SMB);
    cudaFuncSetAttribute(mma_gemm<128, 128, 3, 0, 0, 2, 1>, cudaFuncAttributeMaxDynamicSharedMemorySize, SMA);
    cudaFuncSetAttribute(mma_gemm<128, 128, 3, 0, 0, 2, 0>, cudaFuncAttributeMaxDynamicSharedMemorySize, SMA);
    cudaFuncSetAttribute(mma_gemm<128, 128, 3, 0, 1, 0, 0>, cudaFuncAttributeMaxDynamicSharedMemorySize, SMA);
    cudaFuncSetAttribute(mma_gemm<128, 128, 3, 0, 2, 2, 0>, cudaFuncAttributeMaxDynamicSharedMemorySize, SMA);
    cudaFuncSetAttribute(mma_gemm<128, 128, 3, 0, 3, 0, 0>, cudaFuncAttributeMaxDynamicSharedMemorySize, SMA);

    // --- launches 0..2: GEMM2's only deps; GEMM2 is my launch #3 == ncu slot
    ln_in_kernel<<<BB * NT, 224>>>(emb1, emb2, emb3, lnall_g, lnall_b, ln1_g, ln1_b,
                                   Yh, Xh);
    tb16_k<<<dim3(KVd / 64, NT / 32, BB), 256>>>(Yh, Yth, NT, KVd);
    tb16_k<<<dim3(C2d / 64, NT / 32, BB), 256>>>(Xh, Xth, NT, C2d);

    // 2. Gt_b = Yt_b Xt_b^T  [1792,512], K=1024 (split out: Gt has corr spikes)
    mma_gemm<128, 128, 3, 0, 0, 1, 0><<<dim3(C2d / 128, KVd / 128, BB), 256, SMA>>>(
        Yth, Xth, nullptr, nullptr, Gth, Gtl, nullptr, nullptr,
        KVd, C2d, NT, NT, NT,
        (long)KVd * NT, (long)C2d * NT, (long)KVd * C2d, 0, 0, 1, 0, 0, 1.f);

    // weight prep
    tround_k<<<dim3(C2d / 64, C2d / 32, NHd), 256>>>(Wq, WqTh, C2d, C2d);
    tround_k<<<dim3(KVd / 64, KVd / 32, NHd), 256>>>(Wk, WkTh, KVd, KVd);
    tround_k<<<dim3(C2d / 64, C2d / 32, 1), 256>>>(Wout, WoTh, C2d, C2d);
    tround_k<<<dim3(C2E / 64, C2d / 32, 1), 256>>>(fc1_w, f1Th, C2d, C2E);
    tround_k<<<dim3(C2d / 64, C2E / 32, 1), 256>>>(fc2_w, f2Th, C2E, C2d);
    pround_k<<<4096, 256>>>(Wv, Wvh, (long)NHd * KVd * KVd / 4);

    // 3. T1[b,h] = WqT_h Gt_b^T  [512,1792], K=512  (B-split 2-pass, 2-stage)
    mma_gemm<128, 128, 2, 1, 0, 2, 0><<<dim3(KVd / 128, C2d / 128, BB * NHd), 256, SMB>>>(
        WqTh, Gth, Gtl, nullptr, T1h, nullptr, nullptr, nullptr,
        C2d, KVd, C2d, C2d, C2d,
        (long)C2d * C2d, (long)KVd * C2d, (long)C2d * KVd, 1, 2, 1, 0, 0, 1.f);

    // 4. S[b,h] = T1 WkT_h^T  [512,1792], K=1792 (fp16 out + fused stats partials)
    mma_gemm<128, 128, 3, 0, 0, 2, 1><<<dim3(KVd / 128, C2d / 128, BB * NHd), 256, SMA>>>(
        T1h, WkTh, nullptr, part, Sh, nullptr, nullptr, nullptr,
        C2d, KVd, KVd, KVd, KVd,
        (long)C2d * KVd, (long)KVd * KVd, (long)C2d * KVd, 0, 1, 1, 0, 0, 1.f);

    // 5-6. finish stats + row softmax
    stats2_kernel<<<BB * NHd, 32>>>(part, scl);
    softmax_kernel<<<BB * NHd * C2d, 224>>>(Sh, scl, Ph);

    // 7. Mmt_b[c,e] = (1/H) sum_h sum_k P[b,h,c,k] Wv_h[e,k]  [512,1792]
    mma_gemm<128, 128, 3, 0, 0, 2, 0><<<dim3(KVd / 128, C2d / 128, BB), 256, SMA>>>(
        Ph, Wvh, nullptr, nullptr, Mth, nullptr, nullptr, nullptr,
        C2d, KVd, KVd, KVd, KVd,
        (long)NHd * C2d * KVd, 0, (long)C2d * KVd, 0, 0,
        NHd, (long)C2d * KVd, (long)KVd * KVd, 1.f / NHd);

    // 8. ctx_b = Y_b Mmt_b^T  [1024,512], K=1792
    mma_gemm<128, 128, 3, 0, 0, 2, 0><<<dim3(C2d / 128, NT / 128, BB), 256, SMA>>>(
        Yh, Mth, nullptr, nullptr, Ch, nullptr, nullptr, nullptr,
        NT, C2d, KVd, KVd, KVd,
        (long)NT * KVd, (long)C2d * KVd, (long)NT * C2d, 0, 0, 1, 0, 0, 1.f);

    // 9. cx2 = ctx WoutT^T + emb2  [8192,512]
    mma_gemm<128, 128, 3, 0, 1, 0, 0><<<dim3(C2d / 128, BB * NT / 128, 1), 256, SMA>>>(
        Ch, WoTh, nullptr, cx2, nullptr, nullptr, nullptr, emb2,
        BB * NT, C2d, C2d, C2d, C2d, 0, 0, 0, 0, 0, 1, 0, 0, 1.f);

    // 10. Z = LN(cx2)
    ln2_kernel<<<BB * NT, 128>>>(cx2, lnffn_g, lnffn_b, Zh);

    // 11. F = gelu(Z f1T^T + b1)  [8192,2048]
    mma_gemm<128, 128, 3, 0, 2, 2, 0><<<dim3(C2E / 128, BB * NT / 128, 1), 256, SMA>>>(
        Zh, f1Th, nullptr, nullptr, Fh, nullptr, fc1_b, nullptr,
        BB * NT, C2E, C2d, C2d, C2d, 0, 0, 0, 0, 0, 1, 0, 0, 1.f);

    // 12. out = F f2T^T + b2 + cx2  [8192,512]
    mma_gemm<128, 128, 3, 0, 3, 0, 0><<<dim3(C2d / 128, BB * NT / 128, 1), 256, SMA>>>(
        Fh, f2Th, nullptr, out, nullptr, nullptr, fc2_b, cx2,
        BB * NT, C2d, C2E, C2E, C2E, 0, 0, 0, 0, 0, 1, 0, 0, 1.f);
}

// round 15
// speedup vs baseline: 5.4286x; 1.0752x over previous
#include <cuda_runtime.h>
#include <cuda_fp16.h>
#include <math.h>
#include <stdint.h>

// Problem constants
#define BB   8
#define NT   1024
#define C1d  256
#define C2d  512
#define C3d  1024
#define KVd  1792
#define NHd  4
#define C2E  2048

// ===================== scratch (device statics) ==============================
__device__ __half g_Yh [BB*NT*KVd];                       // LN(concat)  [b][n][kv]
__device__ __half g_Yth[BB*NT*KVd];                       // transposed  [b][kv][n]
__device__ __half g_Xh [BB*NT*C2d];                       // LN(emb2)    [b][n][c]
__device__ __half g_Xth[BB*NT*C2d];                       // transposed  [b][c][n]
__device__ __half g_Gth[BB*KVd*C2d], g_Gtl[BB*KVd*C2d];   // Gt split (spiky!)
__device__ __half g_T1h[BB*NHd*C2d*KVd];
__device__ __half g_Sh [BB*NHd*C2d*KVd];                  // scores fp16
__device__ __half g_Ph [BB*NHd*C2d*KVd];                  // probs
__device__ __half g_Mth[BB*C2d*KVd];                      // Mmt [b][c][e]
__device__ __half g_Ch [BB*NT*C2d];                       // ctx
__device__ float  g_cx2[BB*NT*C2d];                       // residual fp32
__device__ __half g_Zh [BB*NT*C2d];                       // LN(cx2)
__device__ __half g_Fh [BB*NT*C2E];                       // gelu(fc1)
// weights (pre-transposed + rounded to fp16)
__device__ __half g_WqTh[NHd*C2d*C2d];
__device__ __half g_WkTh[NHd*KVd*KVd];
__device__ __half g_Wvh [NHd*KVd*KVd];
__device__ __half g_WoTh[C2d*C2d];
__device__ __half g_f1Th[C2E*C2d];
__device__ __half g_f2Th[C2d*C2E];
__device__ float g_sc[BB*NHd];
__device__ float g_part[BB*NHd*56*2];

// ===================== PTX helpers (baseline sm_80+ only) ====================
__device__ __forceinline__ uint32_t smem_u32(const void* p) {
    uint32_t a;
    asm("{ .reg .u64 t; cvta.to.shared.u64 t, %1; cvt.u32.u64 %0, t; }" : "=r"(a) : "l"(p));
    return a;
}
#define CPA16(d, s)   asm volatile("cp.async.cg.shared.global [%0], [%1], 16;" :: "r"(d), "l"(s))
#define CPA_COMMIT()  asm volatile("cp.async.commit_group;" ::: "memory")
#define CPA_WAIT2()   asm volatile("cp.async.wait_group 2;" ::: "memory")
#define CPA_WAIT1()   asm volatile("cp.async.wait_group 1;" ::: "memory")
#define CPA_WAIT0()   asm volatile("cp.async.wait_group 0;" ::: "memory")

#define LDSM4(r, a) \
    asm volatile("ldmatrix.sync.aligned.m8n8.x4.shared.b16 {%0,%1,%2,%3}, [%4];" \
        : "=r"((r)[0]), "=r"((r)[1]), "=r"((r)[2]), "=r"((r)[3]) : "r"(a))

#define MMA16816(C, A, B0, B1) \
    asm volatile("mma.sync.aligned.m16n8k16.row.col.f32.f16.f16.f32 " \
        "{%0,%1,%2,%3}, {%4,%5,%6,%7}, {%8,%9}, {%0,%1,%2,%3};" \
        : "+f"((C)[0]), "+f"((C)[1]), "+f"((C)[2]), "+f"((C)[3]) \
        : "r"((A)[0]), "r"((A)[1]), "r"((A)[2]), "r"((A)[3]), "r"(B0), "r"(B1))

__device__ __forceinline__ void splt(float v, __half& h, __half& l) {
    h = __float2half_rn(v);
    l = __float2half_rn(v - __half2float(h));
}
__device__ __forceinline__ int selidx(int mode, int z) {
    return mode == 0 ? z : (mode == 1 ? (z & 3) : (z >> 2));
}

// block reductions (warp shuffle + tiny smem); fixed order -> deterministic
__device__ __forceinline__ float2 bred2(float s, float q, float* sh, int tid, int nw) {
#pragma unroll
    for (int o = 16; o; o >>= 1) {
        s += __shfl_xor_sync(0xffffffffu, s, o);
        q += __shfl_xor_sync(0xffffffffu, q, o);
    }
    if ((tid & 31) == 0) { sh[(tid >> 5) * 2] = s; sh[(tid >> 5) * 2 + 1] = q; }
    __syncthreads();
    float rs = 0.f, rq = 0.f;
    for (int j = 0; j < nw; ++j) { rs += sh[j * 2]; rq += sh[j * 2 + 1]; }
    __syncthreads();
    return make_float2(rs, rq);
}
__device__ __forceinline__ float bmax(float v, float* sh, int tid, int nw) {
#pragma unroll
    for (int o = 16; o; o >>= 1) v = fmaxf(v, __shfl_xor_sync(0xffffffffu, v, o));
    if ((tid & 31) == 0) sh[tid >> 5] = v;
    __syncthreads();
    float r = sh[0];
    for (int j = 1; j < nw; ++j) r = fmaxf(r, sh[j]);
    __syncthreads();
    return r;
}

// ===================== mma.sync fp16 GEMM ====================================
// C[M,Nn] = outScale * sum_h A_h[M,K] * B_h[N,K]^T  (+ epilogue)
// BM: CTA M-tile; N-tile 128. Warp layout 4(M) x 2(N). STG: pipeline stages.
// MODE: 0 -> 1-pass (A,B fp16-rounded);  1 -> 2-pass B-split (A*Bh + A*Bl)
// EPI: 0 none, 1 +add, 2 +bias,gelu, 3 +bias+add.
// OUT: 0 fp32, 1 fp16 hi+lo, 2 fp16 rounded
// STATS: 1 -> per-CTA sum/sumsq of outputs -> C (as partials buffer)
// smem row stride 2*BKE+16 B -> mod 128 = 16, conflict-free ldmatrix cycling.
// BK64 + 3 stages keeps the stage at 36.9 KB -> 110.6 KB/CTA -> 2 CTAs/SM.
template<int BM, int BKE, int STG, int MODE, int EPI, int OUT, int STATS>
__global__ __launch_bounds__(256, 2)
void mma_gemm(const __half* __restrict__ Ahi,
              const __half* __restrict__ Bhi, const __half* __restrict__ Blo,
              float* __restrict__ C, __half* __restrict__ Chi, __half* __restrict__ Clo,
              const float* __restrict__ bias, const float* __restrict__ addp,
              int M, int Nn, int K, int lda, int ldb,
              long sA, long sB, long sC, int selA, int selB,
              int nH, long hA, long hB, float outScale)
{
    constexpr int PADB  = 2 * BKE + 16;
    constexpr int TILEA = BM * PADB;
    constexpr int TILEB = 128 * PADB;
    constexpr uint32_t STB = TILEA + (1 + MODE) * TILEB;   // stage bytes
    constexpr int SEGS  = BKE / 8;                         // 16B segments per row
    constexpr int RSTEP = 256 / SEGS;                      // rows staged per iter
    constexpr int KSN   = BKE / 16;
    constexpr int MF    = BM / 64;                         // 16-row frags per warp

    extern __shared__ char smem[];
    const uint32_t sb = smem_u32(smem);
    const int tid = threadIdx.x, wid = tid >> 5, lane = tid & 31;
    const int z = blockIdx.z;
    const int m0 = blockIdx.y * BM, n0 = blockIdx.x * 128;
    const int warpM = (wid & 3) * (BM / 4), warpN = (wid >> 2) * 64;

    const __half* A0h = Ahi + (long)selidx(selA, z) * sA;
    const __half* B0h = Bhi + (long)selidx(selB, z) * sB;
    const __half* B0l = (MODE == 1) ? (Blo + (long)selidx(selB, z) * sB) : nullptr;

    const int nchK = K / BKE;
    const int nch  = nH * nchK;

    const int srow = tid / SEGS;
    const int sseg = tid % SEGS;

    auto issue = [&](int ch, int buf) {
        const uint32_t so = sb + (uint32_t)buf * STB;
        const int h  = ch / nchK;
        const int k0 = (ch - h * nchK) * BKE;
        {   // A tile: BM rows
            const __half* gb = A0h + (long)h * hA + (long)(m0 + srow) * lda + k0 + sseg * 8;
            const uint32_t tb = so + srow * PADB + sseg * 16;
#pragma unroll
            for (int j = 0; j < BM / RSTEP; ++j)
                CPA16(tb + j * RSTEP * PADB, gb + (long)(j * RSTEP) * lda);
        }
        {   // Bh tile: 128 rows
            const __half* gb = B0h + (long)h * hB + (long)(n0 + srow) * ldb + k0 + sseg * 8;
            const uint32_t tb = so + TILEA + srow * PADB + sseg * 16;
#pragma unroll
            for (int j = 0; j < 128 / RSTEP; ++j)
                CPA16(tb + j * RSTEP * PADB, gb + (long)(j * RSTEP) * ldb);
        }
        if (MODE == 1) {
            const __half* gb = B0l + (long)h * hB + (long)(n0 + srow) * ldb + k0 + sseg * 8;
            const uint32_t tb = so + TILEA + TILEB + srow * PADB + sseg * 16;
#pragma unroll
            for (int j = 0; j < 128 / RSTEP; ++j)
                CPA16(tb + j * RSTEP * PADB, gb + (long)(j * RSTEP) * ldb);
        }
        CPA_COMMIT();
    };

    float acc[MF][8][4];
#pragma unroll
    for (int i = 0; i < MF; ++i)
#pragma unroll
        for (int j = 0; j < 8; ++j)
#pragma unroll
            for (int k = 0; k < 4; ++k) acc[i][j][k] = 0.f;

#pragma unroll
    for (int p = 0; p < STG; ++p) issue(p, p);

    const uint32_t aRow = (uint32_t)(warpM + (lane & 15)) * PADB + ((lane >> 4) << 4);
    const uint32_t bRow = (uint32_t)(warpN + ((lane >> 4) << 3) + (lane & 7)) * PADB
                        + (((lane >> 3) & 1) << 4);

    int buf = 0;
    for (int ch = 0; ch < nch; ++ch) {
        const int rem = nch - 1 - ch;         // groups still pending beyond ch
        if (STG == 3) {
            if (rem >= 2) { CPA_WAIT2(); } else if (rem == 1) { CPA_WAIT1(); } else { CPA_WAIT0(); }
        } else {
            if (rem >= 1) { CPA_WAIT1(); } else { CPA_WAIT0(); }
        }
        __syncthreads();
        const uint32_t so = sb + (uint32_t)buf * STB;
#pragma unroll
        for (int ks = 0; ks < KSN; ++ks) {
            const uint32_t kb = ks * 32;
            uint32_t ah[MF][4], bh[4][4], bl[4][4];
#pragma unroll
            for (int mf = 0; mf < MF; ++mf)
                LDSM4(ah[mf], so + aRow + (uint32_t)(mf * 16 * PADB) + kb);
#pragma unroll
            for (int q = 0; q < 4; ++q) {
                const uint32_t bd = so + TILEA + bRow + (uint32_t)(q * 16 * PADB) + kb;
                LDSM4(bh[q], bd);
                if (MODE == 1) LDSM4(bl[q], bd + TILEB);
            }
#pragma unroll
            for (int mf = 0; mf < MF; ++mf)
#pragma unroll
                for (int nf = 0; nf < 8; ++nf) {
                    MMA16816(acc[mf][nf], ah[mf],
                             bh[nf >> 1][(nf & 1) * 2], bh[nf >> 1][(nf & 1) * 2 + 1]);
                    if (MODE == 1)
                        MMA16816(acc[mf][nf], ah[mf],
                                 bl[nf >> 1][(nf & 1) * 2], bl[nf >> 1][(nf & 1) * 2 + 1]);
                }
        }
        __syncthreads();
        if (ch + STG < nch) issue(ch + STG, buf);
        buf = (buf + 1 == STG) ? 0 : buf + 1;
    }

    // ---- epilogue (register accumulators -> gmem)
    const int rbase = m0 + warpM + (lane >> 2);
    const int cbase = n0 + warpN + (lane & 3) * 2;
    float ssum = 0.f, ssq = 0.f;
#pragma unroll
    for (int mf = 0; mf < MF; ++mf) {
#pragma unroll
        for (int h2 = 0; h2 < 2; ++h2) {
            const long m = rbase + mf * 16 + h2 * 8;
#pragma unroll
            for (int nf = 0; nf < 8; ++nf) {
                const long col = cbase + nf * 8;
                float v0 = acc[mf][nf][h2 * 2]     * outScale;
                float v1 = acc[mf][nf][h2 * 2 + 1] * outScale;
                if (EPI == 1) {
                    const float2 ad = *(const float2*)(addp + m * Nn + col);
                    v0 += ad.x; v1 += ad.y;
                }
                if (EPI == 2) {
                    v0 += bias[col]; v1 += bias[col + 1];
                    v0 = 0.5f * v0 * (1.f + erff(v0 * 0.70710678118654752f));
                    v1 = 0.5f * v1 * (1.f + erff(v1 * 0.70710678118654752f));
                }
                if (EPI == 3) {
                    const float2 ad = *(const float2*)(addp + m * Nn + col);
                    v0 += bias[col]     + ad.x;
                    v1 += bias[col + 1] + ad.y;
                }
                if (STATS) { ssum += v0 + v1; ssq += v0 * v0 + v1 * v1; }
                const long idx = (long)z * sC + m * Nn + col;
                if (OUT == 0) {
                    *(float2*)(C + idx) = make_float2(v0, v1);
                } else if (OUT == 1) {
                    __half h0, l0, h1, l1;
                    splt(v0, h0, l0); splt(v1, h1, l1);
                    *(__half2*)(Chi + idx) = __halves2half2(h0, h1);
                    *(__half2*)(Clo + idx) = __halves2half2(l0, l1);
                } else {
                    *(__half2*)(Chi + idx) =
                        __halves2half2(__float2half_rn(v0), __float2half_rn(v1));
                }
            }
        }
    }
    if (STATS) {
        __shared__ float sred[16];
        float s = ssum, q = ssq;
#pragma unroll
        for (int o = 16; o; o >>= 1) {
            s += __shfl_xor_sync(0xffffffffu, s, o);
            q += __shfl_xor_sync(0xffffffffu, q, o);
        }
        if (lane == 0) { sred[wid * 2] = s; sred[wid * 2 + 1] = q; }
        __syncthreads();
        if (tid == 0) {
            float rs = 0.f, rq = 0.f;
#pragma unroll
            for (int j = 0; j < 8; ++j) { rs += sred[j * 2]; rq += sred[j * 2 + 1]; }
            const long t = (long)z * (gridDim.x * gridDim.y)
                         + blockIdx.y * gridDim.x + blockIdx.x;
            C[t * 2] = rs; C[t * 2 + 1] = rq;
        }
    }
}

// ===================== prep kernels (vectorized) =============================
// fp32 [Z][R][C] -> fp16 [Z][C][R] (rounded), 32x64 tiles, 16B transactions
__global__ __launch_bounds__(256)
void tround_k(const float* __restrict__ in, __half* __restrict__ oh, int R, int Cc)
{
    __shared__ float t[32][65];
    const long zo = (long)blockIdx.z * R * Cc;
    const int c0 = blockIdx.x * 64, r0 = blockIdx.y * 32;
    const int tid = threadIdx.x;
#pragma unroll
    for (int it = 0; it < 2; ++it) {
        const int idx = tid + it * 256;
        const int r = idx >> 4, cs = idx & 15;
        const float4 v = *(const float4*)(in + zo + (long)(r0 + r) * Cc + c0 + cs * 4);
        t[r][cs * 4 + 0] = v.x; t[r][cs * 4 + 1] = v.y;
        t[r][cs * 4 + 2] = v.z; t[r][cs * 4 + 3] = v.w;
    }
    __syncthreads();
    const int c = tid >> 2, rs = tid & 3;
    __align__(16) __half hh[8];
#pragma unroll
    for (int j = 0; j < 8; ++j) hh[j] = __float2half_rn(t[rs * 8 + j][c]);
    *(uint4*)&oh[zo + (long)(c0 + c) * R + r0 + rs * 8] = *(uint4*)hh;
}

// fp32 -> fp16 rounded (same layout)
__global__ void pround_k(const float* __restrict__ in, __half* __restrict__ oh, long n4)
{
    for (long i = blockIdx.x * blockDim.x + threadIdx.x; i < n4; i += (long)gridDim.x * blockDim.x) {
        float4 v = ((const float4*)in)[i];
        __half hh[4] = { __float2half_rn(v.x), __float2half_rn(v.y),
                         __float2half_rn(v.z), __float2half_rn(v.w) };
        ((uint2*)oh)[i] = *(uint2*)hh;
    }
}

// fp16 [Z][R][C] -> [Z][C][R], 32x64 tiles, 16B transactions
__global__ __launch_bounds__(256)
void tb16_k(const __half* __restrict__ in, __half* __restrict__ out, int R, int Cc)
{
    __shared__ __half t[32][72];
    const long zo = (long)blockIdx.z * R * Cc;
    const int c0 = blockIdx.x * 64, r0 = blockIdx.y * 32;
    const int tid = threadIdx.x;
    {
        const int r = tid >> 3, cs = tid & 7;
        __align__(16) __half v[8];
        *(uint4*)v = *(const uint4*)(in + zo + (long)(r0 + r) * Cc + c0 + cs * 8);
#pragma unroll
        for (int j = 0; j < 8; ++j) t[r][cs * 8 + j] = v[j];
    }
    __syncthreads();
    const int c = tid >> 2, rs = tid & 3;
    __align__(16) __half o8[8];
#pragma unroll
    for (int j = 0; j < 8; ++j) o8[j] = t[rs * 8 + j][c];
    *(uint4*)&out[zo + (long)(c0 + c) * R + r0 + rs * 8] = *(uint4*)o8;
}

// input LayerNorms -> rounded fp16 outputs (224 thr: 448 float4 = 1792 elems)
__global__ __launch_bounds__(224)
void ln_in_kernel(const float* __restrict__ e1, const float* __restrict__ e2,
                  const float* __restrict__ e3,
                  const float* __restrict__ ag, const float* __restrict__ ab,
                  const float* __restrict__ g1, const float* __restrict__ b1,
                  __half* __restrict__ Yh, __half* __restrict__ Xh)
{
    const long row = blockIdx.x;
    const int  tid = threadIdx.x;
    const float4* p1 = (const float4*)(e1 + row * C1d);
    const float4* p2 = (const float4*)(e2 + row * C2d);
    const float4* p3 = (const float4*)(e3 + row * C3d);
    __shared__ float sh[16];

    const int f0 = tid, f1 = tid + 224;
    const bool isX = (f0 >= 64) && (f0 < 192);
    float4 a = (f0 < 64) ? p1[f0] : (isX ? p2[f0 - 64] : p3[f0 - 192]);
    float4 b = p3[f1 - 192];

    float s = a.x + a.y + a.z + a.w + b.x + b.y + b.z + b.w;
    float q = a.x * a.x + a.y * a.y + a.z * a.z + a.w * a.w
            + b.x * b.x + b.y * b.y + b.z * b.z + b.w * b.w;
    float2 r = bred2(s, q, sh, tid, 7);
    float mean = r.x * (1.f / KVd);
    float inv  = rsqrtf(r.y * (1.f / KVd) - mean * mean + 1e-6f);

    const float4* g4 = (const float4*)ag;
    const float4* b4 = (const float4*)ab;
    {
        const float4 ga = g4[f0], ba = b4[f0];
        __half hh[4];
        hh[0] = __float2half_rn((a.x - mean) * inv * ga.x + ba.x);
        hh[1] = __float2half_rn((a.y - mean) * inv * ga.y + ba.y);
        hh[2] = __float2half_rn((a.z - mean) * inv * ga.z + ba.z);
        hh[3] = __float2half_rn((a.w - mean) * inv * ga.w + ba.w);
        *(uint2*)&Yh[row * KVd + f0 * 4] = *(uint2*)hh;
        const float4 gb = g4[f1], bb = b4[f1];
        hh[0] = __float2half_rn((b.x - mean) * inv * gb.x + bb.x);
        hh[1] = __float2half_rn((b.y - mean) * inv * gb.y + bb.y);
        hh[2] = __float2half_rn((b.z - mean) * inv * gb.z + bb.z);
        hh[3] = __float2half_rn((b.w - mean) * inv * gb.w + bb.w);
        *(uint2*)&Yh[row * KVd + f1 * 4] = *(uint2*)hh;
    }

    // X = LN(emb2): chunk0 of threads 64..191 covers e2 exactly
    float sX = isX ? (a.x + a.y + a.z + a.w) : 0.f;
    float qX = isX ? (a.x * a.x + a.y * a.y + a.z * a.z + a.w * a.w) : 0.f;
    float2 rX = bred2(sX, qX, sh, tid, 7);
    if (isX) {
        float meanX = rX.x * (1.f / C2d);
        float invX  = rsqrtf(rX.y * (1.f / C2d) - meanX * meanX + 1e-6f);
        const int fx = f0 - 64;
        const float4 gx = ((const float4*)g1)[fx], bx = ((const float4*)b1)[fx];
        __half hh[4];
        hh[0] = __float2half_rn((a.x - meanX) * invX * gx.x + bx.x);
        hh[1] = __float2half_rn((a.y - meanX) * invX * gx.y + bx.y);
        hh[2] = __float2half_rn((a.z - meanX) * invX * gx.z + bx.z);
        hh[3] = __float2half_rn((a.w - meanX) * invX * gx.w + bx.w);
        *(uint2*)&Xh[row * C2d + fx * 4] = *(uint2*)hh;
    }
}

__global__ __launch_bounds__(128)
void ln2_kernel(const float* __restrict__ in,
                const float* __restrict__ g, const float* __restrict__ b,
                __half* __restrict__ Zh)
{
    const long row = blockIdx.x;
    const int  tid = threadIdx.x;
    __shared__ float sh[8];
    const float4 v = ((const float4*)(in + row * C2d))[tid];
    float s = v.x + v.y + v.z + v.w;
    float q = v.x * v.x + v.y * v.y + v.z * v.z + v.w * v.w;
    float2 r = bred2(s, q, sh, tid, 4);
    float mean = r.x * (1.f / C2d);
    float inv  = rsqrtf(r.y * (1.f / C2d) - mean * mean + 1e-6f);
    const float4 gg = ((const float4*)g)[tid], bb = ((const float4*)b)[tid];
    __half hh[4];
    hh[0] = __float2half_rn((v.x - mean) * inv * gg.x + bb.x);
    hh[1] = __float2half_rn((v.y - mean) * inv * gg.y + bb.y);
    hh[2] = __float2half_rn((v.z - mean) * inv * gg.z + bb.z);
    hh[3] = __float2half_rn((v.w - mean) * inv * gg.w + bb.w);
    *(uint2*)&Zh[row * C2d + tid * 4] = *(uint2*)hh;
}

// finish per-map variance from 56 per-tile partials -> softmax scale
__global__ __launch_bounds__(32)
void stats2_kernel(const float* __restrict__ part, float* __restrict__ scale)
{
    const int z = blockIdx.x, lane = threadIdx.x;
    float s = 0.f, q = 0.f;
#pragma unroll
    for (int j = 0; j < 2; ++j) {
        const int i = lane + j * 32;
        if (i < 56) { s += part[((long)z * 56 + i) * 2]; q += part[((long)z * 56 + i) * 2 + 1]; }
    }
#pragma unroll
    for (int o = 16; o; o >>= 1) {
        s += __shfl_xor_sync(0xffffffffu, s, o);
        q += __shfl_xor_sync(0xffffffffu, q, o);
    }
    if (lane == 0) {
        const float cnt = (float)(C2d * KVd);
        float mean = s / cnt;
        float var  = q / cnt - mean * mean;
        float a    = rsqrtf((float)KVd);
        scale[z]   = a * rsqrtf(a * a * var + 1e-5f);
    }
}

__global__ __launch_bounds__(224)
void softmax_kernel(const __half* __restrict__ Sh, const float* __restrict__ scale,
                    __half* __restrict__ Ph)
{
    const long row = blockIdx.x;
    const int  tid = threadIdx.x;
    const __half* p = Sh + row * KVd;
    const float sc = scale[blockIdx.x >> 9];
    __shared__ float sh[16];

    __align__(16) __half v8[8];
    *(uint4*)v8 = *(const uint4*)(p + tid * 8);
    float f[8];
#pragma unroll
    for (int j = 0; j < 8; ++j) f[j] = __half2float(v8[j]);
    float mx = f[0];
#pragma unroll
    for (int j = 1; j < 8; ++j) mx = fmaxf(mx, f[j]);
    mx = bmax(mx, sh, tid, 7);

    float e[8], s = 0.f;
#pragma unroll
    for (int j = 0; j < 8; ++j) { e[j] = __expf((f[j] - mx) * sc); s += e[j]; }
    float2 r = bred2(s, 0.f, sh, tid, 7);
    const float inv = 1.f / r.x;

#pragma unroll
    for (int j = 0; j < 8; ++j) v8[j] = __float2half_rn(e[j] * inv);
    *(uint4*)&Ph[row * KVd + tid * 8] = *(uint4*)v8;
}

// ===================== launcher =============================================
#define SYM(v, t, s) t* v; { void* _p; cudaGetSymbolAddress(&_p, s); v = (t*)_p; }

extern "C" void kernel_launch(void* const* d_in, const int* in_sizes, int n_in,
                              void* d_out, int out_size)
{
    const float* emb1    = (const float*)d_in[0];
    const float* emb2    = (const float*)d_in[1];
    const float* emb3    = (const float*)d_in[2];
    const float* Wq      = (const float*)d_in[3];
    const float* Wk      = (const float*)d_in[4];
    const float* Wv      = (const float*)d_in[5];
    const float* Wout    = (const float*)d_in[6];
    const float* ln1_g   = (const float*)d_in[7];
    const float* ln1_b   = (const float*)d_in[8];
    const float* lnall_g = (const float*)d_in[9];
    const float* lnall_b = (const float*)d_in[10];
    const float* lnffn_g = (const float*)d_in[11];
    const float* lnffn_b = (const float*)d_in[12];
    const float* fc1_w   = (const float*)d_in[13];
    const float* fc1_b   = (const float*)d_in[14];
    const float* fc2_w   = (const float*)d_in[15];
    const float* fc2_b   = (const float*)d_in[16];
    float* out = (float*)d_out;

    SYM(Yh, __half, g_Yh)   SYM(Yth, __half, g_Yth)
    SYM(Xh, __half, g_Xh)   SYM(Xth, __half, g_Xth)
    SYM(Gth, __half, g_Gth) SYM(Gtl, __half, g_Gtl)
    SYM(T1h, __half, g_T1h)
    SYM(Sh, __half, g_Sh)
    SYM(Ph, __half, g_Ph)
    SYM(Mth, __half, g_Mth)
    SYM(Ch, __half, g_Ch)
    SYM(cx2, float, g_cx2)
    SYM(Zh, __half, g_Zh)
    SYM(Fh, __half, g_Fh)
    SYM(WqTh, __half, g_WqTh)
    SYM(WkTh, __half, g_WkTh)
    SYM(Wvh, __half, g_Wvh)
    SYM(WoTh, __half, g_WoTh)
    SYM(f1Th, __half, g_f1Th)
    SYM(f2Th, __half, g_f2Th)
    SYM(scl, float, g_sc)     SYM(part, float, g_part)

    const int SMA = 3 * ((128 + 128) * (2 * 64 + 16));   // 110592 B: BK64 3-stage 1-pass -> 2 CTAs/SM
    const int SMB = 2 * ((128 + 256) * (2 * 64 + 16));   // 110592 B: BK64 2-stage 2-pass -> 2 CTAs/SM
    cudaFuncSetAttribute(mma_gemm<128, 64, 3, 0, 0, 1, 0>, cudaFuncAttributeMaxDynamicSharedMemorySize, SMA);
    cudaFuncSetAttribute(mma_gemm<128, 64, 2, 1, 0, 2, 0>, cudaFuncAttributeMaxDynamicSharedMemorySize, SMB);
    cudaFuncSetAttribute(mma_gemm<128, 64, 3, 0, 0, 2, 1>, cudaFuncAttributeMaxDynamicSharedMemorySize, SMA);
    cudaFuncSetAttribute(mma_gemm<128, 64, 3, 0, 0, 2, 0>, cudaFuncAttributeMaxDynamicSharedMemorySize, SMA);
    cudaFuncSetAttribute(mma_gemm<128, 64, 3, 0, 1, 0, 0>, cudaFuncAttributeMaxDynamicSharedMemorySize, SMA);
    cudaFuncSetAttribute(mma_gemm<128, 64, 3, 0, 2, 2, 0>, cudaFuncAttributeMaxDynamicSharedMemorySize, SMA);
    cudaFuncSetAttribute(mma_gemm<128, 64, 3, 0, 3, 0, 0>, cudaFuncAttributeMaxDynamicSharedMemorySize, SMA);

    // --- launches 0..2: GEMM2's only deps; GEMM2 is my launch #3 == ncu slot
    ln_in_kernel<<<BB * NT, 224>>>(emb1, emb2, emb3, lnall_g, lnall_b, ln1_g, ln1_b,
                                   Yh, Xh);
    tb16_k<<<dim3(KVd / 64, NT / 32, BB), 256>>>(Yh, Yth, NT, KVd);
    tb16_k<<<dim3(C2d / 64, NT / 32, BB), 256>>>(Xh, Xth, NT, C2d);

    // 2. Gt_b = Yt_b Xt_b^T  [1792,512], K=1024 (split out: Gt has corr spikes)
    mma_gemm<128, 64, 3, 0, 0, 1, 0><<<dim3(C2d / 128, KVd / 128, BB), 256, SMA>>>(
        Yth, Xth, nullptr, nullptr, Gth, Gtl, nullptr, nullptr,
        KVd, C2d, NT, NT, NT,
        (long)KVd * NT, (long)C2d * NT, (long)KVd * C2d, 0, 0, 1, 0, 0, 1.f);

    // weight prep
    tround_k<<<dim3(C2d / 64, C2d / 32, NHd), 256>>>(Wq, WqTh, C2d, C2d);
    tround_k<<<dim3(KVd / 64, KVd / 32, NHd), 256>>>(Wk, WkTh, KVd, KVd);
    tround_k<<<dim3(C2d / 64, C2d / 32, 1), 256>>>(Wout, WoTh, C2d, C2d);
    tround_k<<<dim3(C2E / 64, C2d / 32, 1), 256>>>(fc1_w, f1Th, C2d, C2E);
    tround_k<<<dim3(C2d / 64, C2E / 32, 1), 256>>>(fc2_w, f2Th, C2E, C2d);
    pround_k<<<4096, 256>>>(Wv, Wvh, (long)NHd * KVd * KVd / 4);

    // 3. T1[b,h] = WqT_h Gt_b^T  [512,1792], K=512  (B-split 2-pass, 2-stage)
    mma_gemm<128, 64, 2, 1, 0, 2, 0><<<dim3(KVd / 128, C2d / 128, BB * NHd), 256, SMB>>>(
        WqTh, Gth, Gtl, nullptr, T1h, nullptr, nullptr, nullptr,
        C2d, KVd, C2d, C2d, C2d,
        (long)C2d * C2d, (long)KVd * C2d, (long)C2d * KVd, 1, 2, 1, 0, 0, 1.f);

    // 4. S[b,h] = T1 WkT_h^T  [512,1792], K=1792 (fp16 out + fused stats partials)
    mma_gemm<128, 64, 3, 0, 0, 2, 1><<<dim3(KVd / 128, C2d / 128, BB * NHd), 256, SMA>>>(
        T1h, WkTh, nullptr, part, Sh, nullptr, nullptr, nullptr,
        C2d, KVd, KVd, KVd, KVd,
        (long)C2d * KVd, (long)KVd * KVd, (long)C2d * KVd, 0, 1, 1, 0, 0, 1.f);

    // 5-6. finish stats + row softmax
    stats2_kernel<<<BB * NHd, 32>>>(part, scl);
    softmax_kernel<<<BB * NHd * C2d, 224>>>(Sh, scl, Ph);

    // 7. Mmt_b[c,e] = (1/H) sum_h sum_k P[b,h,c,k] Wv_h[e,k]  [512,1792]
    mma_gemm<128, 64, 3, 0, 0, 2, 0><<<dim3(KVd / 128, C2d / 128, BB), 256, SMA>>>(
        Ph, Wvh, nullptr, nullptr, Mth, nullptr, nullptr, nullptr,
        C2d, KVd, KVd, KVd, KVd,
        (long)NHd * C2d * KVd, 0, (long)C2d * KVd, 0, 0,
        NHd, (long)C2d * KVd, (long)KVd * KVd, 1.f / NHd);

    // 8. ctx_b = Y_b Mmt_b^T  [1024,512], K=1792
    mma_gemm<128, 64, 3, 0, 0, 2, 0><<<dim3(C2d / 128, NT / 128, BB), 256, SMA>>>(
        Yh, Mth, nullptr, nullptr, Ch, nullptr, nullptr, nullptr,
        NT, C2d, KVd, KVd, KVd,
        (long)NT * KVd, (long)C2d * KVd, (long)NT * C2d, 0, 0, 1, 0, 0, 1.f);

    // 9. cx2 = ctx WoutT^T + emb2  [8192,512]
    mma_gemm<128, 64, 3, 0, 1, 0, 0><<<dim3(C2d / 128, BB * NT / 128, 1), 256, SMA>>>(
        Ch, WoTh, nullptr, cx2, nullptr, nullptr, nullptr, emb2,
        BB * NT, C2d, C2d, C2d, C2d, 0, 0, 0, 0, 0, 1, 0, 0, 1.f);

    // 10. Z = LN(cx2)
    ln2_kernel<<<BB * NT, 128>>>(cx2, lnffn_g, lnffn_b, Zh);

    // 11. F = gelu(Z f1T^T + b1)  [8192,2048]
    mma_gemm<128, 64, 3, 0, 2, 2, 0><<<dim3(C2E / 128, BB * NT / 128, 1), 256, SMA>>>(
        Zh, f1Th, nullptr, nullptr, Fh, nullptr, fc1_b, nullptr,
        BB * NT, C2E, C2d, C2d, C2d, 0, 0, 0, 0, 0, 1, 0, 0, 1.f);

    // 12. out = F f2T^T + b2 + cx2  [8192,512]
    mma_gemm<128, 64, 3, 0, 3, 0, 0><<<dim3(C2d / 128, BB * NT / 128, 1), 256, SMA>>>(
        Fh, f2Th, nullptr, out, nullptr, nullptr, fc2_b, cx2,
        BB * NT, C2d, C2E, C2E, C2E, 0, 0, 0, 0, 0, 1, 0, 0, 1.f);
}

// round 16
// speedup vs baseline: 5.7355x; 1.0565x over previous
#include <cuda_runtime.h>
#include <cuda_fp16.h>
#include <math.h>
#include <stdint.h>

// Problem constants
#define BB   8
#define NT   1024
#define C1d  256
#define C2d  512
#define C3d  1024
#define KVd  1792
#define NHd  4
#define C2E  2048

// ===================== scratch (device statics) ==============================
__device__ __half g_Yh [BB*NT*KVd];                       // LN(concat)  [b][n][kv]
__device__ __half g_Yth[BB*NT*KVd];                       // transposed  [b][kv][n]
__device__ __half g_Xh [BB*NT*C2d];                       // LN(emb2)    [b][n][c]
__device__ __half g_Xth[BB*NT*C2d];                       // transposed  [b][c][n]
__device__ __half g_Gth[BB*KVd*C2d], g_Gtl[BB*KVd*C2d];   // Gt split (spiky!)
__device__ __half g_T1h[BB*NHd*C2d*KVd];
__device__ __half g_Sh [BB*NHd*C2d*KVd];                  // scores fp16
__device__ __half g_Ph [BB*NHd*C2d*KVd];                  // probs
__device__ __half g_Mth[BB*C2d*KVd];                      // Mmt [b][c][e]
__device__ __half g_Ch [BB*NT*C2d];                       // ctx
__device__ float  g_cx2[BB*NT*C2d];                       // residual fp32
__device__ __half g_Zh [BB*NT*C2d];                       // LN(cx2)
__device__ __half g_Fh [BB*NT*C2E];                       // gelu(fc1)
// weights (pre-transposed + rounded to fp16)
__device__ __half g_WqTh[NHd*C2d*C2d];
__device__ __half g_WkTh[NHd*KVd*KVd];
__device__ __half g_Wvh [NHd*KVd*KVd];
__device__ __half g_WoTh[C2d*C2d];
__device__ __half g_f1Th[C2E*C2d];
__device__ __half g_f2Th[C2d*C2E];
__device__ float g_sc[BB*NHd];
__device__ float g_part[BB*NHd*56*2];

// ===================== PTX helpers (baseline sm_80+ only) ====================
__device__ __forceinline__ uint32_t smem_u32(const void* p) {
    uint32_t a;
    asm("{ .reg .u64 t; cvta.to.shared.u64 t, %1; cvt.u32.u64 %0, t; }" : "=r"(a) : "l"(p));
    return a;
}
#define CPA16(d, s)   asm volatile("cp.async.cg.shared.global [%0], [%1], 16;" :: "r"(d), "l"(s))
#define CPA_COMMIT()  asm volatile("cp.async.commit_group;" ::: "memory")
#define CPA_WAIT2()   asm volatile("cp.async.wait_group 2;" ::: "memory")
#define CPA_WAIT1()   asm volatile("cp.async.wait_group 1;" ::: "memory")
#define CPA_WAIT0()   asm volatile("cp.async.wait_group 0;" ::: "memory")

#define LDSM4(r, a) \
    asm volatile("ldmatrix.sync.aligned.m8n8.x4.shared.b16 {%0,%1,%2,%3}, [%4];" \
        : "=r"((r)[0]), "=r"((r)[1]), "=r"((r)[2]), "=r"((r)[3]) : "r"(a))

#define MMA16816(C, A, B0, B1) \
    asm volatile("mma.sync.aligned.m16n8k16.row.col.f32.f16.f16.f32 " \
        "{%0,%1,%2,%3}, {%4,%5,%6,%7}, {%8,%9}, {%0,%1,%2,%3};" \
        : "+f"((C)[0]), "+f"((C)[1]), "+f"((C)[2]), "+f"((C)[3]) \
        : "r"((A)[0]), "r"((A)[1]), "r"((A)[2]), "r"((A)[3]), "r"(B0), "r"(B1))

__device__ __forceinline__ void splt(float v, __half& h, __half& l) {
    h = __float2half_rn(v);
    l = __float2half_rn(v - __half2float(h));
}
__device__ __forceinline__ int selidx(int mode, int z) {
    return mode == 0 ? z : (mode == 1 ? (z & 3) : (z >> 2));
}

// block reductions (warp shuffle + tiny smem); fixed order -> deterministic
__device__ __forceinline__ float2 bred2(float s, float q, float* sh, int tid, int nw) {
#pragma unroll
    for (int o = 16; o; o >>= 1) {
        s += __shfl_xor_sync(0xffffffffu, s, o);
        q += __shfl_xor_sync(0xffffffffu, q, o);
    }
    if ((tid & 31) == 0) { sh[(tid >> 5) * 2] = s; sh[(tid >> 5) * 2 + 1] = q; }
    __syncthreads();
    float rs = 0.f, rq = 0.f;
    for (int j = 0; j < nw; ++j) { rs += sh[j * 2]; rq += sh[j * 2 + 1]; }
    __syncthreads();
    return make_float2(rs, rq);
}
__device__ __forceinline__ float bmax(float v, float* sh, int tid, int nw) {
#pragma unroll
    for (int o = 16; o; o >>= 1) v = fmaxf(v, __shfl_xor_sync(0xffffffffu, v, o));
    if ((tid & 31) == 0) sh[tid >> 5] = v;
    __syncthreads();
    float r = sh[0];
    for (int j = 1; j < nw; ++j) r = fmaxf(r, sh[j]);
    __syncthreads();
    return r;
}

// ===================== mma.sync fp16 GEMM ====================================
// C[M,Nn] = outScale * sum_h A_h[M,K] * B_h[N,K]^T  (+ epilogue)
// NTHR=128: 4 warps, 2(M)x2(N), warp tile 64x64 (0.0625 B/MAC smem traffic)
// NTHR=256: 8 warps, 4(M)x2(N), warp tile (BM/4)x64
// MODE: 0 -> 1-pass (A,B fp16-rounded);  1 -> 2-pass B-split (A*Bh + A*Bl)
// EPI: 0 none, 1 +add, 2 +bias,gelu, 3 +bias+add.
// OUT: 0 fp32, 1 fp16 hi+lo, 2 fp16 rounded
// STATS: 1 -> per-CTA sum/sumsq of outputs -> C (as partials buffer)
// smem row stride 2*BKE+16 B -> mod 128 = 16, conflict-free ldmatrix cycling.
// BK64 stages (36.9 KB) -> 110.6 KB/CTA -> 2 CTAs/SM.
template<int BM, int BKE, int STG, int MODE, int EPI, int OUT, int STATS, int NTHR>
__global__ __launch_bounds__(NTHR, 2)
void mma_gemm(const __half* __restrict__ Ahi,
              const __half* __restrict__ Bhi, const __half* __restrict__ Blo,
              float* __restrict__ C, __half* __restrict__ Chi, __half* __restrict__ Clo,
              const float* __restrict__ bias, const float* __restrict__ addp,
              int M, int Nn, int K, int lda, int ldb,
              long sA, long sB, long sC, int selA, int selB,
              int nH, long hA, long hB, float outScale)
{
    constexpr int PADB  = 2 * BKE + 16;
    constexpr int TILEA = BM * PADB;
    constexpr int TILEB = 128 * PADB;
    constexpr uint32_t STB = TILEA + (1 + MODE) * TILEB;   // stage bytes
    constexpr int SEGS  = BKE / 8;                         // 16B segments per row
    constexpr int RSTEP = NTHR / SEGS;                     // rows staged per iter
    constexpr int KSN   = BKE / 16;
    constexpr int NWARP = NTHR / 32;
    constexpr int MW    = (NTHR == 128) ? 2 : 4;           // warps along M
    constexpr int MF    = BM / MW / 16;                    // 16-row frags per warp

    extern __shared__ char smem[];
    const uint32_t sb = smem_u32(smem);
    const int tid = threadIdx.x, wid = tid >> 5, lane = tid & 31;
    const int z = blockIdx.z;
    const int m0 = blockIdx.y * BM, n0 = blockIdx.x * 128;
    const int warpM = (wid & (MW - 1)) * (BM / MW);
    const int warpN = (wid / MW) * 64;

    const __half* A0h = Ahi + (long)selidx(selA, z) * sA;
    const __half* B0h = Bhi + (long)selidx(selB, z) * sB;
    const __half* B0l = (MODE == 1) ? (Blo + (long)selidx(selB, z) * sB) : nullptr;

    const int nchK = K / BKE;
    const int nch  = nH * nchK;

    const int srow = tid / SEGS;
    const int sseg = tid % SEGS;

    auto issue = [&](int ch, int buf) {
        const uint32_t so = sb + (uint32_t)buf * STB;
        const int h  = ch / nchK;
        const int k0 = (ch - h * nchK) * BKE;
        {   // A tile: BM rows
            const __half* gb = A0h + (long)h * hA + (long)(m0 + srow) * lda + k0 + sseg * 8;
            const uint32_t tb = so + srow * PADB + sseg * 16;
#pragma unroll
            for (int j = 0; j < BM / RSTEP; ++j)
                CPA16(tb + j * RSTEP * PADB, gb + (long)(j * RSTEP) * lda);
        }
        {   // Bh tile: 128 rows
            const __half* gb = B0h + (long)h * hB + (long)(n0 + srow) * ldb + k0 + sseg * 8;
            const uint32_t tb = so + TILEA + srow * PADB + sseg * 16;
#pragma unroll
            for (int j = 0; j < 128 / RSTEP; ++j)
                CPA16(tb + j * RSTEP * PADB, gb + (long)(j * RSTEP) * ldb);
        }
        if (MODE == 1) {
            const __half* gb = B0l + (long)h * hB + (long)(n0 + srow) * ldb + k0 + sseg * 8;
            const uint32_t tb = so + TILEA + TILEB + srow * PADB + sseg * 16;
#pragma unroll
            for (int j = 0; j < 128 / RSTEP; ++j)
                CPA16(tb + j * RSTEP * PADB, gb + (long)(j * RSTEP) * ldb);
        }
        CPA_COMMIT();
    };

    float acc[MF][8][4];
#pragma unroll
    for (int i = 0; i < MF; ++i)
#pragma unroll
        for (int j = 0; j < 8; ++j)
#pragma unroll
            for (int k = 0; k < 4; ++k) acc[i][j][k] = 0.f;

#pragma unroll
    for (int p = 0; p < STG; ++p) issue(p, p);

    const uint32_t aRow = (uint32_t)(warpM + (lane & 15)) * PADB + ((lane >> 4) << 4);
    const uint32_t bRow = (uint32_t)(warpN + ((lane >> 4) << 3) + (lane & 7)) * PADB
                        + (((lane >> 3) & 1) << 4);

    int buf = 0;
    for (int ch = 0; ch < nch; ++ch) {
        const int rem = nch - 1 - ch;         // groups still pending beyond ch
        if (STG == 3) {
            if (rem >= 2) { CPA_WAIT2(); } else if (rem == 1) { CPA_WAIT1(); } else { CPA_WAIT0(); }
        } else {
            if (rem >= 1) { CPA_WAIT1(); } else { CPA_WAIT0(); }
        }
        __syncthreads();
        const uint32_t so = sb + (uint32_t)buf * STB;
#pragma unroll
        for (int ks = 0; ks < KSN; ++ks) {
            const uint32_t kb = ks * 32;
            uint32_t ah[MF][4], bh[4][4], bl[4][4];
#pragma unroll
            for (int mf = 0; mf < MF; ++mf)
                LDSM4(ah[mf], so + aRow + (uint32_t)(mf * 16 * PADB) + kb);
#pragma unroll
            for (int q = 0; q < 4; ++q) {
                const uint32_t bd = so + TILEA + bRow + (uint32_t)(q * 16 * PADB) + kb;
                LDSM4(bh[q], bd);
                if (MODE == 1) LDSM4(bl[q], bd + TILEB);
            }
#pragma unroll
            for (int mf = 0; mf < MF; ++mf)
#pragma unroll
                for (int nf = 0; nf < 8; ++nf) {
                    MMA16816(acc[mf][nf], ah[mf],
                             bh[nf >> 1][(nf & 1) * 2], bh[nf >> 1][(nf & 1) * 2 + 1]);
                    if (MODE == 1)
                        MMA16816(acc[mf][nf], ah[mf],
                                 bl[nf >> 1][(nf & 1) * 2], bl[nf >> 1][(nf & 1) * 2 + 1]);
                }
        }
        __syncthreads();
        if (ch + STG < nch) issue(ch + STG, buf);
        buf = (buf + 1 == STG) ? 0 : buf + 1;
    }

    // ---- epilogue (register accumulators -> gmem)
    const int rbase = m0 + warpM + (lane >> 2);
    const int cbase = n0 + warpN + (lane & 3) * 2;
    float ssum = 0.f, ssq = 0.f;
#pragma unroll
    for (int mf = 0; mf < MF; ++mf) {
#pragma unroll
        for (int h2 = 0; h2 < 2; ++h2) {
            const long m = rbase + mf * 16 + h2 * 8;
#pragma unroll
            for (int nf = 0; nf < 8; ++nf) {
                const long col = cbase + nf * 8;
                float v0 = acc[mf][nf][h2 * 2]     * outScale;
                float v1 = acc[mf][nf][h2 * 2 + 1] * outScale;
                if (EPI == 1) {
                    const float2 ad = *(const float2*)(addp + m * Nn + col);
                    v0 += ad.x; v1 += ad.y;
                }
                if (EPI == 2) {
                    v0 += bias[col]; v1 += bias[col + 1];
                    v0 = 0.5f * v0 * (1.f + erff(v0 * 0.70710678118654752f));
                    v1 = 0.5f * v1 * (1.f + erff(v1 * 0.70710678118654752f));
                }
                if (EPI == 3) {
                    const float2 ad = *(const float2*)(addp + m * Nn + col);
                    v0 += bias[col]     + ad.x;
                    v1 += bias[col + 1] + ad.y;
                }
                if (STATS) { ssum += v0 + v1; ssq += v0 * v0 + v1 * v1; }
                const long idx = (long)z * sC + m * Nn + col;
                if (OUT == 0) {
                    *(float2*)(C + idx) = make_float2(v0, v1);
                } else if (OUT == 1) {
                    __half h0, l0, h1, l1;
                    splt(v0, h0, l0); splt(v1, h1, l1);
                    *(__half2*)(Chi + idx) = __halves2half2(h0, h1);
                    *(__half2*)(Clo + idx) = __halves2half2(l0, l1);
                } else {
                    *(__half2*)(Chi + idx) =
                        __halves2half2(__float2half_rn(v0), __float2half_rn(v1));
                }
            }
        }
    }
    if (STATS) {
        __shared__ float sred[2 * NWARP];
        float s = ssum, q = ssq;
#pragma unroll
        for (int o = 16; o; o >>= 1) {
            s += __shfl_xor_sync(0xffffffffu, s, o);
            q += __shfl_xor_sync(0xffffffffu, q, o);
        }
        if (lane == 0) { sred[wid * 2] = s; sred[wid * 2 + 1] = q; }
        __syncthreads();
        if (tid == 0) {
            float rs = 0.f, rq = 0.f;
#pragma unroll
            for (int j = 0; j < NWARP; ++j) { rs += sred[j * 2]; rq += sred[j * 2 + 1]; }
            const long t = (long)z * (gridDim.x * gridDim.y)
                         + blockIdx.y * gridDim.x + blockIdx.x;
            C[t * 2] = rs; C[t * 2 + 1] = rq;
        }
    }
}

// ===================== prep kernels (vectorized) =============================
// fp32 [Z][R][C] -> fp16 [Z][C][R] (rounded), 32x64 tiles, 16B transactions
__global__ __launch_bounds__(256)
void tround_k(const float* __restrict__ in, __half* __restrict__ oh, int R, int Cc)
{
    __shared__ float t[32][65];
    const long zo = (long)blockIdx.z * R * Cc;
    const int c0 = blockIdx.x * 64, r0 = blockIdx.y * 32;
    const int tid = threadIdx.x;
#pragma unroll
    for (int it = 0; it < 2; ++it) {
        const int idx = tid + it * 256;
        const int r = idx >> 4, cs = idx & 15;
        const float4 v = *(const float4*)(in + zo + (long)(r0 + r) * Cc + c0 + cs * 4);
        t[r][cs * 4 + 0] = v.x; t[r][cs * 4 + 1] = v.y;
        t[r][cs * 4 + 2] = v.z; t[r][cs * 4 + 3] = v.w;
    }
    __syncthreads();
    const int c = tid >> 2, rs = tid & 3;
    __align__(16) __half hh[8];
#pragma unroll
    for (int j = 0; j < 8; ++j) hh[j] = __float2half_rn(t[rs * 8 + j][c]);
    *(uint4*)&oh[zo + (long)(c0 + c) * R + r0 + rs * 8] = *(uint4*)hh;
}

// fp32 -> fp16 rounded (same layout)
__global__ void pround_k(const float* __restrict__ in, __half* __restrict__ oh, long n4)
{
    for (long i = blockIdx.x * blockDim.x + threadIdx.x; i < n4; i += (long)gridDim.x * blockDim.x) {
        float4 v = ((const float4*)in)[i];
        __half hh[4] = { __float2half_rn(v.x), __float2half_rn(v.y),
                         __float2half_rn(v.z), __float2half_rn(v.w) };
        ((uint2*)oh)[i] = *(uint2*)hh;
    }
}

// fp16 [Z][R][C] -> [Z][C][R], 32x64 tiles, 16B transactions
__global__ __launch_bounds__(256)
void tb16_k(const __half* __restrict__ in, __half* __restrict__ out, int R, int Cc)
{
    __shared__ __half t[32][72];
    const long zo = (long)blockIdx.z * R * Cc;
    const int c0 = blockIdx.x * 64, r0 = blockIdx.y * 32;
    const int tid = threadIdx.x;
    {
        const int r = tid >> 3, cs = tid & 7;
        __align__(16) __half v[8];
        *(uint4*)v = *(const uint4*)(in + zo + (long)(r0 + r) * Cc + c0 + cs * 8);
#pragma unroll
        for (int j = 0; j < 8; ++j) t[r][cs * 8 + j] = v[j];
    }
    __syncthreads();
    const int c = tid >> 2, rs = tid & 3;
    __align__(16) __half o8[8];
#pragma unroll
    for (int j = 0; j < 8; ++j) o8[j] = t[rs * 8 + j][c];
    *(uint4*)&out[zo + (long)(c0 + c) * R + r0 + rs * 8] = *(uint4*)o8;
}

// input LayerNorms -> rounded fp16 outputs (224 thr: 448 float4 = 1792 elems)
__global__ __launch_bounds__(224)
void ln_in_kernel(const float* __restrict__ e1, const float* __restrict__ e2,
                  const float* __restrict__ e3,
                  const float* __restrict__ ag, const float* __restrict__ ab,
                  const float* __restrict__ g1, const float* __restrict__ b1,
                  __half* __restrict__ Yh, __half* __restrict__ Xh)
{
    const long row = blockIdx.x;
    const int  tid = threadIdx.x;
    const float4* p1 = (const float4*)(e1 + row * C1d);
    const float4* p2 = (const float4*)(e2 + row * C2d);
    const float4* p3 = (const float4*)(e3 + row * C3d);
    __shared__ float sh[16];

    const int f0 = tid, f1 = tid + 224;
    const bool isX = (f0 >= 64) && (f0 < 192);
    float4 a = (f0 < 64) ? p1[f0] : (isX ? p2[f0 - 64] : p3[f0 - 192]);
    float4 b = p3[f1 - 192];

    float s = a.x + a.y + a.z + a.w + b.x + b.y + b.z + b.w;
    float q = a.x * a.x + a.y * a.y + a.z * a.z + a.w * a.w
            + b.x * b.x + b.y * b.y + b.z * b.z + b.w * b.w;
    float2 r = bred2(s, q, sh, tid, 7);
    float mean = r.x * (1.f / KVd);
    float inv  = rsqrtf(r.y * (1.f / KVd) - mean * mean + 1e-6f);

    const float4* g4 = (const float4*)ag;
    const float4* b4 = (const float4*)ab;
    {
        const float4 ga = g4[f0], ba = b4[f0];
        __half hh[4];
        hh[0] = __float2half_rn((a.x - mean) * inv * ga.x + ba.x);
        hh[1] = __float2half_rn((a.y - mean) * inv * ga.y + ba.y);
        hh[2] = __float2half_rn((a.z - mean) * inv * ga.z + ba.z);
        hh[3] = __float2half_rn((a.w - mean) * inv * ga.w + ba.w);
        *(uint2*)&Yh[row * KVd + f0 * 4] = *(uint2*)hh;
        const float4 gb = g4[f1], bb = b4[f1];
        hh[0] = __float2half_rn((b.x - mean) * inv * gb.x + bb.x);
        hh[1] = __float2half_rn((b.y - mean) * inv * gb.y + bb.y);
        hh[2] = __float2half_rn((b.z - mean) * inv * gb.z + bb.z);
        hh[3] = __float2half_rn((b.w - mean) * inv * gb.w + bb.w);
        *(uint2*)&Yh[row * KVd + f1 * 4] = *(uint2*)hh;
    }

    // X = LN(emb2): chunk0 of threads 64..191 covers e2 exactly
    float sX = isX ? (a.x + a.y + a.z + a.w) : 0.f;
    float qX = isX ? (a.x * a.x + a.y * a.y + a.z * a.z + a.w * a.w) : 0.f;
    float2 rX = bred2(sX, qX, sh, tid, 7);
    if (isX) {
        float meanX = rX.x * (1.f / C2d);
        float invX  = rsqrtf(rX.y * (1.f / C2d) - meanX * meanX + 1e-6f);
        const int fx = f0 - 64;
        const float4 gx = ((const float4*)g1)[fx], bx = ((const float4*)b1)[fx];
        __half hh[4];
        hh[0] = __float2half_rn((a.x - meanX) * invX * gx.x + bx.x);
        hh[1] = __float2half_rn((a.y - meanX) * invX * gx.y + bx.y);
        hh[2] = __float2half_rn((a.z - meanX) * invX * gx.z + bx.z);
        hh[3] = __float2half_rn((a.w - meanX) * invX * gx.w + bx.w);
        *(uint2*)&Xh[row * C2d + fx * 4] = *(uint2*)hh;
    }
}

__global__ __launch_bounds__(128)
void ln2_kernel(const float* __restrict__ in,
                const float* __restrict__ g, const float* __restrict__ b,
                __half* __restrict__ Zh)
{
    const long row = blockIdx.x;
    const int  tid = threadIdx.x;
    __shared__ float sh[8];
    const float4 v = ((const float4*)(in + row * C2d))[tid];
    float s = v.x + v.y + v.z + v.w;
    float q = v.x * v.x + v.y * v.y + v.z * v.z + v.w * v.w;
    float2 r = bred2(s, q, sh, tid, 4);
    float mean = r.x * (1.f / C2d);
    float inv  = rsqrtf(r.y * (1.f / C2d) - mean * mean + 1e-6f);
    const float4 gg = ((const float4*)g)[tid], bb = ((const float4*)b)[tid];
    __half hh[4];
    hh[0] = __float2half_rn((v.x - mean) * inv * gg.x + bb.x);
    hh[1] = __float2half_rn((v.y - mean) * inv * gg.y + bb.y);
    hh[2] = __float2half_rn((v.z - mean) * inv * gg.z + bb.z);
    hh[3] = __float2half_rn((v.w - mean) * inv * gg.w + bb.w);
    *(uint2*)&Zh[row * C2d + tid * 4] = *(uint2*)hh;
}

// finish per-map variance from 56 per-tile partials -> softmax scale
__global__ __launch_bounds__(32)
void stats2_kernel(const float* __restrict__ part, float* __restrict__ scale)
{
    const int z = blockIdx.x, lane = threadIdx.x;
    float s = 0.f, q = 0.f;
#pragma unroll
    for (int j = 0; j < 2; ++j) {
        const int i = lane + j * 32;
        if (i < 56) { s += part[((long)z * 56 + i) * 2]; q += part[((long)z * 56 + i) * 2 + 1]; }
    }
#pragma unroll
    for (int o = 16; o; o >>= 1) {
        s += __shfl_xor_sync(0xffffffffu, s, o);
        q += __shfl_xor_sync(0xffffffffu, q, o);
    }
    if (lane == 0) {
        const float cnt = (float)(C2d * KVd);
        float mean = s / cnt;
        float var  = q / cnt - mean * mean;
        float a    = rsqrtf((float)KVd);
        scale[z]   = a * rsqrtf(a * a * var + 1e-5f);
    }
}

__global__ __launch_bounds__(224)
void softmax_kernel(const __half* __restrict__ Sh, const float* __restrict__ scale,
                    __half* __restrict__ Ph)
{
    const long row = blockIdx.x;
    const int  tid = threadIdx.x;
    const __half* p = Sh + row * KVd;
    const float sc = scale[blockIdx.x >> 9];
    __shared__ float sh[16];

    __align__(16) __half v8[8];
    *(uint4*)v8 = *(const uint4*)(p + tid * 8);
    float f[8];
#pragma unroll
    for (int j = 0; j < 8; ++j) f[j] = __half2float(v8[j]);
    float mx = f[0];
#pragma unroll
    for (int j = 1; j < 8; ++j) mx = fmaxf(mx, f[j]);
    mx = bmax(mx, sh, tid, 7);

    float e[8], s = 0.f;
#pragma unroll
    for (int j = 0; j < 8; ++j) { e[j] = __expf((f[j] - mx) * sc); s += e[j]; }
    float2 r = bred2(s, 0.f, sh, tid, 7);
    const float inv = 1.f / r.x;

#pragma unroll
    for (int j = 0; j < 8; ++j) v8[j] = __float2half_rn(e[j] * inv);
    *(uint4*)&Ph[row * KVd + tid * 8] = *(uint4*)v8;
}

// ===================== launcher =============================================
#define SYM(v, t, s) t* v; { void* _p; cudaGetSymbolAddress(&_p, s); v = (t*)_p; }

extern "C" void kernel_launch(void* const* d_in, const int* in_sizes, int n_in,
                              void* d_out, int out_size)
{
    const float* emb1    = (const float*)d_in[0];
    const float* emb2    = (const float*)d_in[1];
    const float* emb3    = (const float*)d_in[2];
    const float* Wq      = (const float*)d_in[3];
    const float* Wk      = (const float*)d_in[4];
    const float* Wv      = (const float*)d_in[5];
    const float* Wout    = (const float*)d_in[6];
    const float* ln1_g   = (const float*)d_in[7];
    const float* ln1_b   = (const float*)d_in[8];
    const float* lnall_g = (const float*)d_in[9];
    const float* lnall_b = (const float*)d_in[10];
    const float* lnffn_g = (const float*)d_in[11];
    const float* lnffn_b = (const float*)d_in[12];
    const float* fc1_w   = (const float*)d_in[13];
    const float* fc1_b   = (const float*)d_in[14];
    const float* fc2_w   = (const float*)d_in[15];
    const float* fc2_b   = (const float*)d_in[16];
    float* out = (float*)d_out;

    SYM(Yh, __half, g_Yh)   SYM(Yth, __half, g_Yth)
    SYM(Xh, __half, g_Xh)   SYM(Xth, __half, g_Xth)
    SYM(Gth, __half, g_Gth) SYM(Gtl, __half, g_Gtl)
    SYM(T1h, __half, g_T1h)
    SYM(Sh, __half, g_Sh)
    SYM(Ph, __half, g_Ph)
    SYM(Mth, __half, g_Mth)
    SYM(Ch, __half, g_Ch)
    SYM(cx2, float, g_cx2)
    SYM(Zh, __half, g_Zh)
    SYM(Fh, __half, g_Fh)
    SYM(WqTh, __half, g_WqTh)
    SYM(WkTh, __half, g_WkTh)
    SYM(Wvh, __half, g_Wvh)
    SYM(WoTh, __half, g_WoTh)
    SYM(f1Th, __half, g_f1Th)
    SYM(f2Th, __half, g_f2Th)
    SYM(scl, float, g_sc)     SYM(part, float, g_part)

    const int SMA = 3 * ((128 + 128) * (2 * 64 + 16));   // 110592 B: BK64 3-stage 1-pass -> 2 CTAs/SM
    const int SMB = 2 * ((128 + 256) * (2 * 64 + 16));   // 110592 B: BK64 2-stage 2-pass -> 2 CTAs/SM
    cudaFuncSetAttribute(mma_gemm<128, 64, 3, 0, 0, 1, 0, 128>, cudaFuncAttributeMaxDynamicSharedMemorySize, SMA);
    cudaFuncSetAttribute(mma_gemm<128, 64, 2, 1, 0, 2, 0, 256>, cudaFuncAttributeMaxDynamicSharedMemorySize, SMB);
    cudaFuncSetAttribute(mma_gemm<128, 64, 3, 0, 0, 2, 1, 128>, cudaFuncAttributeMaxDynamicSharedMemorySize, SMA);
    cudaFuncSetAttribute(mma_gemm<128, 64, 3, 0, 0, 2, 0, 128>, cudaFuncAttributeMaxDynamicSharedMemorySize, SMA);
    cudaFuncSetAttribute(mma_gemm<128, 64, 3, 0, 1, 0, 0, 128>, cudaFuncAttributeMaxDynamicSharedMemorySize, SMA);
    cudaFuncSetAttribute(mma_gemm<128, 64, 3, 0, 2, 2, 0, 128>, cudaFuncAttributeMaxDynamicSharedMemorySize, SMA);
    cudaFuncSetAttribute(mma_gemm<128, 64, 3, 0, 3, 0, 0, 128>, cudaFuncAttributeMaxDynamicSharedMemorySize, SMA);

    // --- launches 0..2: GEMM2's only deps; GEMM2 is my launch #3 == ncu slot
    ln_in_kernel<<<BB * NT, 224>>>(emb1, emb2, emb3, lnall_g, lnall_b, ln1_g, ln1_b,
                                   Yh, Xh);
    tb16_k<<<dim3(KVd / 64, NT / 32, BB), 256>>>(Yh, Yth, NT, KVd);
    tb16_k<<<dim3(C2d / 64, NT / 32, BB), 256>>>(Xh, Xth, NT, C2d);

    // 2. Gt_b = Yt_b Xt_b^T  [1792,512], K=1024 (split out: Gt has corr spikes)
    mma_gemm<128, 64, 3, 0, 0, 1, 0, 128><<<dim3(C2d / 128, KVd / 128, BB), 128, SMA>>>(
        Yth, Xth, nullptr, nullptr, Gth, Gtl, nullptr, nullptr,
        KVd, C2d, NT, NT, NT,
        (long)KVd * NT, (long)C2d * NT, (long)KVd * C2d, 0, 0, 1, 0, 0, 1.f);

    // weight prep
    tround_k<<<dim3(C2d / 64, C2d / 32, NHd), 256>>>(Wq, WqTh, C2d, C2d);
    tround_k<<<dim3(KVd / 64, KVd / 32, NHd), 256>>>(Wk, WkTh, KVd, KVd);
    tround_k<<<dim3(C2d / 64, C2d / 32, 1), 256>>>(Wout, WoTh, C2d, C2d);
    tround_k<<<dim3(C2E / 64, C2d / 32, 1), 256>>>(fc1_w, f1Th, C2d, C2E);
    tround_k<<<dim3(C2d / 64, C2E / 32, 1), 256>>>(fc2_w, f2Th, C2E, C2d);
    pround_k<<<4096, 256>>>(Wv, Wvh, (long)NHd * KVd * KVd / 4);

    // 3. T1[b,h] = WqT_h Gt_b^T  [512,1792], K=512  (B-split 2-pass, 2-stage)
    mma_gemm<128, 64, 2, 1, 0, 2, 0, 256><<<dim3(KVd / 128, C2d / 128, BB * NHd), 256, SMB>>>(
        WqTh, Gth, Gtl, nullptr, T1h, nullptr, nullptr, nullptr,
        C2d, KVd, C2d, C2d, C2d,
        (long)C2d * C2d, (long)KVd * C2d, (long)C2d * KVd, 1, 2, 1, 0, 0, 1.f);

    // 4. S[b,h] = T1 WkT_h^T  [512,1792], K=1792 (fp16 out + fused stats partials)
    mma_gemm<128, 64, 3, 0, 0, 2, 1, 128><<<dim3(KVd / 128, C2d / 128, BB * NHd), 128, SMA>>>(
        T1h, WkTh, nullptr, part, Sh, nullptr, nullptr, nullptr,
        C2d, KVd, KVd, KVd, KVd,
        (long)C2d * KVd, (long)KVd * KVd, (long)C2d * KVd, 0, 1, 1, 0, 0, 1.f);

    // 5-6. finish stats + row softmax
    stats2_kernel<<<BB * NHd, 32>>>(part, scl);
    softmax_kernel<<<BB * NHd * C2d, 224>>>(Sh, scl, Ph);

    // 7. Mmt_b[c,e] = (1/H) sum_h sum_k P[b,h,c,k] Wv_h[e,k]  [512,1792]
    mma_gemm<128, 64, 3, 0, 0, 2, 0, 128><<<dim3(KVd / 128, C2d / 128, BB), 128, SMA>>>(
        Ph, Wvh, nullptr, nullptr, Mth, nullptr, nullptr, nullptr,
        C2d, KVd, KVd, KVd, KVd,
        (long)NHd * C2d * KVd, 0, (long)C2d * KVd, 0, 0,
        NHd, (long)C2d * KVd, (long)KVd * KVd, 1.f / NHd);

    // 8. ctx_b = Y_b Mmt_b^T  [1024,512], K=1792
    mma_gemm<128, 64, 3, 0, 0, 2, 0, 128><<<dim3(C2d / 128, NT / 128, BB), 128, SMA>>>(
        Yh, Mth, nullptr, nullptr, Ch, nullptr, nullptr, nullptr,
        NT, C2d, KVd, KVd, KVd,
        (long)NT * KVd, (long)C2d * KVd, (long)NT * C2d, 0, 0, 1, 0, 0, 1.f);

    // 9. cx2 = ctx WoutT^T + emb2  [8192,512]
    mma_gemm<128, 64, 3, 0, 1, 0, 0, 128><<<dim3(C2d / 128, BB * NT / 128, 1), 128, SMA>>>(
        Ch, WoTh, nullptr, cx2, nullptr, nullptr, nullptr, emb2,
        BB * NT, C2d, C2d, C2d, C2d, 0, 0, 0, 0, 0, 1, 0, 0, 1.f);

    // 10. Z = LN(cx2)
    ln2_kernel<<<BB * NT, 128>>>(cx2, lnffn_g, lnffn_b, Zh);

    // 11. F = gelu(Z f1T^T + b1)  [8192,2048]
    mma_gemm<128, 64, 3, 0, 2, 2, 0, 128><<<dim3(C2E / 128, BB * NT / 128, 1), 128, SMA>>>(
        Zh, f1Th, nullptr, nullptr, Fh, nullptr, fc1_b, nullptr,
        BB * NT, C2E, C2d, C2d, C2d, 0, 0, 0, 0, 0, 1, 0, 0, 1.f);

    // 12. out = F f2T^T + b2 + cx2  [8192,512]
    mma_gemm<128, 64, 3, 0, 3, 0, 0, 128><<<dim3(C2d / 128, BB * NT / 128, 1), 128, SMA>>>(
        Fh, f2Th, nullptr, out, nullptr, nullptr, fc2_b, cx2,
        BB * NT, C2d, C2E, C2E, C2E, 0, 0, 0, 0, 0, 1, 0, 0, 1.f);
}

// round 17
// speedup vs baseline: 6.1931x; 1.0798x over previous
#include <cuda_runtime.h>
#include <cuda_fp16.h>
#include <math.h>
#include <stdint.h>

// Problem constants
#define BB   8
#define NT   1024
#define C1d  256
#define C2d  512
#define C3d  1024
#define KVd  1792
#define NHd  4
#define C2E  2048

// ===================== scratch (device statics) ==============================
__device__ __half g_Yh [BB*NT*KVd];                       // LN(concat)  [b][n][kv]
__device__ __half g_Yth[BB*NT*KVd];                       // transposed  [b][kv][n]
__device__ __half g_Xh [BB*NT*C2d];                       // LN(emb2)    [b][n][c]
__device__ __half g_Xth[BB*NT*C2d];                       // transposed  [b][c][n]
__device__ __half g_Gth[BB*KVd*C2d];                      // Gt fp16
__device__ __half g_T1h[BB*NHd*C2d*KVd];
__device__ __half g_Sh [BB*NHd*C2d*KVd];                  // scores fp16
__device__ __half g_Ph [BB*NHd*C2d*KVd];                  // probs
__device__ __half g_Mth[BB*C2d*KVd];                      // Mmt [b][c][e]
__device__ __half g_Ch [BB*NT*C2d];                       // ctx
__device__ float  g_cx2[BB*NT*C2d];                       // residual fp32
__device__ __half g_Zh [BB*NT*C2d];                       // LN(cx2)
__device__ __half g_Fh [BB*NT*C2E];                       // gelu(fc1)
// weights (pre-transposed + rounded to fp16)
__device__ __half g_WqTh[NHd*C2d*C2d];
__device__ __half g_WkTh[NHd*KVd*KVd];
__device__ __half g_Wvh [NHd*KVd*KVd];
__device__ __half g_WoTh[C2d*C2d];
__device__ __half g_f1Th[C2E*C2d];
__device__ __half g_f2Th[C2d*C2E];
__device__ float g_sc[BB*NHd];
__device__ float g_part[BB*NHd*56*2];

// ===================== PTX helpers (baseline sm_80+ only) ====================
__device__ __forceinline__ uint32_t smem_u32(const void* p) {
    uint32_t a;
    asm("{ .reg .u64 t; cvta.to.shared.u64 t, %1; cvt.u32.u64 %0, t; }" : "=r"(a) : "l"(p));
    return a;
}
#define CPA16(d, s)   asm volatile("cp.async.cg.shared.global [%0], [%1], 16;" :: "r"(d), "l"(s))
#define CPA_COMMIT()  asm volatile("cp.async.commit_group;" ::: "memory")
#define CPA_WAIT2()   asm volatile("cp.async.wait_group 2;" ::: "memory")
#define CPA_WAIT1()   asm volatile("cp.async.wait_group 1;" ::: "memory")
#define CPA_WAIT0()   asm volatile("cp.async.wait_group 0;" ::: "memory")

#define LDSM4(r, a) \
    asm volatile("ldmatrix.sync.aligned.m8n8.x4.shared.b16 {%0,%1,%2,%3}, [%4];" \
        : "=r"((r)[0]), "=r"((r)[1]), "=r"((r)[2]), "=r"((r)[3]) : "r"(a))

#define MMA16816(C, A, B0, B1) \
    asm volatile("mma.sync.aligned.m16n8k16.row.col.f32.f16.f16.f32 " \
        "{%0,%1,%2,%3}, {%4,%5,%6,%7}, {%8,%9}, {%0,%1,%2,%3};" \
        : "+f"((C)[0]), "+f"((C)[1]), "+f"((C)[2]), "+f"((C)[3]) \
        : "r"((A)[0]), "r"((A)[1]), "r"((A)[2]), "r"((A)[3]), "r"(B0), "r"(B1))

__device__ __forceinline__ void splt(float v, __half& h, __half& l) {
    h = __float2half_rn(v);
    l = __float2half_rn(v - __half2float(h));
}
__device__ __forceinline__ int selidx(int mode, int z) {
    return mode == 0 ? z : (mode == 1 ? (z & 3) : (z >> 2));
}

// block reductions (warp shuffle + tiny smem); fixed order -> deterministic
__device__ __forceinline__ float2 bred2(float s, float q, float* sh, int tid, int nw) {
#pragma unroll
    for (int o = 16; o; o >>= 1) {
        s += __shfl_xor_sync(0xffffffffu, s, o);
        q += __shfl_xor_sync(0xffffffffu, q, o);
    }
    if ((tid & 31) == 0) { sh[(tid >> 5) * 2] = s; sh[(tid >> 5) * 2 + 1] = q; }
    __syncthreads();
    float rs = 0.f, rq = 0.f;
    for (int j = 0; j < nw; ++j) { rs += sh[j * 2]; rq += sh[j * 2 + 1]; }
    __syncthreads();
    return make_float2(rs, rq);
}
__device__ __forceinline__ float bmax(float v, float* sh, int tid, int nw) {
#pragma unroll
    for (int o = 16; o; o >>= 1) v = fmaxf(v, __shfl_xor_sync(0xffffffffu, v, o));
    if ((tid & 31) == 0) sh[tid >> 5] = v;
    __syncthreads();
    float r = sh[0];
    for (int j = 1; j < nw; ++j) r = fmaxf(r, sh[j]);
    __syncthreads();
    return r;
}

// ===================== mma.sync fp16 GEMM ====================================
// C[M,Nn] = outScale * sum_h A_h[M,K] * B_h[N,K]^T  (+ epilogue)
// NTHR=128: 4 warps, 2(M)x2(N), warp tile 64x64 (0.0625 B/MAC smem traffic)
// MODE: 0 -> 1-pass (A,B fp16-rounded);  1 -> 2-pass B-split (A*Bh + A*Bl)
// EPI: 0 none, 1 +add, 2 +bias,gelu, 3 +bias+add.
// OUT: 0 fp32, 1 fp16 hi+lo, 2 fp16 rounded
// STATS: 1 -> per-CTA sum/sumsq of outputs -> C (as partials buffer)
// smem row stride 2*BKE+16 B -> mod 128 = 16, conflict-free ldmatrix cycling.
// BK64 stages (36.9 KB) -> 110.6 KB/CTA -> 2 CTAs/SM.
template<int BM, int BKE, int STG, int MODE, int EPI, int OUT, int STATS, int NTHR>
__global__ __launch_bounds__(NTHR, 2)
void mma_gemm(const __half* __restrict__ Ahi,
              const __half* __restrict__ Bhi, const __half* __restrict__ Blo,
              float* __restrict__ C, __half* __restrict__ Chi, __half* __restrict__ Clo,
              const float* __restrict__ bias, const float* __restrict__ addp,
              int M, int Nn, int K, int lda, int ldb,
              long sA, long sB, long sC, int selA, int selB,
              int nH, long hA, long hB, float outScale)
{
    constexpr int PADB  = 2 * BKE + 16;
    constexpr int TILEA = BM * PADB;
    constexpr int TILEB = 128 * PADB;
    constexpr uint32_t STB = TILEA + (1 + MODE) * TILEB;   // stage bytes
    constexpr int SEGS  = BKE / 8;                         // 16B segments per row
    constexpr int RSTEP = NTHR / SEGS;                     // rows staged per iter
    constexpr int KSN   = BKE / 16;
    constexpr int NWARP = NTHR / 32;
    constexpr int MW    = (NTHR == 128) ? 2 : 4;           // warps along M
    constexpr int MF    = BM / MW / 16;                    // 16-row frags per warp

    extern __shared__ char smem[];
    const uint32_t sb = smem_u32(smem);
    const int tid = threadIdx.x, wid = tid >> 5, lane = tid & 31;
    const int z = blockIdx.z;
    const int m0 = blockIdx.y * BM, n0 = blockIdx.x * 128;
    const int warpM = (wid & (MW - 1)) * (BM / MW);
    const int warpN = (wid / MW) * 64;

    const __half* A0h = Ahi + (long)selidx(selA, z) * sA;
    const __half* B0h = Bhi + (long)selidx(selB, z) * sB;
    const __half* B0l = (MODE == 1) ? (Blo + (long)selidx(selB, z) * sB) : nullptr;

    const int nchK = K / BKE;
    const int nch  = nH * nchK;

    const int srow = tid / SEGS;
    const int sseg = tid % SEGS;

    auto issue = [&](int ch, int buf) {
        const uint32_t so = sb + (uint32_t)buf * STB;
        const int h  = ch / nchK;
        const int k0 = (ch - h * nchK) * BKE;
        {   // A tile: BM rows
            const __half* gb = A0h + (long)h * hA + (long)(m0 + srow) * lda + k0 + sseg * 8;
            const uint32_t tb = so + srow * PADB + sseg * 16;
#pragma unroll
            for (int j = 0; j < BM / RSTEP; ++j)
                CPA16(tb + j * RSTEP * PADB, gb + (long)(j * RSTEP) * lda);
        }
        {   // Bh tile: 128 rows
            const __half* gb = B0h + (long)h * hB + (long)(n0 + srow) * ldb + k0 + sseg * 8;
            const uint32_t tb = so + TILEA + srow * PADB + sseg * 16;
#pragma unroll
            for (int j = 0; j < 128 / RSTEP; ++j)
                CPA16(tb + j * RSTEP * PADB, gb + (long)(j * RSTEP) * ldb);
        }
        if (MODE == 1) {
            const __half* gb = B0l + (long)h * hB + (long)(n0 + srow) * ldb + k0 + sseg * 8;
            const uint32_t tb = so + TILEA + TILEB + srow * PADB + sseg * 16;
#pragma unroll
            for (int j = 0; j < 128 / RSTEP; ++j)
                CPA16(tb + j * RSTEP * PADB, gb + (long)(j * RSTEP) * ldb);
        }
        CPA_COMMIT();
    };

    float acc[MF][8][4];
#pragma unroll
    for (int i = 0; i < MF; ++i)
#pragma unroll
        for (int j = 0; j < 8; ++j)
#pragma unroll
            for (int k = 0; k < 4; ++k) acc[i][j][k] = 0.f;

#pragma unroll
    for (int p = 0; p < STG; ++p) issue(p, p);

    const uint32_t aRow = (uint32_t)(warpM + (lane & 15)) * PADB + ((lane >> 4) << 4);
    const uint32_t bRow = (uint32_t)(warpN + ((lane >> 4) << 3) + (lane & 7)) * PADB
                        + (((lane >> 3) & 1) << 4);

    int buf = 0;
    for (int ch = 0; ch < nch; ++ch) {
        const int rem = nch - 1 - ch;         // groups still pending beyond ch
        if (STG == 3) {
            if (rem >= 2) { CPA_WAIT2(); } else if (rem == 1) { CPA_WAIT1(); } else { CPA_WAIT0(); }
        } else {
            if (rem >= 1) { CPA_WAIT1(); } else { CPA_WAIT0(); }
        }
        __syncthreads();
        const uint32_t so = sb + (uint32_t)buf * STB;
#pragma unroll
        for (int ks = 0; ks < KSN; ++ks) {
            const uint32_t kb = ks * 32;
            uint32_t ah[MF][4], bh[4][4], bl[4][4];
#pragma unroll
            for (int mf = 0; mf < MF; ++mf)
                LDSM4(ah[mf], so + aRow + (uint32_t)(mf * 16 * PADB) + kb);
#pragma unroll
            for (int q = 0; q < 4; ++q) {
                const uint32_t bd = so + TILEA + bRow + (uint32_t)(q * 16 * PADB) + kb;
                LDSM4(bh[q], bd);
                if (MODE == 1) LDSM4(bl[q], bd + TILEB);
            }
#pragma unroll
            for (int mf = 0; mf < MF; ++mf)
#pragma unroll
                for (int nf = 0; nf < 8; ++nf) {
                    MMA16816(acc[mf][nf], ah[mf],
                             bh[nf >> 1][(nf & 1) * 2], bh[nf >> 1][(nf & 1) * 2 + 1]);
                    if (MODE == 1)
                        MMA16816(acc[mf][nf], ah[mf],
                                 bl[nf >> 1][(nf & 1) * 2], bl[nf >> 1][(nf & 1) * 2 + 1]);
                }
        }
        __syncthreads();
        if (ch + STG < nch) issue(ch + STG, buf);
        buf = (buf + 1 == STG) ? 0 : buf + 1;
    }

    // ---- epilogue (register accumulators -> gmem)
    const int rbase = m0 + warpM + (lane >> 2);
    const int cbase = n0 + warpN + (lane & 3) * 2;
    float ssum = 0.f, ssq = 0.f;
#pragma unroll
    for (int mf = 0; mf < MF; ++mf) {
#pragma unroll
        for (int h2 = 0; h2 < 2; ++h2) {
            const long m = rbase + mf * 16 + h2 * 8;
#pragma unroll
            for (int nf = 0; nf < 8; ++nf) {
                const long col = cbase + nf * 8;
                float v0 = acc[mf][nf][h2 * 2]     * outScale;
                float v1 = acc[mf][nf][h2 * 2 + 1] * outScale;
                if (EPI == 1) {
                    const float2 ad = *(const float2*)(addp + m * Nn + col);
                    v0 += ad.x; v1 += ad.y;
                }
                if (EPI == 2) {
                    v0 += bias[col]; v1 += bias[col + 1];
                    v0 = 0.5f * v0 * (1.f + erff(v0 * 0.70710678118654752f));
                    v1 = 0.5f * v1 * (1.f + erff(v1 * 0.70710678118654752f));
                }
                if (EPI == 3) {
                    const float2 ad = *(const float2*)(addp + m * Nn + col);
                    v0 += bias[col]     + ad.x;
                    v1 += bias[col + 1] + ad.y;
                }
                if (STATS) { ssum += v0 + v1; ssq += v0 * v0 + v1 * v1; }
                const long idx = (long)z * sC + m * Nn + col;
                if (OUT == 0) {
                    *(float2*)(C + idx) = make_float2(v0, v1);
                } else if (OUT == 1) {
                    __half h0, l0, h1, l1;
                    splt(v0, h0, l0); splt(v1, h1, l1);
                    *(__half2*)(Chi + idx) = __halves2half2(h0, h1);
                    *(__half2*)(Clo + idx) = __halves2half2(l0, l1);
                } else {
                    *(__half2*)(Chi + idx) =
                        __halves2half2(__float2half_rn(v0), __float2half_rn(v1));
                }
            }
        }
    }
    if (STATS) {
        __shared__ float sred[2 * NWARP];
        float s = ssum, q = ssq;
#pragma unroll
        for (int o = 16; o; o >>= 1) {
            s += __shfl_xor_sync(0xffffffffu, s, o);
            q += __shfl_xor_sync(0xffffffffu, q, o);
        }
        if (lane == 0) { sred[wid * 2] = s; sred[wid * 2 + 1] = q; }
        __syncthreads();
        if (tid == 0) {
            float rs = 0.f, rq = 0.f;
#pragma unroll
            for (int j = 0; j < NWARP; ++j) { rs += sred[j * 2]; rq += sred[j * 2 + 1]; }
            const long t = (long)z * (gridDim.x * gridDim.y)
                         + blockIdx.y * gridDim.x + blockIdx.x;
            C[t * 2] = rs; C[t * 2 + 1] = rq;
        }
    }
}

// ===================== prep kernels (vectorized) =============================
// all five weight transpose+round jobs in ONE flat-grid launch
// segments: Wq 512 | Wk 6272 | Wout 128 | fc1 512 | fc2 512  (total 7936)
__global__ __launch_bounds__(256)
void wprep_k(const float* __restrict__ Wq, __half* __restrict__ WqT,
             const float* __restrict__ Wk, __half* __restrict__ WkT,
             const float* __restrict__ Wo, __half* __restrict__ WoT,
             const float* __restrict__ f1, __half* __restrict__ f1T,
             const float* __restrict__ f2, __half* __restrict__ f2T)
{
    const int bid = blockIdx.x;
    const float* in; __half* oh; int R, Cc, bx, by, bz;
    if (bid < 512) {
        in = Wq; oh = WqT; R = C2d; Cc = C2d;
        int l = bid; bx = l & 7; l >>= 3; by = l & 15; bz = l >> 4;
    } else if (bid < 6784) {
        in = Wk; oh = WkT; R = KVd; Cc = KVd;
        int l = bid - 512; bx = l % 28; l /= 28; by = l % 56; bz = l / 56;
    } else if (bid < 6912) {
        in = Wo; oh = WoT; R = C2d; Cc = C2d;
        int l = bid - 6784; bx = l & 7; by = l >> 3; bz = 0;
    } else if (bid < 7424) {
        in = f1; oh = f1T; R = C2d; Cc = C2E;
        int l = bid - 6912; bx = l & 31; by = l >> 5; bz = 0;
    } else {
        in = f2; oh = f2T; R = C2E; Cc = C2d;
        int l = bid - 7424; bx = l & 7; by = l >> 3; bz = 0;
    }
    __shared__ float t[32][65];
    const long zo = (long)bz * R * Cc;
    const int c0 = bx * 64, r0 = by * 32;
    const int tid = threadIdx.x;
#pragma unroll
    for (int it = 0; it < 2; ++it) {
        const int idx = tid + it * 256;
        const int r = idx >> 4, cs = idx & 15;
        const float4 v = *(const float4*)(in + zo + (long)(r0 + r) * Cc + c0 + cs * 4);
        t[r][cs * 4 + 0] = v.x; t[r][cs * 4 + 1] = v.y;
        t[r][cs * 4 + 2] = v.z; t[r][cs * 4 + 3] = v.w;
    }
    __syncthreads();
    const int c = tid >> 2, rs = tid & 3;
    __align__(16) __half hh[8];
#pragma unroll
    for (int j = 0; j < 8; ++j) hh[j] = __float2half_rn(t[rs * 8 + j][c]);
    *(uint4*)&oh[zo + (long)(c0 + c) * R + r0 + rs * 8] = *(uint4*)hh;
}

// fp32 -> fp16 rounded (same layout)
__global__ void pround_k(const float* __restrict__ in, __half* __restrict__ oh, long n4)
{
    for (long i = blockIdx.x * blockDim.x + threadIdx.x; i < n4; i += (long)gridDim.x * blockDim.x) {
        float4 v = ((const float4*)in)[i];
        __half hh[4] = { __float2half_rn(v.x), __float2half_rn(v.y),
                         __float2half_rn(v.z), __float2half_rn(v.w) };
        ((uint2*)oh)[i] = *(uint2*)hh;
    }
}

// fp16 [Z][R][C] -> [Z][C][R], 32x64 tiles, 16B transactions
__global__ __launch_bounds__(256)
void tb16_k(const __half* __restrict__ in, __half* __restrict__ out, int R, int Cc)
{
    __shared__ __half t[32][72];
    const long zo = (long)blockIdx.z * R * Cc;
    const int c0 = blockIdx.x * 64, r0 = blockIdx.y * 32;
    const int tid = threadIdx.x;
    {
        const int r = tid >> 3, cs = tid & 7;
        __align__(16) __half v[8];
        *(uint4*)v = *(const uint4*)(in + zo + (long)(r0 + r) * Cc + c0 + cs * 8);
#pragma unroll
        for (int j = 0; j < 8; ++j) t[r][cs * 8 + j] = v[j];
    }
    __syncthreads();
    const int c = tid >> 2, rs = tid & 3;
    __align__(16) __half o8[8];
#pragma unroll
    for (int j = 0; j < 8; ++j) o8[j] = t[rs * 8 + j][c];
    *(uint4*)&out[zo + (long)(c0 + c) * R + r0 + rs * 8] = *(uint4*)o8;
}

// input LayerNorms -> rounded fp16 outputs (224 thr: 448 float4 = 1792 elems)
__global__ __launch_bounds__(224)
void ln_in_kernel(const float* __restrict__ e1, const float* __restrict__ e2,
                  const float* __restrict__ e3,
                  const float* __restrict__ ag, const float* __restrict__ ab,
                  const float* __restrict__ g1, const float* __restrict__ b1,
                  __half* __restrict__ Yh, __half* __restrict__ Xh)
{
    const long row = blockIdx.x;
    const int  tid = threadIdx.x;
    const float4* p1 = (const float4*)(e1 + row * C1d);
    const float4* p2 = (const float4*)(e2 + row * C2d);
    const float4* p3 = (const float4*)(e3 + row * C3d);
    __shared__ float sh[16];

    const int f0 = tid, f1 = tid + 224;
    const bool isX = (f0 >= 64) && (f0 < 192);
    float4 a = (f0 < 64) ? p1[f0] : (isX ? p2[f0 - 64] : p3[f0 - 192]);
    float4 b = p3[f1 - 192];

    float s = a.x + a.y + a.z + a.w + b.x + b.y + b.z + b.w;
    float q = a.x * a.x + a.y * a.y + a.z * a.z + a.w * a.w
            + b.x * b.x + b.y * b.y + b.z * b.z + b.w * b.w;
    float2 r = bred2(s, q, sh, tid, 7);
    float mean = r.x * (1.f / KVd);
    float inv  = rsqrtf(r.y * (1.f / KVd) - mean * mean + 1e-6f);

    const float4* g4 = (const float4*)ag;
    const float4* b4 = (const float4*)ab;
    {
        const float4 ga = g4[f0], ba = b4[f0];
        __half hh[4];
        hh[0] = __float2half_rn((a.x - mean) * inv * ga.x + ba.x);
        hh[1] = __float2half_rn((a.y - mean) * inv * ga.y + ba.y);
        hh[2] = __float2half_rn((a.z - mean) * inv * ga.z + ba.z);
        hh[3] = __float2half_rn((a.w - mean) * inv * ga.w + ba.w);
        *(uint2*)&Yh[row * KVd + f0 * 4] = *(uint2*)hh;
        const float4 gb = g4[f1], bb = b4[f1];
        hh[0] = __float2half_rn((b.x - mean) * inv * gb.x + bb.x);
        hh[1] = __float2half_rn((b.y - mean) * inv * gb.y + bb.y);
        hh[2] = __float2half_rn((b.z - mean) * inv * gb.z + bb.z);
        hh[3] = __float2half_rn((b.w - mean) * inv * gb.w + bb.w);
        *(uint2*)&Yh[row * KVd + f1 * 4] = *(uint2*)hh;
    }

    // X = LN(emb2): chunk0 of threads 64..191 covers e2 exactly
    float sX = isX ? (a.x + a.y + a.z + a.w) : 0.f;
    float qX = isX ? (a.x * a.x + a.y * a.y + a.z * a.z + a.w * a.w) : 0.f;
    float2 rX = bred2(sX, qX, sh, tid, 7);
    if (isX) {
        float meanX = rX.x * (1.f / C2d);
        float invX  = rsqrtf(rX.y * (1.f / C2d) - meanX * meanX + 1e-6f);
        const int fx = f0 - 64;
        const float4 gx = ((const float4*)g1)[fx], bx = ((const float4*)b1)[fx];
        __half hh[4];
        hh[0] = __float2half_rn((a.x - meanX) * invX * gx.x + bx.x);
        hh[1] = __float2half_rn((a.y - meanX) * invX * gx.y + bx.y);
        hh[2] = __float2half_rn((a.z - meanX) * invX * gx.z + bx.z);
        hh[3] = __float2half_rn((a.w - meanX) * invX * gx.w + bx.w);
        *(uint2*)&Xh[row * C2d + fx * 4] = *(uint2*)hh;
    }
}

__global__ __launch_bounds__(128)
void ln2_kernel(const float* __restrict__ in,
                const float* __restrict__ g, const float* __restrict__ b,
                __half* __restrict__ Zh)
{
    const long row = blockIdx.x;
    const int  tid = threadIdx.x;
    __shared__ float sh[8];
    const float4 v = ((const float4*)(in + row * C2d))[tid];
    float s = v.x + v.y + v.z + v.w;
    float q = v.x * v.x + v.y * v.y + v.z * v.z + v.w * v.w;
    float2 r = bred2(s, q, sh, tid, 4);
    float mean = r.x * (1.f / C2d);
    float inv  = rsqrtf(r.y * (1.f / C2d) - mean * mean + 1e-6f);
    const float4 gg = ((const float4*)g)[tid], bb = ((const float4*)b)[tid];
    __half hh[4];
    hh[0] = __float2half_rn((v.x - mean) * inv * gg.x + bb.x);
    hh[1] = __float2half_rn((v.y - mean) * inv * gg.y + bb.y);
    hh[2] = __float2half_rn((v.z - mean) * inv * gg.z + bb.z);
    hh[3] = __float2half_rn((v.w - mean) * inv * gg.w + bb.w);
    *(uint2*)&Zh[row * C2d + tid * 4] = *(uint2*)hh;
}

// finish per-map variance from 56 per-tile partials -> softmax scale
__global__ __launch_bounds__(32)
void stats2_kernel(const float* __restrict__ part, float* __restrict__ scale)
{
    const int z = blockIdx.x, lane = threadIdx.x;
    float s = 0.f, q = 0.f;
#pragma unroll
    for (int j = 0; j < 2; ++j) {
        const int i = lane + j * 32;
        if (i < 56) { s += part[((long)z * 56 + i) * 2]; q += part[((long)z * 56 + i) * 2 + 1]; }
    }
#pragma unroll
    for (int o = 16; o; o >>= 1) {
        s += __shfl_xor_sync(0xffffffffu, s, o);
        q += __shfl_xor_sync(0xffffffffu, q, o);
    }
    if (lane == 0) {
        const float cnt = (float)(C2d * KVd);
        float mean = s / cnt;
        float var  = q / cnt - mean * mean;
        float a    = rsqrtf((float)KVd);
        scale[z]   = a * rsqrtf(a * a * var + 1e-5f);
    }
}

__global__ __launch_bounds__(224)
void softmax_kernel(const __half* __restrict__ Sh, const float* __restrict__ scale,
                    __half* __restrict__ Ph)
{
    const long row = blockIdx.x;
    const int  tid = threadIdx.x;
    const __half* p = Sh + row * KVd;
    const float sc = scale[blockIdx.x >> 9];
    __shared__ float sh[16];

    __align__(16) __half v8[8];
    *(uint4*)v8 = *(const uint4*)(p + tid * 8);
    float f[8];
#pragma unroll
    for (int j = 0; j < 8; ++j) f[j] = __half2float(v8[j]);
    float mx = f[0];
#pragma unroll
    for (int j = 1; j < 8; ++j) mx = fmaxf(mx, f[j]);
    mx = bmax(mx, sh, tid, 7);

    float e[8], s = 0.f;
#pragma unroll
    for (int j = 0; j < 8; ++j) { e[j] = __expf((f[j] - mx) * sc); s += e[j]; }
    float2 r = bred2(s, 0.f, sh, tid, 7);
    const float inv = 1.f / r.x;

#pragma unroll
    for (int j = 0; j < 8; ++j) v8[j] = __float2half_rn(e[j] * inv);
    *(uint4*)&Ph[row * KVd + tid * 8] = *(uint4*)v8;
}

// ===================== launcher =============================================
#define SYM(v, t, s) t* v; { void* _p; cudaGetSymbolAddress(&_p, s); v = (t*)_p; }

extern "C" void kernel_launch(void* const* d_in, const int* in_sizes, int n_in,
                              void* d_out, int out_size)
{
    const float* emb1    = (const float*)d_in[0];
    const float* emb2    = (const float*)d_in[1];
    const float* emb3    = (const float*)d_in[2];
    const float* Wq      = (const float*)d_in[3];
    const float* Wk      = (const float*)d_in[4];
    const float* Wv      = (const float*)d_in[5];
    const float* Wout    = (const float*)d_in[6];
    const float* ln1_g   = (const float*)d_in[7];
    const float* ln1_b   = (const float*)d_in[8];
    const float* lnall_g = (const float*)d_in[9];
    const float* lnall_b = (const float*)d_in[10];
    const float* lnffn_g = (const float*)d_in[11];
    const float* lnffn_b = (const float*)d_in[12];
    const float* fc1_w   = (const float*)d_in[13];
    const float* fc1_b   = (const float*)d_in[14];
    const float* fc2_w   = (const float*)d_in[15];
    const float* fc2_b   = (const float*)d_in[16];
    float* out = (float*)d_out;

    SYM(Yh, __half, g_Yh)   SYM(Yth, __half, g_Yth)
    SYM(Xh, __half, g_Xh)   SYM(Xth, __half, g_Xth)
    SYM(Gth, __half, g_Gth)
    SYM(T1h, __half, g_T1h)
    SYM(Sh, __half, g_Sh)
    SYM(Ph, __half, g_Ph)
    SYM(Mth, __half, g_Mth)
    SYM(Ch, __half, g_Ch)
    SYM(cx2, float, g_cx2)
    SYM(Zh, __half, g_Zh)
    SYM(Fh, __half, g_Fh)
    SYM(WqTh, __half, g_WqTh)
    SYM(WkTh, __half, g_WkTh)
    SYM(Wvh, __half, g_Wvh)
    SYM(WoTh, __half, g_WoTh)
    SYM(f1Th, __half, g_f1Th)
    SYM(f2Th, __half, g_f2Th)
    SYM(scl, float, g_sc)     SYM(part, float, g_part)

    const int SMA = 3 * ((128 + 128) * (2 * 64 + 16));   // 110592 B: BK64 3-stage 1-pass -> 2 CTAs/SM
    cudaFuncSetAttribute(mma_gemm<128, 64, 3, 0, 0, 2, 0, 128>, cudaFuncAttributeMaxDynamicSharedMemorySize, SMA);
    cudaFuncSetAttribute(mma_gemm<128, 64, 3, 0, 0, 2, 1, 128>, cudaFuncAttributeMaxDynamicSharedMemorySize, SMA);
    cudaFuncSetAttribute(mma_gemm<128, 64, 3, 0, 1, 0, 0, 128>, cudaFuncAttributeMaxDynamicSharedMemorySize, SMA);
    cudaFuncSetAttribute(mma_gemm<128, 64, 3, 0, 2, 2, 0, 128>, cudaFuncAttributeMaxDynamicSharedMemorySize, SMA);
    cudaFuncSetAttribute(mma_gemm<128, 64, 3, 0, 3, 0, 0, 128>, cudaFuncAttributeMaxDynamicSharedMemorySize, SMA);

    // --- launches 0..2: GEMM2's only deps; GEMM2 is my launch #3 == ncu slot
    ln_in_kernel<<<BB * NT, 224>>>(emb1, emb2, emb3, lnall_g, lnall_b, ln1_g, ln1_b,
                                   Yh, Xh);
    tb16_k<<<dim3(KVd / 64, NT / 32, BB), 256>>>(Yh, Yth, NT, KVd);
    tb16_k<<<dim3(C2d / 64, NT / 32, BB), 256>>>(Xh, Xth, NT, C2d);

    // 2. Gt_b = Yt_b Xt_b^T  [1792,512], K=1024 (fp16-rounded out)
    mma_gemm<128, 64, 3, 0, 0, 2, 0, 128><<<dim3(C2d / 128, KVd / 128, BB), 128, SMA>>>(
        Yth, Xth, nullptr, nullptr, Gth, nullptr, nullptr, nullptr,
        KVd, C2d, NT, NT, NT,
        (long)KVd * NT, (long)C2d * NT, (long)KVd * C2d, 0, 0, 1, 0, 0, 1.f);

    // weight prep (merged) + Wv round
    wprep_k<<<7936, 256>>>(Wq, WqTh, Wk, WkTh, Wout, WoTh, fc1_w, f1Th, fc2_w, f2Th);
    pround_k<<<4096, 256>>>(Wv, Wvh, (long)NHd * KVd * KVd / 4);

    // 3. T1[b,h] = WqT_h Gt_b^T  [512,1792], K=512 (1-pass)
    mma_gemm<128, 64, 3, 0, 0, 2, 0, 128><<<dim3(KVd / 128, C2d / 128, BB * NHd), 128, SMA>>>(
        WqTh, Gth, nullptr, nullptr, T1h, nullptr, nullptr, nullptr,
        C2d, KVd, C2d, C2d, C2d,
        (long)C2d * C2d, (long)KVd * C2d, (long)C2d * KVd, 1, 2, 1, 0, 0, 1.f);

    // 4. S[b,h] = T1 WkT_h^T  [512,1792], K=1792 (fp16 out + fused stats partials)
    mma_gemm<128, 64, 3, 0, 0, 2, 1, 128><<<dim3(KVd / 128, C2d / 128, BB * NHd), 128, SMA>>>(
        T1h, WkTh, nullptr, part, Sh, nullptr, nullptr, nullptr,
        C2d, KVd, KVd, KVd, KVd,
        (long)C2d * KVd, (long)KVd * KVd, (long)C2d * KVd, 0, 1, 1, 0, 0, 1.f);

    // 5-6. finish stats + row softmax
    stats2_kernel<<<BB * NHd, 32>>>(part, scl);
    softmax_kernel<<<BB * NHd * C2d, 224>>>(Sh, scl, Ph);

    // 7. Mmt_b[c,e] = (1/H) sum_h sum_k P[b,h,c,k] Wv_h[e,k]  [512,1792]
    mma_gemm<128, 64, 3, 0, 0, 2, 0, 128><<<dim3(KVd / 128, C2d / 128, BB), 128, SMA>>>(
        Ph, Wvh, nullptr, nullptr, Mth, nullptr, nullptr, nullptr,
        C2d, KVd, KVd, KVd, KVd,
        (long)NHd * C2d * KVd, 0, (long)C2d * KVd, 0, 0,
        NHd, (long)C2d * KVd, (long)KVd * KVd, 1.f / NHd);

    // 8. ctx_b = Y_b Mmt_b^T  [1024,512], K=1792
    mma_gemm<128, 64, 3, 0, 0, 2, 0, 128><<<dim3(C2d / 128, NT / 128, BB), 128, SMA>>>(
        Yh, Mth, nullptr, nullptr, Ch, nullptr, nullptr, nullptr,
        NT, C2d, KVd, KVd, KVd,
        (long)NT * KVd, (long)C2d * KVd, (long)NT * C2d, 0, 0, 1, 0, 0, 1.f);

    // 9. cx2 = ctx WoutT^T + emb2  [8192,512]
    mma_gemm<128, 64, 3, 0, 1, 0, 0, 128><<<dim3(C2d / 128, BB * NT / 128, 1), 128, SMA>>>(
        Ch, WoTh, nullptr, cx2, nullptr, nullptr, nullptr, emb2,
        BB * NT, C2d, C2d, C2d, C2d, 0, 0, 0, 0, 0, 1, 0, 0, 1.f);

    // 10. Z = LN(cx2)
    ln2_kernel<<<BB * NT, 128>>>(cx2, lnffn_g, lnffn_b, Zh);

    // 11. F = gelu(Z f1T^T + b1)  [8192,2048]
    mma_gemm<128, 64, 3, 0, 2, 2, 0, 128><<<dim3(C2E / 128, BB * NT / 128, 1), 128, SMA>>>(
        Zh, f1Th, nullptr, nullptr, Fh, nullptr, fc1_b, nullptr,
        BB * NT, C2E, C2d, C2d, C2d, 0, 0, 0, 0, 0, 1, 0, 0, 1.f);

    // 12. out = F f2T^T + b2 + cx2  [8192,512]
    mma_gemm<128, 64, 3, 0, 3, 0, 0, 128><<<dim3(C2d / 128, BB * NT / 128, 1), 128, SMA>>>(
        Fh, f2Th, nullptr, out, nullptr, nullptr, fc2_b, cx2,
        BB * NT, C2d, C2E, C2E, C2E, 0, 0, 0, 0, 0, 1, 0, 0, 1.f);
}